// round 1
// baseline (speedup 1.0000x reference)
#include <cuda_runtime.h>
#include <cuda_bf16.h>

// Problem constants
#define BATCH 4
#define LEN   1024
#define DIM   1024
#define HEADS 16
#define HD    64
#define SCALE 0.125f   // 64^-0.5

// ---------------------------------------------------------------------------
// Scratch: Q, K, V in [B, H, L, HD] layout (fp32). 16.78 MB each.
// ---------------------------------------------------------------------------
__device__ float g_q[BATCH * HEADS * LEN * HD];
__device__ float g_k[BATCH * HEADS * LEN * HD];
__device__ float g_v[BATCH * HEADS * LEN * HD];

// ---------------------------------------------------------------------------
// Kernel 1: QKV projection GEMM.  C[4096,3072] = x[4096,1024] @ W[1024,3072] + b
// 128x128 tile, K-step 16, 256 threads, 8x8 per-thread microtile.
// Epilogue scatters into g_q/g_k/g_v with [B,H,L,HD] layout.
// ---------------------------------------------------------------------------
__global__ __launch_bounds__(256) void qkv_kernel(
    const float* __restrict__ A,      // x   [4096, 1024]
    const float* __restrict__ B,      // W   [1024, 3072]
    const float* __restrict__ bias)   // b   [3072]
{
    __shared__ float As[16][132];   // transposed: As[k][m]
    __shared__ float Bs[16][132];   // Bs[k][n]

    const int tid = threadIdx.x;
    const int m0 = blockIdx.y * 128;
    const int n0 = blockIdx.x * 128;
    const int ri = (tid >> 4) * 8;   // row offset in tile
    const int ci = (tid & 15) * 8;   // col offset in tile

    float acc[8][8];
#pragma unroll
    for (int u = 0; u < 8; u++)
#pragma unroll
        for (int v = 0; v < 8; v++) acc[u][v] = 0.0f;

    for (int k0 = 0; k0 < 1024; k0 += 16) {
        // Load A tile (128x16) transposed, and B tile (16x128)
#pragma unroll
        for (int q = 0; q < 2; q++) {
            int f = tid + 256 * q;               // 0..511
            // A: rm = f/4, kc = (f%4)*4
            int rm = f >> 2;
            int kc = (f & 3) * 4;
            float4 va = *(const float4*)&A[(size_t)(m0 + rm) * 1024 + k0 + kc];
            As[kc + 0][rm] = va.x;
            As[kc + 1][rm] = va.y;
            As[kc + 2][rm] = va.z;
            As[kc + 3][rm] = va.w;
            // B: kb = f/32, cb = (f%32)*4
            int kb = f >> 5;
            int cb = (f & 31) * 4;
            *(float4*)&Bs[kb][cb] = *(const float4*)&B[(size_t)(k0 + kb) * 3072 + n0 + cb];
        }
        __syncthreads();

#pragma unroll
        for (int kk = 0; kk < 16; kk++) {
            float af[8], bf[8];
            *(float4*)(af)     = *(float4*)&As[kk][ri];
            *(float4*)(af + 4) = *(float4*)&As[kk][ri + 4];
            *(float4*)(bf)     = *(float4*)&Bs[kk][ci];
            *(float4*)(bf + 4) = *(float4*)&Bs[kk][ci + 4];
#pragma unroll
            for (int u = 0; u < 8; u++)
#pragma unroll
                for (int v = 0; v < 8; v++)
                    acc[u][v] = fmaf(af[u], bf[v], acc[u][v]);
        }
        __syncthreads();
    }

    // Epilogue: add bias, scatter to Q/K/V in [B,H,L,HD]
#pragma unroll
    for (int u = 0; u < 8; u++) {
        int m = m0 + ri + u;
        int bb = m >> 10;          // batch
        int l  = m & 1023;         // position
#pragma unroll
        for (int v = 0; v < 8; v++) {
            int n = n0 + ci + v;
            float val = acc[u][v] + bias[n];
            int s  = n >> 10;          // 0=q, 1=k, 2=v
            int h  = (n >> 6) & 15;
            int hd = n & 63;
            float* dst = (s == 0) ? g_q : (s == 1) ? g_k : g_v;
            dst[(((bb * HEADS + h) << 10) + l) * HD + hd] = val;
        }
    }
}

// ---------------------------------------------------------------------------
// Kernel 2: fused attention with relative_key_query bias, flash-style.
// One CTA per (bh, l-tile of 64). 256 threads as 16x16; each thread owns a
// 4x4 S microtile and a 4x4 O microtile. Online softmax stats replicated
// across the 16 threads of a row-group via butterfly shuffles.
// ---------------------------------------------------------------------------
#define SSTR 65
// smem layout (floats): Qs[64*65] Ks[64*65] Vs[64*65] Es[127*65] Ps[64*65]
#define OFF_Q 0
#define OFF_K 4160
#define OFF_V 8320
#define OFF_E 12480
#define OFF_P 20735
#define ATT_SMEM_FLOATS 24895
#define ATT_SMEM_BYTES  (ATT_SMEM_FLOATS * 4)

__global__ __launch_bounds__(256) void attn_kernel(
    const float* __restrict__ emb,   // dist_emb [2047, 64]
    float* __restrict__ out)         // [B, L, D]
{
    extern __shared__ float sm[];
    float* Qs = sm + OFF_Q;
    float* Ks = sm + OFF_K;
    float* Vs = sm + OFF_V;
    float* Es = sm + OFF_E;
    float* Ps = sm + OFF_P;

    const int tid = threadIdx.x;
    const int tx = tid & 15;
    const int ty = tid >> 4;
    const int l0 = blockIdx.x * 64;
    const int bh = blockIdx.y;
    const int b = bh >> 4;
    const int h = bh & 15;

    const float* qb = g_q + (size_t)bh * LEN * HD;
    const float* kb = g_k + (size_t)bh * LEN * HD;
    const float* vb = g_v + (size_t)bh * LEN * HD;

    // Load Q tile [64 x 64]
#pragma unroll
    for (int q = 0; q < 4; q++) {
        int f = tid + 256 * q;            // 0..1023 float4s
        int row = f >> 4;
        int c4 = (f & 15) * 4;
        float4 v = *(const float4*)&qb[(size_t)(l0 + row) * HD + c4];
        Qs[row * SSTR + c4 + 0] = v.x;
        Qs[row * SSTR + c4 + 1] = v.y;
        Qs[row * SSTR + c4 + 2] = v.z;
        Qs[row * SSTR + c4 + 3] = v.w;
    }

    float m_r[4], l_r[4], O[4][4];
#pragma unroll
    for (int u = 0; u < 4; u++) {
        m_r[u] = -1e30f;
        l_r[u] = 0.0f;
#pragma unroll
        for (int v = 0; v < 4; v++) O[u][v] = 0.0f;
    }

    const int eb = ty * 4 - tx * 4 + 63;   // delta smem row for (u=0, v=0)

    for (int j0 = 0; j0 < LEN; j0 += 64) {
        __syncthreads();   // prior iteration's reads of Ks/Vs/Es/Ps complete

        // Load K, V tiles [64x64]
#pragma unroll
        for (int q = 0; q < 4; q++) {
            int f = tid + 256 * q;
            int row = f >> 4;
            int c4 = (f & 15) * 4;
            float4 vk = *(const float4*)&kb[(size_t)(j0 + row) * HD + c4];
            Ks[row * SSTR + c4 + 0] = vk.x;
            Ks[row * SSTR + c4 + 1] = vk.y;
            Ks[row * SSTR + c4 + 2] = vk.z;
            Ks[row * SSTR + c4 + 3] = vk.w;
            float4 vv = *(const float4*)&vb[(size_t)(j0 + row) * HD + c4];
            Vs[row * SSTR + c4 + 0] = vv.x;
            Vs[row * SSTR + c4 + 1] = vv.y;
            Vs[row * SSTR + c4 + 2] = vv.z;
            Vs[row * SSTR + c4 + 3] = vv.w;
        }
        // Load E tile [127 x 64]: global rows (l0 - j0 + 960) + t, t in [0,127)
        const int ebase = l0 - j0 + 960;
#pragma unroll
        for (int q = 0; q < 8; q++) {
            int f = tid + 256 * q;        // need 127*16 = 2032 float4s
            if (f < 2032) {
                int row = f >> 4;
                int c4 = (f & 15) * 4;
                float4 ve = *(const float4*)&emb[(size_t)(ebase + row) * HD + c4];
                Es[row * SSTR + c4 + 0] = ve.x;
                Es[row * SSTR + c4 + 1] = ve.y;
                Es[row * SSTR + c4 + 2] = ve.z;
                Es[row * SSTR + c4 + 3] = ve.w;
            }
        }
        __syncthreads();

        // ---- S = (q.k + (q+k).e) * SCALE ----
        float acc[4][4];
#pragma unroll
        for (int u = 0; u < 4; u++)
#pragma unroll
            for (int v = 0; v < 4; v++) acc[u][v] = 0.0f;

#pragma unroll 8
        for (int d = 0; d < HD; d++) {
            float qf[4], kf[4], ef[7];
#pragma unroll
            for (int u = 0; u < 4; u++) qf[u] = Qs[(ty * 4 + u) * SSTR + d];
#pragma unroll
            for (int v = 0; v < 4; v++) kf[v] = Ks[(tx * 4 + v) * SSTR + d];
#pragma unroll
            for (int w = 0; w < 7; w++) ef[w] = Es[(eb - 3 + w) * SSTR + d];
#pragma unroll
            for (int u = 0; u < 4; u++)
#pragma unroll
                for (int v = 0; v < 4; v++) {
                    acc[u][v] = fmaf(qf[u], kf[v], acc[u][v]);
                    acc[u][v] = fmaf(qf[u] + kf[v], ef[u - v + 3], acc[u][v]);
                }
        }

        // ---- online softmax ----
        float pf_[4];
#pragma unroll
        for (int u = 0; u < 4; u++) {
#pragma unroll
            for (int v = 0; v < 4; v++) acc[u][v] *= SCALE;
            float r = fmaxf(fmaxf(acc[u][0], acc[u][1]), fmaxf(acc[u][2], acc[u][3]));
#pragma unroll
            for (int off = 8; off >= 1; off >>= 1)
                r = fmaxf(r, __shfl_xor_sync(0xffffffffu, r, off));
            float nm = fmaxf(m_r[u], r);
            pf_[u] = __expf(m_r[u] - nm);
            float rs = 0.0f;
#pragma unroll
            for (int v = 0; v < 4; v++) {
                acc[u][v] = __expf(acc[u][v] - nm);
                rs += acc[u][v];
            }
#pragma unroll
            for (int off = 8; off >= 1; off >>= 1)
                rs += __shfl_xor_sync(0xffffffffu, rs, off);
            l_r[u] = l_r[u] * pf_[u] + rs;
            m_r[u] = nm;
            // stage P
#pragma unroll
            for (int v = 0; v < 4; v++)
                Ps[(ty * 4 + u) * SSTR + tx * 4 + v] = acc[u][v];
        }
        __syncthreads();

        // ---- O = O*pf + P @ V ----
#pragma unroll
        for (int u = 0; u < 4; u++)
#pragma unroll
            for (int v = 0; v < 4; v++) O[u][v] *= pf_[u];

#pragma unroll 8
        for (int j = 0; j < 64; j++) {
            float pf4[4], vf4[4];
#pragma unroll
            for (int u = 0; u < 4; u++) pf4[u] = Ps[(ty * 4 + u) * SSTR + j];
#pragma unroll
            for (int v = 0; v < 4; v++) vf4[v] = Vs[j * SSTR + tx * 4 + v];
#pragma unroll
            for (int u = 0; u < 4; u++)
#pragma unroll
                for (int v = 0; v < 4; v++)
                    O[u][v] = fmaf(pf4[u], vf4[v], O[u][v]);
        }
    }

    // ---- write output: out[b, l, h*64 + d] ----
#pragma unroll
    for (int u = 0; u < 4; u++) {
        float inv = 1.0f / l_r[u];
        int l = l0 + ty * 4 + u;
#pragma unroll
        for (int v = 0; v < 4; v++) {
            int d = tx * 4 + v;
            out[((size_t)(b * LEN + l)) * DIM + h * HD + d] = O[u][v] * inv;
        }
    }
}

// ---------------------------------------------------------------------------
// Launch
// ---------------------------------------------------------------------------
extern "C" void kernel_launch(void* const* d_in, const int* in_sizes, int n_in,
                              void* d_out, int out_size)
{
    const float* x    = (const float*)d_in[0];   // [4, 1024, 1024]
    const float* Wqkv = (const float*)d_in[1];   // [1024, 3072]
    const float* bqkv = (const float*)d_in[2];   // [3072]
    const float* emb  = (const float*)d_in[3];   // [2047, 64]
    float* out = (float*)d_out;                  // [4, 1024, 1024]

    cudaFuncSetAttribute(attn_kernel, cudaFuncAttributeMaxDynamicSharedMemorySize,
                         ATT_SMEM_BYTES);

    dim3 gq(3072 / 128, 4096 / 128);   // (24, 32)
    qkv_kernel<<<gq, 256>>>(x, Wqkv, bqkv);

    dim3 ga(LEN / 64, BATCH * HEADS);  // (16, 64)
    attn_kernel<<<ga, 256, ATT_SMEM_BYTES>>>(emb, out);
}

// round 2
// speedup vs baseline: 1.6344x; 1.6344x over previous
#include <cuda_runtime.h>
#include <cuda_bf16.h>

// Problem constants
#define BATCH 4
#define LEN   1024
#define DIM   1024
#define HEADS 16
#define HD    64
#define SCALE 0.125f   // 64^-0.5

// ---------------------------------------------------------------------------
// Scratch: Q, K, V in [B, H, L, HD] layout (fp32). 16.78 MB each.
// ---------------------------------------------------------------------------
__device__ float g_q[BATCH * HEADS * LEN * HD];
__device__ float g_k[BATCH * HEADS * LEN * HD];
__device__ float g_v[BATCH * HEADS * LEN * HD];

// ---------------------------------------------------------------------------
// Kernel 1: QKV projection GEMM.  C[4096,3072] = x[4096,1024] @ W[1024,3072] + b
// 128x128 tile, K-step 16, 256 threads, 8x8 per-thread microtile.
// Epilogue scatters into g_q/g_k/g_v with [B,H,L,HD] layout.
// ---------------------------------------------------------------------------
__global__ __launch_bounds__(256) void qkv_kernel(
    const float* __restrict__ A,      // x   [4096, 1024]
    const float* __restrict__ B,      // W   [1024, 3072]
    const float* __restrict__ bias)   // b   [3072]
{
    __shared__ float As[16][132];   // transposed: As[k][m]
    __shared__ float Bs[16][132];   // Bs[k][n]

    const int tid = threadIdx.x;
    const int m0 = blockIdx.y * 128;
    const int n0 = blockIdx.x * 128;
    const int ri = (tid >> 4) * 8;   // row offset in tile
    const int ci = (tid & 15) * 8;   // col offset in tile

    float acc[8][8];
#pragma unroll
    for (int u = 0; u < 8; u++)
#pragma unroll
        for (int v = 0; v < 8; v++) acc[u][v] = 0.0f;

    for (int k0 = 0; k0 < 1024; k0 += 16) {
        // Load A tile (128x16) transposed, and B tile (16x128)
#pragma unroll
        for (int q = 0; q < 2; q++) {
            int f = tid + 256 * q;               // 0..511
            // A: rm = f/4, kc = (f%4)*4
            int rm = f >> 2;
            int kc = (f & 3) * 4;
            float4 va = *(const float4*)&A[(size_t)(m0 + rm) * 1024 + k0 + kc];
            As[kc + 0][rm] = va.x;
            As[kc + 1][rm] = va.y;
            As[kc + 2][rm] = va.z;
            As[kc + 3][rm] = va.w;
            // B: kb = f/32, cb = (f%32)*4
            int kb = f >> 5;
            int cb = (f & 31) * 4;
            *(float4*)&Bs[kb][cb] = *(const float4*)&B[(size_t)(k0 + kb) * 3072 + n0 + cb];
        }
        __syncthreads();

#pragma unroll
        for (int kk = 0; kk < 16; kk++) {
            float af[8], bf[8];
            *(float4*)(af)     = *(float4*)&As[kk][ri];
            *(float4*)(af + 4) = *(float4*)&As[kk][ri + 4];
            *(float4*)(bf)     = *(float4*)&Bs[kk][ci];
            *(float4*)(bf + 4) = *(float4*)&Bs[kk][ci + 4];
#pragma unroll
            for (int u = 0; u < 8; u++)
#pragma unroll
                for (int v = 0; v < 8; v++)
                    acc[u][v] = fmaf(af[u], bf[v], acc[u][v]);
        }
        __syncthreads();
    }

    // Epilogue: add bias, scatter to Q/K/V in [B,H,L,HD]
#pragma unroll
    for (int u = 0; u < 8; u++) {
        int m = m0 + ri + u;
        int bb = m >> 10;          // batch
        int l  = m & 1023;         // position
#pragma unroll
        for (int v = 0; v < 8; v++) {
            int n = n0 + ci + v;
            float val = acc[u][v] + bias[n];
            int s  = n >> 10;          // 0=q, 1=k, 2=v
            int h  = (n >> 6) & 15;
            int hd = n & 63;
            float* dst = (s == 0) ? g_q : (s == 1) ? g_k : g_v;
            dst[(((bb * HEADS + h) << 10) + l) * HD + hd] = val;
        }
    }
}

// ---------------------------------------------------------------------------
// Kernel 2: fused attention with relative_key_query bias, flash-style.
// One CTA per (bh, l-tile of 64). 256 threads as 16x16; each thread owns a
// 4x4 S microtile and a 4x4 O microtile. Online softmax stats replicated
// across the 16 threads of a row-group via butterfly shuffles.
// ---------------------------------------------------------------------------
#define SSTR 65
// smem layout (floats): Qs[64*65] Ks[64*65] Vs[64*65] Es[127*65] Ps[64*65]
#define OFF_Q 0
#define OFF_K 4160
#define OFF_V 8320
#define OFF_E 12480
#define OFF_P 20735
#define ATT_SMEM_FLOATS 24895
#define ATT_SMEM_BYTES  (ATT_SMEM_FLOATS * 4)

__global__ __launch_bounds__(256) void attn_kernel(
    const float* __restrict__ emb,   // dist_emb [2047, 64]
    float* __restrict__ out)         // [B, L, D]
{
    extern __shared__ float sm[];
    float* Qs = sm + OFF_Q;
    float* Ks = sm + OFF_K;
    float* Vs = sm + OFF_V;
    float* Es = sm + OFF_E;
    float* Ps = sm + OFF_P;

    const int tid = threadIdx.x;
    const int tx = tid & 15;
    const int ty = tid >> 4;
    const int l0 = blockIdx.x * 64;
    const int bh = blockIdx.y;
    const int b = bh >> 4;
    const int h = bh & 15;

    const float* qb = g_q + (size_t)bh * LEN * HD;
    const float* kb = g_k + (size_t)bh * LEN * HD;
    const float* vb = g_v + (size_t)bh * LEN * HD;

    // Load Q tile [64 x 64]
#pragma unroll
    for (int q = 0; q < 4; q++) {
        int f = tid + 256 * q;            // 0..1023 float4s
        int row = f >> 4;
        int c4 = (f & 15) * 4;
        float4 v = *(const float4*)&qb[(size_t)(l0 + row) * HD + c4];
        Qs[row * SSTR + c4 + 0] = v.x;
        Qs[row * SSTR + c4 + 1] = v.y;
        Qs[row * SSTR + c4 + 2] = v.z;
        Qs[row * SSTR + c4 + 3] = v.w;
    }

    float m_r[4], l_r[4], O[4][4];
#pragma unroll
    for (int u = 0; u < 4; u++) {
        m_r[u] = -1e30f;
        l_r[u] = 0.0f;
#pragma unroll
        for (int v = 0; v < 4; v++) O[u][v] = 0.0f;
    }

    const int eb = ty * 4 - tx * 4 + 63;   // delta smem row for (u=0, v=0)

    for (int j0 = 0; j0 < LEN; j0 += 64) {
        __syncthreads();   // prior iteration's reads of Ks/Vs/Es/Ps complete

        // Load K, V tiles [64x64]
#pragma unroll
        for (int q = 0; q < 4; q++) {
            int f = tid + 256 * q;
            int row = f >> 4;
            int c4 = (f & 15) * 4;
            float4 vk = *(const float4*)&kb[(size_t)(j0 + row) * HD + c4];
            Ks[row * SSTR + c4 + 0] = vk.x;
            Ks[row * SSTR + c4 + 1] = vk.y;
            Ks[row * SSTR + c4 + 2] = vk.z;
            Ks[row * SSTR + c4 + 3] = vk.w;
            float4 vv = *(const float4*)&vb[(size_t)(j0 + row) * HD + c4];
            Vs[row * SSTR + c4 + 0] = vv.x;
            Vs[row * SSTR + c4 + 1] = vv.y;
            Vs[row * SSTR + c4 + 2] = vv.z;
            Vs[row * SSTR + c4 + 3] = vv.w;
        }
        // Load E tile [127 x 64]: global rows (l0 - j0 + 960) + t, t in [0,127)
        const int ebase = l0 - j0 + 960;
#pragma unroll
        for (int q = 0; q < 8; q++) {
            int f = tid + 256 * q;        // need 127*16 = 2032 float4s
            if (f < 2032) {
                int row = f >> 4;
                int c4 = (f & 15) * 4;
                float4 ve = *(const float4*)&emb[(size_t)(ebase + row) * HD + c4];
                Es[row * SSTR + c4 + 0] = ve.x;
                Es[row * SSTR + c4 + 1] = ve.y;
                Es[row * SSTR + c4 + 2] = ve.z;
                Es[row * SSTR + c4 + 3] = ve.w;
            }
        }
        __syncthreads();

        // ---- S = (q.k + (q+k).e) * SCALE ----
        float acc[4][4];
#pragma unroll
        for (int u = 0; u < 4; u++)
#pragma unroll
            for (int v = 0; v < 4; v++) acc[u][v] = 0.0f;

#pragma unroll 8
        for (int d = 0; d < HD; d++) {
            float qf[4], kf[4], ef[7];
#pragma unroll
            for (int u = 0; u < 4; u++) qf[u] = Qs[(ty * 4 + u) * SSTR + d];
#pragma unroll
            for (int v = 0; v < 4; v++) kf[v] = Ks[(tx * 4 + v) * SSTR + d];
#pragma unroll
            for (int w = 0; w < 7; w++) ef[w] = Es[(eb - 3 + w) * SSTR + d];
#pragma unroll
            for (int u = 0; u < 4; u++)
#pragma unroll
                for (int v = 0; v < 4; v++) {
                    acc[u][v] = fmaf(qf[u], kf[v], acc[u][v]);
                    acc[u][v] = fmaf(qf[u] + kf[v], ef[u - v + 3], acc[u][v]);
                }
        }

        // ---- online softmax ----
        float pf_[4];
#pragma unroll
        for (int u = 0; u < 4; u++) {
#pragma unroll
            for (int v = 0; v < 4; v++) acc[u][v] *= SCALE;
            float r = fmaxf(fmaxf(acc[u][0], acc[u][1]), fmaxf(acc[u][2], acc[u][3]));
#pragma unroll
            for (int off = 8; off >= 1; off >>= 1)
                r = fmaxf(r, __shfl_xor_sync(0xffffffffu, r, off));
            float nm = fmaxf(m_r[u], r);
            pf_[u] = __expf(m_r[u] - nm);
            float rs = 0.0f;
#pragma unroll
            for (int v = 0; v < 4; v++) {
                acc[u][v] = __expf(acc[u][v] - nm);
                rs += acc[u][v];
            }
#pragma unroll
            for (int off = 8; off >= 1; off >>= 1)
                rs += __shfl_xor_sync(0xffffffffu, rs, off);
            l_r[u] = l_r[u] * pf_[u] + rs;
            m_r[u] = nm;
            // stage P
#pragma unroll
            for (int v = 0; v < 4; v++)
                Ps[(ty * 4 + u) * SSTR + tx * 4 + v] = acc[u][v];
        }
        __syncthreads();

        // ---- O = O*pf + P @ V ----
#pragma unroll
        for (int u = 0; u < 4; u++)
#pragma unroll
            for (int v = 0; v < 4; v++) O[u][v] *= pf_[u];

#pragma unroll 8
        for (int j = 0; j < 64; j++) {
            float pf4[4], vf4[4];
#pragma unroll
            for (int u = 0; u < 4; u++) pf4[u] = Ps[(ty * 4 + u) * SSTR + j];
#pragma unroll
            for (int v = 0; v < 4; v++) vf4[v] = Vs[j * SSTR + tx * 4 + v];
#pragma unroll
            for (int u = 0; u < 4; u++)
#pragma unroll
                for (int v = 0; v < 4; v++)
                    O[u][v] = fmaf(pf4[u], vf4[v], O[u][v]);
        }
    }

    // ---- write output: out[b, l, h*64 + d] ----
#pragma unroll
    for (int u = 0; u < 4; u++) {
        float inv = 1.0f / l_r[u];
        int l = l0 + ty * 4 + u;
#pragma unroll
        for (int v = 0; v < 4; v++) {
            int d = tx * 4 + v;
            out[((size_t)(b * LEN + l)) * DIM + h * HD + d] = O[u][v] * inv;
        }
    }
}

// ---------------------------------------------------------------------------
// Launch
// ---------------------------------------------------------------------------
extern "C" void kernel_launch(void* const* d_in, const int* in_sizes, int n_in,
                              void* d_out, int out_size)
{
    const float* x    = (const float*)d_in[0];   // [4, 1024, 1024]
    const float* Wqkv = (const float*)d_in[1];   // [1024, 3072]
    const float* bqkv = (const float*)d_in[2];   // [3072]
    const float* emb  = (const float*)d_in[3];   // [2047, 64]
    float* out = (float*)d_out;                  // [4, 1024, 1024]

    cudaFuncSetAttribute(attn_kernel, cudaFuncAttributeMaxDynamicSharedMemorySize,
                         ATT_SMEM_BYTES);

    dim3 gq(3072 / 128, 4096 / 128);   // (24, 32)
    qkv_kernel<<<gq, 256>>>(x, Wqkv, bqkv);

    dim3 ga(LEN / 64, BATCH * HEADS);  // (16, 64)
    attn_kernel<<<ga, 256, ATT_SMEM_BYTES>>>(emb, out);
}

// round 5
// speedup vs baseline: 1.7857x; 1.0925x over previous
#include <cuda_runtime.h>

#define BATCH 4
#define LEN   1024
#define DIM   1024
#define HEADS 16
#define HD    64
#define SCALE 0.125f

typedef unsigned long long u64;

__device__ __forceinline__ u64 pk2(float lo, float hi) {
    u64 r; asm("mov.b64 %0, {%1, %2};" : "=l"(r) : "f"(lo), "f"(hi)); return r;
}
__device__ __forceinline__ u64 ffma2(u64 a, u64 b, u64 c) {
    u64 d; asm("fma.rn.f32x2 %0, %1, %2, %3;" : "=l"(d) : "l"(a), "l"(b), "l"(c)); return d;
}
__device__ __forceinline__ u64 fmul2(u64 a, u64 b) {
    u64 d; asm("mul.rn.f32x2 %0, %1, %2;" : "=l"(d) : "l"(a), "l"(b)); return d;
}
__device__ __forceinline__ float2 up2(u64 v) {
    float2 f; asm("mov.b64 {%0, %1}, %2;" : "=f"(f.x), "=f"(f.y) : "l"(v)); return f;
}

// Scratch: Q^T,K^T in [bh][d][l]; V in [bh][l][d]; E^T in [d][2048]
__device__ float g_qt[BATCH * HEADS * HD * LEN];
__device__ float g_kt[BATCH * HEADS * HD * LEN];
__device__ float g_v [BATCH * HEADS * LEN * HD];
__device__ float g_et[HD * 2048];

// ---------------------------------------------------------------------------
// Kernel 0: transpose dist_emb [2047,64] -> g_et [64][2048]
// ---------------------------------------------------------------------------
__global__ void etrans_kernel(const float* __restrict__ emb)
{
    int idx = blockIdx.x * 256 + threadIdx.x;
    if (idx < 2047 * 64) {
        int r = idx >> 6, c = idx & 63;
        g_et[c * 2048 + r] = emb[idx];
    }
}

// ---------------------------------------------------------------------------
// Kernel 1: QKV GEMM, f32x2.  C[4096,3072] = x @ W + b
// 128x128 tile, k-step 16, 256 thr, 8x8 microtile (cols split {4tx, 64+4tx}).
// ---------------------------------------------------------------------------
__global__ __launch_bounds__(256, 2) void qkv_kernel(
    const float* __restrict__ A,
    const float* __restrict__ B,
    const float* __restrict__ bias)
{
    __shared__ float As[16 * 132];
    __shared__ float Bs[16 * 132];

    const int tid = threadIdx.x;
    const int m0 = blockIdx.y * 128;
    const int n0 = blockIdx.x * 128;
    const int ri = (tid >> 4) * 8;
    const int ci = (tid & 15) * 4;

    u64 acc[8][4];
#pragma unroll
    for (int u = 0; u < 8; u++)
#pragma unroll
        for (int vp = 0; vp < 4; vp++) acc[u][vp] = 0ull;

    for (int k0 = 0; k0 < 1024; k0 += 16) {
#pragma unroll
        for (int q = 0; q < 2; q++) {
            int f = tid + 256 * q;
            int rm = f >> 2, kc = (f & 3) * 4;
            float4 va = *(const float4*)&A[(size_t)(m0 + rm) * 1024 + k0 + kc];
            As[(kc + 0) * 132 + rm] = va.x;
            As[(kc + 1) * 132 + rm] = va.y;
            As[(kc + 2) * 132 + rm] = va.z;
            As[(kc + 3) * 132 + rm] = va.w;
            int kb = f >> 5, cb = (f & 31) * 4;
            *(float4*)&Bs[kb * 132 + cb] =
                *(const float4*)&B[(size_t)(k0 + kb) * 3072 + n0 + cb];
        }
        __syncthreads();

#pragma unroll
        for (int kk = 0; kk < 16; kk++) {
            float4 a0 = *(const float4*)&As[kk * 132 + ri];
            float4 a1 = *(const float4*)&As[kk * 132 + ri + 4];
            float4 b0 = *(const float4*)&Bs[kk * 132 + ci];
            float4 b1 = *(const float4*)&Bs[kk * 132 + 64 + ci];
            float af[8] = {a0.x, a0.y, a0.z, a0.w, a1.x, a1.y, a1.z, a1.w};
            u64 bb[4] = {pk2(b0.x, b0.y), pk2(b0.z, b0.w),
                         pk2(b1.x, b1.y), pk2(b1.z, b1.w)};
#pragma unroll
            for (int u = 0; u < 8; u++) {
                u64 av = pk2(af[u], af[u]);
#pragma unroll
                for (int vp = 0; vp < 4; vp++)
                    acc[u][vp] = ffma2(av, bb[vp], acc[u][vp]);
            }
        }
        __syncthreads();
    }

#pragma unroll
    for (int u = 0; u < 8; u++) {
        int m = m0 + ri + u;
        int bb_ = m >> 10, l = m & 1023;
#pragma unroll
        for (int vp = 0; vp < 4; vp++) {
            float2 c = up2(acc[u][vp]);
            int base = (vp < 2) ? (ci + 2 * vp) : (64 + ci + 2 * (vp - 2));
#pragma unroll
            for (int h2 = 0; h2 < 2; h2++) {
                int n = n0 + base + h2;
                float val = (h2 ? c.y : c.x) + bias[n];
                int s = n >> 10, h = (n >> 6) & 15, hd = n & 63;
                int bh = bb_ * HEADS + h;
                if (s == 0)
                    g_qt[((size_t)bh * HD + hd) * LEN + l] = val;
                else if (s == 1)
                    g_kt[((size_t)bh * HD + hd) * LEN + l] = val;
                else
                    g_v [((size_t)bh * LEN + l) * HD + hd] = val;
            }
        }
    }
}

// ---------------------------------------------------------------------------
// Kernel 2: fused attention, f32x2, flash-style. CTA tile 64(l) x 64(r),
// 256 thr as 16x16, 4x4 microtile (u packed in pairs).
// smem: QT[64][64] KT[64][64] Vs[64][64] ET[64][128] Pt[64][68]
// ---------------------------------------------------------------------------
#define O_QT 0
#define O_KT 4096
#define O_V  8192
#define O_ET 12288
#define O_PT 20480
#define ATT_SMEM_BYTES ((20480 + 64 * 68) * 4)

__global__ __launch_bounds__(256) void attn_kernel(float* __restrict__ out)
{
    extern __shared__ float sm[];
    float* QT = sm + O_QT;
    float* KT = sm + O_KT;
    float* Vs = sm + O_V;
    float* ET = sm + O_ET;
    float* Pt = sm + O_PT;

    const int tid = threadIdx.x;
    const int tx = tid & 15;
    const int ty = tid >> 4;
    const int l0 = blockIdx.x * 64;
    const int bh = blockIdx.y;
    const int b = bh >> 4;
    const int h = bh & 15;
    const size_t bqt = (size_t)bh * HD * LEN;   // Q^T / K^T base
    const size_t bv  = (size_t)bh * LEN * HD;

    // load Q^T tile: rows d, cols l0..l0+63
#pragma unroll
    for (int it = 0; it < 4; it++) {
        int idx = tid + 256 * it;
        int d = idx >> 4, c4 = (idx & 15) * 4;
        *(float4*)&QT[d * 64 + c4] =
            *(const float4*)&g_qt[bqt + (size_t)d * LEN + l0 + c4];
    }

    float m_r[4], l_r[4], pf[4];
    u64 O2[2][4];
#pragma unroll
    for (int u = 0; u < 4; u++) { m_r[u] = -1e30f; l_r[u] = 0.0f; }
#pragma unroll
    for (int p = 0; p < 2; p++)
#pragma unroll
        for (int v = 0; v < 4; v++) O2[p][v] = 0ull;

    const int w0 = 4 * ty - 4 * tx + 60;   // E window base, 4-aligned, in [0,120]

    for (int j0 = 0; j0 < LEN; j0 += 64) {
        __syncthreads();
        // load K^T, V, E^T tiles
#pragma unroll
        for (int it = 0; it < 4; it++) {
            int idx = tid + 256 * it;
            int d = idx >> 4, c4 = (idx & 15) * 4;
            *(float4*)&KT[d * 64 + c4] =
                *(const float4*)&g_kt[bqt + (size_t)d * LEN + j0 + c4];
            *(float4*)&Vs[d * 64 + c4] =
                *(const float4*)&g_v[bv + (size_t)(j0 + d) * HD + c4];
        }
        {
            int ebase = l0 - j0 + 960;   // in [0,1920]
#pragma unroll
            for (int it = 0; it < 8; it++) {
                int idx = tid + 256 * it;
                int d = idx >> 5, c4 = (idx & 31) * 4;
                *(float4*)&ET[d * 128 + c4] =
                    *(const float4*)&g_et[(size_t)d * 2048 + ebase + c4];
            }
        }
        __syncthreads();

        // ---- S = q.k + q.e + k.e  (u-paired f32x2) ----
        u64 acc2[2][4];
#pragma unroll
        for (int p = 0; p < 2; p++)
#pragma unroll
            for (int v = 0; v < 4; v++) acc2[p][v] = 0ull;

#pragma unroll 4
        for (int d = 0; d < HD; d++) {
            float4 q4 = *(const float4*)&QT[d * 64 + 4 * ty];
            float4 k4 = *(const float4*)&KT[d * 64 + 4 * tx];
            float4 e0 = *(const float4*)&ET[d * 128 + w0];
            float4 e1 = *(const float4*)&ET[d * 128 + w0 + 4];
            float ew[8] = {e0.x, e0.y, e0.z, e0.w, e1.x, e1.y, e1.z, e1.w};
            u64 qq[2] = {pk2(q4.x, q4.y), pk2(q4.z, q4.w)};
            u64 kb[4] = {pk2(k4.x, k4.x), pk2(k4.y, k4.y),
                         pk2(k4.z, k4.z), pk2(k4.w, k4.w)};
            u64 ep[6];
#pragma unroll
            for (int j = 0; j < 6; j++) ep[j] = pk2(ew[j], ew[j + 1]);
#pragma unroll
            for (int p = 0; p < 2; p++)
#pragma unroll
                for (int v = 0; v < 4; v++) {
                    u64 e = ep[3 + 2 * p - v];
                    acc2[p][v] = ffma2(qq[p], kb[v], acc2[p][v]);
                    acc2[p][v] = ffma2(qq[p], e, acc2[p][v]);
                    acc2[p][v] = ffma2(kb[v], e, acc2[p][v]);
                }
        }

        // ---- online softmax (rows u = 2p + hi) ----
        float a[4][4];
#pragma unroll
        for (int p = 0; p < 2; p++)
#pragma unroll
            for (int v = 0; v < 4; v++) {
                float2 c = up2(acc2[p][v]);
                a[2 * p][v] = c.x * SCALE;
                a[2 * p + 1][v] = c.y * SCALE;
            }
#pragma unroll
        for (int u = 0; u < 4; u++) {
            float mx = fmaxf(fmaxf(a[u][0], a[u][1]), fmaxf(a[u][2], a[u][3]));
#pragma unroll
            for (int off = 8; off >= 1; off >>= 1)
                mx = fmaxf(mx, __shfl_xor_sync(0xffffffffu, mx, off));
            float nm = fmaxf(m_r[u], mx);
            pf[u] = __expf(m_r[u] - nm);
            float rs = 0.0f;
#pragma unroll
            for (int v = 0; v < 4; v++) {
                a[u][v] = __expf(a[u][v] - nm);
                rs += a[u][v];
            }
#pragma unroll
            for (int off = 8; off >= 1; off >>= 1)
                rs += __shfl_xor_sync(0xffffffffu, rs, off);
            l_r[u] = l_r[u] * pf[u] + rs;
            m_r[u] = nm;
        }
        // stage P transposed: Pt[r][l]
#pragma unroll
        for (int v = 0; v < 4; v++)
#pragma unroll
            for (int p = 0; p < 2; p++)
                *(float2*)&Pt[(4 * tx + v) * 68 + 4 * ty + 2 * p] =
                    make_float2(a[2 * p][v], a[2 * p + 1][v]);
        __syncthreads();

        // ---- O = O*pf + P @ V ----
#pragma unroll
        for (int p = 0; p < 2; p++) {
            u64 pfp = pk2(pf[2 * p], pf[2 * p + 1]);
#pragma unroll
            for (int v = 0; v < 4; v++) O2[p][v] = fmul2(O2[p][v], pfp);
        }
#pragma unroll 4
        for (int j = 0; j < 64; j++) {
            float4 pr = *(const float4*)&Pt[j * 68 + 4 * ty];
            float4 vv = *(const float4*)&Vs[j * 64 + 4 * tx];
            u64 pp[2] = {pk2(pr.x, pr.y), pk2(pr.z, pr.w)};
            u64 vb[4] = {pk2(vv.x, vv.x), pk2(vv.y, vv.y),
                         pk2(vv.z, vv.z), pk2(vv.w, vv.w)};
#pragma unroll
            for (int p = 0; p < 2; p++)
#pragma unroll
                for (int v = 0; v < 4; v++)
                    O2[p][v] = ffma2(pp[p], vb[v], O2[p][v]);
        }
    }

    // ---- write out[b][l][h*64+d] ----
#pragma unroll
    for (int u = 0; u < 4; u++) {
        float inv = 1.0f / l_r[u];
        int p = u >> 1, hi = u & 1;
        float o[4];
#pragma unroll
        for (int v = 0; v < 4; v++) {
            float2 c = up2(O2[p][v]);
            o[v] = (hi ? c.y : c.x) * inv;
        }
        int l = l0 + 4 * ty + u;
        *(float4*)&out[((size_t)(b * LEN + l)) * DIM + h * HD + 4 * tx] =
            make_float4(o[0], o[1], o[2], o[3]);
    }
}

// ---------------------------------------------------------------------------
extern "C" void kernel_launch(void* const* d_in, const int* in_sizes, int n_in,
                              void* d_out, int out_size)
{
    const float* x    = (const float*)d_in[0];
    const float* Wqkv = (const float*)d_in[1];
    const float* bqkv = (const float*)d_in[2];
    const float* emb  = (const float*)d_in[3];
    float* out = (float*)d_out;

    cudaFuncSetAttribute(attn_kernel, cudaFuncAttributeMaxDynamicSharedMemorySize,
                         ATT_SMEM_BYTES);

    etrans_kernel<<<512, 256>>>(emb);

    dim3 gq(3072 / 128, 4096 / 128);
    qkv_kernel<<<gq, 256>>>(x, Wqkv, bqkv);

    dim3 ga(LEN / 64, BATCH * HEADS);
    attn_kernel<<<ga, 256, ATT_SMEM_BYTES>>>(out);
}

// round 6
// speedup vs baseline: 2.0313x; 1.1376x over previous
#include <cuda_runtime.h>
#include <cuda_bf16.h>

#define BATCH 4
#define LEN   1024
#define DIM   1024
#define HEADS 16
#define HD    64
#define SCALE 0.125f

typedef unsigned long long u64;
typedef unsigned int u32;

__device__ __forceinline__ u64 pk2(float lo, float hi) {
    u64 r; asm("mov.b64 %0, {%1, %2};" : "=l"(r) : "f"(lo), "f"(hi)); return r;
}
__device__ __forceinline__ u64 ffma2(u64 a, u64 b, u64 c) {
    u64 d; asm("fma.rn.f32x2 %0, %1, %2, %3;" : "=l"(d) : "l"(a), "l"(b), "l"(c)); return d;
}
__device__ __forceinline__ float2 up2(u64 v) {
    float2 f; asm("mov.b64 {%0, %1}, %2;" : "=f"(f.x), "=f"(f.y) : "l"(v)); return f;
}
__device__ __forceinline__ float to_tf32(float x) {
    asm("cvt.rna.tf32.f32 %0, %0;" : "+f"(x)); return x;
}
__device__ __forceinline__ void mma8(float* d, const u32* a, u32 b0, u32 b1) {
    asm volatile(
        "mma.sync.aligned.m16n8k8.row.col.f32.tf32.tf32.f32 "
        "{%0,%1,%2,%3}, {%4,%5,%6,%7}, {%8,%9}, {%0,%1,%2,%3};"
        : "+f"(d[0]), "+f"(d[1]), "+f"(d[2]), "+f"(d[3])
        : "r"(a[0]), "r"(a[1]), "r"(a[2]), "r"(a[3]), "r"(b0), "r"(b1));
}

// Scratch (all values stored tf32-rounded): Q^T,K^T [bh][d][l]; V [bh][l][d];
// E^T [d][2048]
__device__ float g_qt[BATCH * HEADS * HD * LEN];
__device__ float g_kt[BATCH * HEADS * HD * LEN];
__device__ float g_v [BATCH * HEADS * LEN * HD];
__device__ float g_et[HD * 2048];

// ---------------------------------------------------------------------------
// Kernel 0: transpose + tf32-round dist_emb [2047,64] -> g_et [64][2048]
// ---------------------------------------------------------------------------
__global__ void etrans_kernel(const float* __restrict__ emb)
{
    int idx = blockIdx.x * 256 + threadIdx.x;
    if (idx < 2047 * 64) {
        int r = idx >> 6, c = idx & 63;
        g_et[c * 2048 + r] = to_tf32(emb[idx]);
    }
}

// ---------------------------------------------------------------------------
// Kernel 1: QKV GEMM (f32x2).  Epilogue stores tf32-rounded values.
// ---------------------------------------------------------------------------
__global__ __launch_bounds__(256, 2) void qkv_kernel(
    const float* __restrict__ A,
    const float* __restrict__ B,
    const float* __restrict__ bias)
{
    __shared__ float As[16 * 132];
    __shared__ float Bs[16 * 132];

    const int tid = threadIdx.x;
    const int m0 = blockIdx.y * 128;
    const int n0 = blockIdx.x * 128;
    const int ri = (tid >> 4) * 8;
    const int ci = (tid & 15) * 4;

    u64 acc[8][4];
#pragma unroll
    for (int u = 0; u < 8; u++)
#pragma unroll
        for (int vp = 0; vp < 4; vp++) acc[u][vp] = 0ull;

    for (int k0 = 0; k0 < 1024; k0 += 16) {
#pragma unroll
        for (int q = 0; q < 2; q++) {
            int f = tid + 256 * q;
            int rm = f >> 2, kc = (f & 3) * 4;
            float4 va = *(const float4*)&A[(size_t)(m0 + rm) * 1024 + k0 + kc];
            As[(kc + 0) * 132 + rm] = va.x;
            As[(kc + 1) * 132 + rm] = va.y;
            As[(kc + 2) * 132 + rm] = va.z;
            As[(kc + 3) * 132 + rm] = va.w;
            int kb = f >> 5, cb = (f & 31) * 4;
            *(float4*)&Bs[kb * 132 + cb] =
                *(const float4*)&B[(size_t)(k0 + kb) * 3072 + n0 + cb];
        }
        __syncthreads();

#pragma unroll
        for (int kk = 0; kk < 16; kk++) {
            float4 a0 = *(const float4*)&As[kk * 132 + ri];
            float4 a1 = *(const float4*)&As[kk * 132 + ri + 4];
            float4 b0 = *(const float4*)&Bs[kk * 132 + ci];
            float4 b1 = *(const float4*)&Bs[kk * 132 + 64 + ci];
            float af[8] = {a0.x, a0.y, a0.z, a0.w, a1.x, a1.y, a1.z, a1.w};
            u64 bb[4] = {pk2(b0.x, b0.y), pk2(b0.z, b0.w),
                         pk2(b1.x, b1.y), pk2(b1.z, b1.w)};
#pragma unroll
            for (int u = 0; u < 8; u++) {
                u64 av = pk2(af[u], af[u]);
#pragma unroll
                for (int vp = 0; vp < 4; vp++)
                    acc[u][vp] = ffma2(av, bb[vp], acc[u][vp]);
            }
        }
        __syncthreads();
    }

#pragma unroll
    for (int u = 0; u < 8; u++) {
        int m = m0 + ri + u;
        int bb_ = m >> 10, l = m & 1023;
#pragma unroll
        for (int vp = 0; vp < 4; vp++) {
            float2 c = up2(acc[u][vp]);
            int base = (vp < 2) ? (ci + 2 * vp) : (64 + ci + 2 * (vp - 2));
#pragma unroll
            for (int h2 = 0; h2 < 2; h2++) {
                int n = n0 + base + h2;
                float val = to_tf32(((h2 ? c.y : c.x) + bias[n]));
                int s = n >> 10, h = (n >> 6) & 15, hd = n & 63;
                int bh = bb_ * HEADS + h;
                if (s == 0)
                    g_qt[((size_t)bh * HD + hd) * LEN + l] = val;
                else if (s == 1)
                    g_kt[((size_t)bh * HD + hd) * LEN + l] = val;
                else
                    g_v [((size_t)bh * LEN + l) * HD + hd] = val;
            }
        }
    }
}

// ---------------------------------------------------------------------------
// Kernel 2: tf32 mma flash attention with relative_key_query bias.
// CTA = 256 thr (8 warps), l-tile 128, r-tile 64.
// smem (floats): QT[64][136] KT[64][72] Vs[64][72] ET[64][200] (Ps[128][76]
// overlays ET), Gq bf16[128][200], Gk bf16[64][200].
// ---------------------------------------------------------------------------
#define oQT 0
#define oKT 8704
#define oVS 13312
#define oET 17920
#define oGQ 30720
#define oGK 43520
#define SMEMF 49920
#define ATT_SMEM_BYTES (SMEMF * 4)

__global__ __launch_bounds__(256) void attn_kernel(float* __restrict__ out)
{
    extern __shared__ float sm[];
    float* QT = sm + oQT;
    float* KT = sm + oKT;
    float* Vs = sm + oVS;
    float* ET = sm + oET;
    float* Ps = sm + oET;   // overlay: P written after all ET reads of this iter
    __nv_bfloat16* Gq = (__nv_bfloat16*)(sm + oGQ);
    __nv_bfloat16* Gk = (__nv_bfloat16*)(sm + oGK);

    const int tid  = threadIdx.x;
    const int wid  = tid >> 5;
    const int lane = tid & 31;
    const int g    = lane >> 2;
    const int kq   = lane & 3;
    const int l0 = blockIdx.x * 128;
    const int bh = blockIdx.y;
    const int b = bh >> 4, h = bh & 15;
    const size_t bqt = (size_t)bh * HD * LEN;
    const size_t bv  = (size_t)bh * LEN * HD;

    // Q tile: QT[d][l], 64 x 128 (tf32 already)
#pragma unroll 4
    for (int it = 0; it < 32; it++) {
        int idx = tid + 256 * it;
        int d = idx >> 7, c = idx & 127;
        QT[d * 136 + c] = g_qt[bqt + (size_t)d * LEN + l0 + c];
    }

    const int i0  = 16 * wid + g;           // rows for phase A / softmax / PV
    const int wmk = wid & 3, wnk = wid >> 2; // Gk layout
    const int rk0 = 16 * wmk + g;

    float mrun0 = -1e30f, mrun1 = -1e30f, lrun0 = 0.f, lrun1 = 0.f;
    float O[8][4];
#pragma unroll
    for (int t = 0; t < 8; t++)
#pragma unroll
        for (int c = 0; c < 4; c++) O[t][c] = 0.f;

    for (int j0 = 0; j0 < LEN; j0 += 64) {
        __syncthreads();
        // ---- tile loads ----
#pragma unroll 4
        for (int it = 0; it < 16; it++) {
            int idx = tid + 256 * it;
            int r0_ = idx >> 6, c = idx & 63;
            KT[r0_ * 72 + c] = g_kt[bqt + (size_t)r0_ * LEN + j0 + c]; // r0_=d
            Vs[r0_ * 72 + c] = g_v [bv + (size_t)(j0 + r0_) * HD + c];
        }
        {
            int ebase = l0 - j0 + 960;   // [0,1856]
            const float* src = g_et + (size_t)(8 * wid) * 2048 + ebase;
            float* dst = ET + (8 * wid) * 200;
#pragma unroll
            for (int dd = 0; dd < 8; dd++)
#pragma unroll
                for (int s = 0; s < 6; s++)
                    dst[dd * 200 + lane + 32 * s] = src[dd * 2048 + lane + 32 * s];
        }
        __syncthreads();

        // ---- phase A: S1 = Q@K^T (rows i0 band, all 64 cols) ----
        float accS[8][4];
#pragma unroll
        for (int t = 0; t < 8; t++)
#pragma unroll
            for (int c = 0; c < 4; c++) accS[t][c] = 0.f;
#pragma unroll 2
        for (int ks = 0; ks < 8; ks++) {
            int kr = 8 * ks + kq;
            u32 a[4];
            a[0] = __float_as_uint(QT[kr * 136 + i0]);
            a[1] = __float_as_uint(QT[kr * 136 + i0 + 8]);
            a[2] = __float_as_uint(QT[(kr + 4) * 136 + i0]);
            a[3] = __float_as_uint(QT[(kr + 4) * 136 + i0 + 8]);
#pragma unroll
            for (int t = 0; t < 8; t++) {
                u32 b0 = __float_as_uint(KT[kr * 72 + 8 * t + g]);
                u32 b1 = __float_as_uint(KT[(kr + 4) * 72 + 8 * t + g]);
                mma8(accS[t], a, b0, b1);
            }
        }

        // ---- Gq = Q@Ew^T, 3 chunks of 64 cols, store bf16 ----
#pragma unroll 1
        for (int ch = 0; ch < 3; ch++) {
            float acc[8][4];
#pragma unroll
            for (int t = 0; t < 8; t++)
#pragma unroll
                for (int c = 0; c < 4; c++) acc[t][c] = 0.f;
#pragma unroll 2
            for (int ks = 0; ks < 8; ks++) {
                int kr = 8 * ks + kq;
                u32 a[4];
                a[0] = __float_as_uint(QT[kr * 136 + i0]);
                a[1] = __float_as_uint(QT[kr * 136 + i0 + 8]);
                a[2] = __float_as_uint(QT[(kr + 4) * 136 + i0]);
                a[3] = __float_as_uint(QT[(kr + 4) * 136 + i0 + 8]);
#pragma unroll
                for (int t = 0; t < 8; t++) {
                    int n = 64 * ch + 8 * t + g;
                    u32 b0 = __float_as_uint(ET[kr * 200 + n]);
                    u32 b1 = __float_as_uint(ET[(kr + 4) * 200 + n]);
                    mma8(acc[t], a, b0, b1);
                }
            }
#pragma unroll
            for (int t = 0; t < 8; t++) {
                int n = 64 * ch + 8 * t + 2 * kq;
                *(__nv_bfloat162*)&Gq[i0 * 200 + n] =
                    __floats2bfloat162_rn(acc[t][0], acc[t][1]);
                *(__nv_bfloat162*)&Gq[(i0 + 8) * 200 + n] =
                    __floats2bfloat162_rn(acc[t][2], acc[t][3]);
            }
        }

        // ---- Gk = K@Ew^T, warps 4x2, 2 chunks of 48 cols ----
#pragma unroll 1
        for (int ch = 0; ch < 2; ch++) {
            float acc[6][4];
#pragma unroll
            for (int t = 0; t < 6; t++)
#pragma unroll
                for (int c = 0; c < 4; c++) acc[t][c] = 0.f;
#pragma unroll 2
            for (int ks = 0; ks < 8; ks++) {
                int kr = 8 * ks + kq;
                u32 a[4];
                a[0] = __float_as_uint(KT[kr * 72 + rk0]);
                a[1] = __float_as_uint(KT[kr * 72 + rk0 + 8]);
                a[2] = __float_as_uint(KT[(kr + 4) * 72 + rk0]);
                a[3] = __float_as_uint(KT[(kr + 4) * 72 + rk0 + 8]);
#pragma unroll
                for (int t = 0; t < 6; t++) {
                    int n = 96 * wnk + 48 * ch + 8 * t + g;
                    u32 b0 = __float_as_uint(ET[kr * 200 + n]);
                    u32 b1 = __float_as_uint(ET[(kr + 4) * 200 + n]);
                    mma8(acc[t], a, b0, b1);
                }
            }
#pragma unroll
            for (int t = 0; t < 6; t++) {
                int n = 96 * wnk + 48 * ch + 8 * t + 2 * kq;
                *(__nv_bfloat162*)&Gk[rk0 * 200 + n] =
                    __floats2bfloat162_rn(acc[t][0], acc[t][1]);
                *(__nv_bfloat162*)&Gk[(rk0 + 8) * 200 + n] =
                    __floats2bfloat162_rn(acc[t][2], acc[t][3]);
            }
        }
        __syncthreads();

        // ---- gather bias + online softmax (warp-local rows) ----
#pragma unroll
        for (int t = 0; t < 8; t++)
#pragma unroll
            for (int e = 0; e < 2; e++) {
                int j = 8 * t + 2 * kq + e;
                int d0 = i0 - j + 63;       // [0,190]
                float gq0 = __bfloat162float(Gq[i0 * 200 + d0]);
                float gk0 = __bfloat162float(Gk[j * 200 + d0]);
                float gq1 = __bfloat162float(Gq[(i0 + 8) * 200 + d0 + 8]);
                float gk1 = __bfloat162float(Gk[j * 200 + d0 + 8]);
                accS[t][e]     = (accS[t][e]     + gq0 + gk0) * SCALE;
                accS[t][2 + e] = (accS[t][2 + e] + gq1 + gk1) * SCALE;
            }

        float mx0 = -1e30f, mx1 = -1e30f;
#pragma unroll
        for (int t = 0; t < 8; t++) {
            mx0 = fmaxf(mx0, fmaxf(accS[t][0], accS[t][1]));
            mx1 = fmaxf(mx1, fmaxf(accS[t][2], accS[t][3]));
        }
        mx0 = fmaxf(mx0, __shfl_xor_sync(0xffffffffu, mx0, 1));
        mx0 = fmaxf(mx0, __shfl_xor_sync(0xffffffffu, mx0, 2));
        mx1 = fmaxf(mx1, __shfl_xor_sync(0xffffffffu, mx1, 1));
        mx1 = fmaxf(mx1, __shfl_xor_sync(0xffffffffu, mx1, 2));
        float nm0 = fmaxf(mrun0, mx0), nm1 = fmaxf(mrun1, mx1);
        float pf0 = __expf(mrun0 - nm0), pf1 = __expf(mrun1 - nm1);
        float s0 = 0.f, s1 = 0.f;
#pragma unroll
        for (int t = 0; t < 8; t++) {
            accS[t][0] = __expf(accS[t][0] - nm0);
            accS[t][1] = __expf(accS[t][1] - nm0);
            accS[t][2] = __expf(accS[t][2] - nm1);
            accS[t][3] = __expf(accS[t][3] - nm1);
            s0 += accS[t][0] + accS[t][1];
            s1 += accS[t][2] + accS[t][3];
        }
        s0 += __shfl_xor_sync(0xffffffffu, s0, 1);
        s0 += __shfl_xor_sync(0xffffffffu, s0, 2);
        s1 += __shfl_xor_sync(0xffffffffu, s1, 1);
        s1 += __shfl_xor_sync(0xffffffffu, s1, 2);
        lrun0 = lrun0 * pf0 + s0;  mrun0 = nm0;
        lrun1 = lrun1 * pf1 + s1;  mrun1 = nm1;

        // write P (tf32) into Ps (overlay on ET)
#pragma unroll
        for (int t = 0; t < 8; t++) {
            int n = 8 * t + 2 * kq;
            *(float2*)&Ps[i0 * 76 + n] =
                make_float2(to_tf32(accS[t][0]), to_tf32(accS[t][1]));
            *(float2*)&Ps[(i0 + 8) * 76 + n] =
                make_float2(to_tf32(accS[t][2]), to_tf32(accS[t][3]));
            O[t][0] *= pf0; O[t][1] *= pf0; O[t][2] *= pf1; O[t][3] *= pf1;
        }
        __syncthreads();

        // ---- O += P @ V ----
#pragma unroll 2
        for (int ks = 0; ks < 8; ks++) {
            int kr = 8 * ks + kq;
            u32 a[4];
            a[0] = __float_as_uint(Ps[i0 * 76 + kr]);
            a[1] = __float_as_uint(Ps[(i0 + 8) * 76 + kr]);
            a[2] = __float_as_uint(Ps[i0 * 76 + kr + 4]);
            a[3] = __float_as_uint(Ps[(i0 + 8) * 76 + kr + 4]);
#pragma unroll
            for (int t = 0; t < 8; t++) {
                u32 b0 = __float_as_uint(Vs[kr * 72 + 8 * t + g]);
                u32 b1 = __float_as_uint(Vs[(kr + 4) * 72 + 8 * t + g]);
                mma8(O[t], a, b0, b1);
            }
        }
    }

    // ---- epilogue ----
    float inv0 = 1.0f / lrun0, inv1 = 1.0f / lrun1;
#pragma unroll
    for (int t = 0; t < 8; t++) {
        int col = h * HD + 8 * t + 2 * kq;
        size_t r0a = ((size_t)(b * LEN + l0 + i0)) * DIM + col;
        size_t r1a = ((size_t)(b * LEN + l0 + i0 + 8)) * DIM + col;
        *(float2*)&out[r0a] = make_float2(O[t][0] * inv0, O[t][1] * inv0);
        *(float2*)&out[r1a] = make_float2(O[t][2] * inv1, O[t][3] * inv1);
    }
}

// ---------------------------------------------------------------------------
extern "C" void kernel_launch(void* const* d_in, const int* in_sizes, int n_in,
                              void* d_out, int out_size)
{
    const float* x    = (const float*)d_in[0];
    const float* Wqkv = (const float*)d_in[1];
    const float* bqkv = (const float*)d_in[2];
    const float* emb  = (const float*)d_in[3];
    float* out = (float*)d_out;

    cudaFuncSetAttribute(attn_kernel, cudaFuncAttributeMaxDynamicSharedMemorySize,
                         ATT_SMEM_BYTES);

    etrans_kernel<<<512, 256>>>(emb);

    dim3 gq(3072 / 128, 4096 / 128);
    qkv_kernel<<<gq, 256>>>(x, Wqkv, bqkv);

    dim3 ga(LEN / 128, BATCH * HEADS);
    attn_kernel<<<ga, 256, ATT_SMEM_BYTES>>>(out);
}

// round 7
// speedup vs baseline: 2.8009x; 1.3789x over previous
#include <cuda_runtime.h>
#include <cuda_bf16.h>

#define BATCH 4
#define LEN   1024
#define DIM   1024
#define HEADS 16
#define HD    64
#define SCALE 0.125f

typedef unsigned long long u64;
typedef unsigned int u32;

__device__ __forceinline__ float to_tf32(float x) {
    asm("cvt.rna.tf32.f32 %0, %0;" : "+f"(x)); return x;
}
__device__ __forceinline__ void mma8(float* d, const u32* a, u32 b0, u32 b1) {
    asm volatile(
        "mma.sync.aligned.m16n8k8.row.col.f32.tf32.tf32.f32 "
        "{%0,%1,%2,%3}, {%4,%5,%6,%7}, {%8,%9}, {%0,%1,%2,%3};"
        : "+f"(d[0]), "+f"(d[1]), "+f"(d[2]), "+f"(d[3])
        : "r"(a[0]), "r"(a[1]), "r"(a[2]), "r"(a[3]), "r"(b0), "r"(b1));
}

// Scratch (tf32-rounded): Q^T,K^T [bh][d][l]; V [bh][l][d]; E^T [d][2048]
__device__ float g_qt[BATCH * HEADS * HD * LEN];
__device__ float g_kt[BATCH * HEADS * HD * LEN];
__device__ float g_v [BATCH * HEADS * LEN * HD];
__device__ float g_et[HD * 2048];

// ---------------------------------------------------------------------------
// Kernel 0: transpose + tf32-round dist_emb [2047,64] -> g_et [64][2048]
// ---------------------------------------------------------------------------
__global__ void etrans_kernel(const float* __restrict__ emb)
{
    int idx = blockIdx.x * 256 + threadIdx.x;
    if (idx < 2047 * 64) {
        int r = idx >> 6, c = idx & 63;
        g_et[c * 2048 + r] = to_tf32(emb[idx]);
    }
}

// ---------------------------------------------------------------------------
// Kernel 1: QKV GEMM on tf32 tensor cores.
// C[4096,3072] = x[4096,1024] @ W[1024,3072] + b
// CTA 128x128, k-chunk 32, 8 warps (2m x 4n), warp tile 64x32 (4x4 mma m16n8k8).
// As[m][k] stride 36 (conflict-free frag loads: bank = 4g+kq).
// Bs[k][n] stride 136 (conflict-free: bank = 8kq+g).
// ---------------------------------------------------------------------------
#define ASTR 36
#define BSTR 136

__global__ __launch_bounds__(256, 2) void qkv_kernel(
    const float* __restrict__ A,
    const float* __restrict__ B,
    const float* __restrict__ bias)
{
    __shared__ float As[128 * ASTR];
    __shared__ float Bs[32 * BSTR];

    const int tid  = threadIdx.x;
    const int wid  = tid >> 5;
    const int lane = tid & 31;
    const int g    = lane >> 2;
    const int kq   = lane & 3;
    const int wm   = wid & 1;
    const int wn   = wid >> 1;
    const int m0 = blockIdx.y * 128;
    const int n0 = blockIdx.x * 128;

    float acc[4][4][4];
#pragma unroll
    for (int mt = 0; mt < 4; mt++)
#pragma unroll
        for (int nt = 0; nt < 4; nt++)
#pragma unroll
            for (int c = 0; c < 4; c++) acc[mt][nt][c] = 0.f;

    for (int k0 = 0; k0 < 1024; k0 += 32) {
        // load A tile 128x32 (natural layout) and B tile 32x128
#pragma unroll
        for (int it = 0; it < 4; it++) {
            int f = tid + 256 * it;
            int rm = f >> 3, kc = (f & 7) * 4;
            float4 va = *(const float4*)&A[(size_t)(m0 + rm) * 1024 + k0 + kc];
            va.x = to_tf32(va.x); va.y = to_tf32(va.y);
            va.z = to_tf32(va.z); va.w = to_tf32(va.w);
            *(float4*)&As[rm * ASTR + kc] = va;

            int kb = f >> 5, cb = (f & 31) * 4;
            float4 vb = *(const float4*)&B[(size_t)(k0 + kb) * 3072 + n0 + cb];
            vb.x = to_tf32(vb.x); vb.y = to_tf32(vb.y);
            vb.z = to_tf32(vb.z); vb.w = to_tf32(vb.w);
            *(float4*)&Bs[kb * BSTR + cb] = vb;
        }
        __syncthreads();

#pragma unroll
        for (int s = 0; s < 4; s++) {
            int kk = 8 * s + kq;
            u32 a[4][4];
#pragma unroll
            for (int mt = 0; mt < 4; mt++) {
                int r = 64 * wm + 16 * mt + g;
                a[mt][0] = __float_as_uint(As[r * ASTR + kk]);
                a[mt][1] = __float_as_uint(As[(r + 8) * ASTR + kk]);
                a[mt][2] = __float_as_uint(As[r * ASTR + kk + 4]);
                a[mt][3] = __float_as_uint(As[(r + 8) * ASTR + kk + 4]);
            }
            u32 b0[4], b1[4];
#pragma unroll
            for (int nt = 0; nt < 4; nt++) {
                int c = 32 * wn + 8 * nt + g;
                b0[nt] = __float_as_uint(Bs[kk * BSTR + c]);
                b1[nt] = __float_as_uint(Bs[(kk + 4) * BSTR + c]);
            }
#pragma unroll
            for (int mt = 0; mt < 4; mt++)
#pragma unroll
                for (int nt = 0; nt < 4; nt++)
                    mma8(acc[mt][nt], a[mt], b0[nt], b1[nt]);
        }
        __syncthreads();
    }

    // epilogue: bias add, tf32 round, scatter into Q^T / K^T / V
#pragma unroll
    for (int mt = 0; mt < 4; mt++) {
        int r0 = m0 + 64 * wm + 16 * mt + g;
#pragma unroll
        for (int nt = 0; nt < 4; nt++) {
            int c0 = n0 + 32 * wn + 8 * nt + 2 * kq;
#pragma unroll
            for (int e = 0; e < 4; e++) {
                int m = r0 + (e >> 1) * 8;          // e: 0,1 -> r0; 2,3 -> r0+8
                int n = c0 + (e & 1);
                float val = to_tf32(acc[mt][nt][e] + bias[n]);
                int bb = m >> 10, l = m & 1023;
                int s = n >> 10, h = (n >> 6) & 15, hd = n & 63;
                int bh = bb * HEADS + h;
                if (s == 0)
                    g_qt[((size_t)bh * HD + hd) * LEN + l] = val;
                else if (s == 1)
                    g_kt[((size_t)bh * HD + hd) * LEN + l] = val;
                else
                    g_v [((size_t)bh * LEN + l) * HD + hd] = val;
            }
        }
    }
}

// ---------------------------------------------------------------------------
// Kernel 2: tf32 mma flash attention with relative_key_query bias.
// (unchanged from Round 6 passing version)
// ---------------------------------------------------------------------------
#define oQT 0
#define oKT 8704
#define oVS 13312
#define oET 17920
#define oGQ 30720
#define oGK 43520
#define SMEMF 49920
#define ATT_SMEM_BYTES (SMEMF * 4)

__global__ __launch_bounds__(256) void attn_kernel(float* __restrict__ out)
{
    extern __shared__ float sm[];
    float* QT = sm + oQT;
    float* KT = sm + oKT;
    float* Vs = sm + oVS;
    float* ET = sm + oET;
    float* Ps = sm + oET;   // overlay
    __nv_bfloat16* Gq = (__nv_bfloat16*)(sm + oGQ);
    __nv_bfloat16* Gk = (__nv_bfloat16*)(sm + oGK);

    const int tid  = threadIdx.x;
    const int wid  = tid >> 5;
    const int lane = tid & 31;
    const int g    = lane >> 2;
    const int kq   = lane & 3;
    const int l0 = blockIdx.x * 128;
    const int bh = blockIdx.y;
    const int b = bh >> 4, h = bh & 15;
    const size_t bqt = (size_t)bh * HD * LEN;
    const size_t bv  = (size_t)bh * LEN * HD;

#pragma unroll 4
    for (int it = 0; it < 32; it++) {
        int idx = tid + 256 * it;
        int d = idx >> 7, c = idx & 127;
        QT[d * 136 + c] = g_qt[bqt + (size_t)d * LEN + l0 + c];
    }

    const int i0  = 16 * wid + g;
    const int wmk = wid & 3, wnk = wid >> 2;
    const int rk0 = 16 * wmk + g;

    float mrun0 = -1e30f, mrun1 = -1e30f, lrun0 = 0.f, lrun1 = 0.f;
    float O[8][4];
#pragma unroll
    for (int t = 0; t < 8; t++)
#pragma unroll
        for (int c = 0; c < 4; c++) O[t][c] = 0.f;

    for (int j0 = 0; j0 < LEN; j0 += 64) {
        __syncthreads();
#pragma unroll 4
        for (int it = 0; it < 16; it++) {
            int idx = tid + 256 * it;
            int r0_ = idx >> 6, c = idx & 63;
            KT[r0_ * 72 + c] = g_kt[bqt + (size_t)r0_ * LEN + j0 + c];
            Vs[r0_ * 72 + c] = g_v [bv + (size_t)(j0 + r0_) * HD + c];
        }
        {
            int ebase = l0 - j0 + 960;
            const float* src = g_et + (size_t)(8 * wid) * 2048 + ebase;
            float* dst = ET + (8 * wid) * 200;
#pragma unroll
            for (int dd = 0; dd < 8; dd++)
#pragma unroll
                for (int s = 0; s < 6; s++)
                    dst[dd * 200 + lane + 32 * s] = src[dd * 2048 + lane + 32 * s];
        }
        __syncthreads();

        float accS[8][4];
#pragma unroll
        for (int t = 0; t < 8; t++)
#pragma unroll
            for (int c = 0; c < 4; c++) accS[t][c] = 0.f;
#pragma unroll 2
        for (int ks = 0; ks < 8; ks++) {
            int kr = 8 * ks + kq;
            u32 a[4];
            a[0] = __float_as_uint(QT[kr * 136 + i0]);
            a[1] = __float_as_uint(QT[kr * 136 + i0 + 8]);
            a[2] = __float_as_uint(QT[(kr + 4) * 136 + i0]);
            a[3] = __float_as_uint(QT[(kr + 4) * 136 + i0 + 8]);
#pragma unroll
            for (int t = 0; t < 8; t++) {
                u32 b0 = __float_as_uint(KT[kr * 72 + 8 * t + g]);
                u32 b1 = __float_as_uint(KT[(kr + 4) * 72 + 8 * t + g]);
                mma8(accS[t], a, b0, b1);
            }
        }

#pragma unroll 1
        for (int ch = 0; ch < 3; ch++) {
            float acc[8][4];
#pragma unroll
            for (int t = 0; t < 8; t++)
#pragma unroll
                for (int c = 0; c < 4; c++) acc[t][c] = 0.f;
#pragma unroll 2
            for (int ks = 0; ks < 8; ks++) {
                int kr = 8 * ks + kq;
                u32 a[4];
                a[0] = __float_as_uint(QT[kr * 136 + i0]);
                a[1] = __float_as_uint(QT[kr * 136 + i0 + 8]);
                a[2] = __float_as_uint(QT[(kr + 4) * 136 + i0]);
                a[3] = __float_as_uint(QT[(kr + 4) * 136 + i0 + 8]);
#pragma unroll
                for (int t = 0; t < 8; t++) {
                    int n = 64 * ch + 8 * t + g;
                    u32 b0 = __float_as_uint(ET[kr * 200 + n]);
                    u32 b1 = __float_as_uint(ET[(kr + 4) * 200 + n]);
                    mma8(acc[t], a, b0, b1);
                }
            }
#pragma unroll
            for (int t = 0; t < 8; t++) {
                int n = 64 * ch + 8 * t + 2 * kq;
                *(__nv_bfloat162*)&Gq[i0 * 200 + n] =
                    __floats2bfloat162_rn(acc[t][0], acc[t][1]);
                *(__nv_bfloat162*)&Gq[(i0 + 8) * 200 + n] =
                    __floats2bfloat162_rn(acc[t][2], acc[t][3]);
            }
        }

#pragma unroll 1
        for (int ch = 0; ch < 2; ch++) {
            float acc[6][4];
#pragma unroll
            for (int t = 0; t < 6; t++)
#pragma unroll
                for (int c = 0; c < 4; c++) acc[t][c] = 0.f;
#pragma unroll 2
            for (int ks = 0; ks < 8; ks++) {
                int kr = 8 * ks + kq;
                u32 a[4];
                a[0] = __float_as_uint(KT[kr * 72 + rk0]);
                a[1] = __float_as_uint(KT[kr * 72 + rk0 + 8]);
                a[2] = __float_as_uint(KT[(kr + 4) * 72 + rk0]);
                a[3] = __float_as_uint(KT[(kr + 4) * 72 + rk0 + 8]);
#pragma unroll
                for (int t = 0; t < 6; t++) {
                    int n = 96 * wnk + 48 * ch + 8 * t + g;
                    u32 b0 = __float_as_uint(ET[kr * 200 + n]);
                    u32 b1 = __float_as_uint(ET[(kr + 4) * 200 + n]);
                    mma8(acc[t], a, b0, b1);
                }
            }
#pragma unroll
            for (int t = 0; t < 6; t++) {
                int n = 96 * wnk + 48 * ch + 8 * t + 2 * kq;
                *(__nv_bfloat162*)&Gk[rk0 * 200 + n] =
                    __floats2bfloat162_rn(acc[t][0], acc[t][1]);
                *(__nv_bfloat162*)&Gk[(rk0 + 8) * 200 + n] =
                    __floats2bfloat162_rn(acc[t][2], acc[t][3]);
            }
        }
        __syncthreads();

#pragma unroll
        for (int t = 0; t < 8; t++)
#pragma unroll
            for (int e = 0; e < 2; e++) {
                int j = 8 * t + 2 * kq + e;
                int d0 = i0 - j + 63;
                float gq0 = __bfloat162float(Gq[i0 * 200 + d0]);
                float gk0 = __bfloat162float(Gk[j * 200 + d0]);
                float gq1 = __bfloat162float(Gq[(i0 + 8) * 200 + d0 + 8]);
                float gk1 = __bfloat162float(Gk[j * 200 + d0 + 8]);
                accS[t][e]     = (accS[t][e]     + gq0 + gk0) * SCALE;
                accS[t][2 + e] = (accS[t][2 + e] + gq1 + gk1) * SCALE;
            }

        float mx0 = -1e30f, mx1 = -1e30f;
#pragma unroll
        for (int t = 0; t < 8; t++) {
            mx0 = fmaxf(mx0, fmaxf(accS[t][0], accS[t][1]));
            mx1 = fmaxf(mx1, fmaxf(accS[t][2], accS[t][3]));
        }
        mx0 = fmaxf(mx0, __shfl_xor_sync(0xffffffffu, mx0, 1));
        mx0 = fmaxf(mx0, __shfl_xor_sync(0xffffffffu, mx0, 2));
        mx1 = fmaxf(mx1, __shfl_xor_sync(0xffffffffu, mx1, 1));
        mx1 = fmaxf(mx1, __shfl_xor_sync(0xffffffffu, mx1, 2));
        float nm0 = fmaxf(mrun0, mx0), nm1 = fmaxf(mrun1, mx1);
        float pf0 = __expf(mrun0 - nm0), pf1 = __expf(mrun1 - nm1);
        float s0 = 0.f, s1 = 0.f;
#pragma unroll
        for (int t = 0; t < 8; t++) {
            accS[t][0] = __expf(accS[t][0] - nm0);
            accS[t][1] = __expf(accS[t][1] - nm0);
            accS[t][2] = __expf(accS[t][2] - nm1);
            accS[t][3] = __expf(accS[t][3] - nm1);
            s0 += accS[t][0] + accS[t][1];
            s1 += accS[t][2] + accS[t][3];
        }
        s0 += __shfl_xor_sync(0xffffffffu, s0, 1);
        s0 += __shfl_xor_sync(0xffffffffu, s0, 2);
        s1 += __shfl_xor_sync(0xffffffffu, s1, 1);
        s1 += __shfl_xor_sync(0xffffffffu, s1, 2);
        lrun0 = lrun0 * pf0 + s0;  mrun0 = nm0;
        lrun1 = lrun1 * pf1 + s1;  mrun1 = nm1;

#pragma unroll
        for (int t = 0; t < 8; t++) {
            int n = 8 * t + 2 * kq;
            *(float2*)&Ps[i0 * 76 + n] =
                make_float2(to_tf32(accS[t][0]), to_tf32(accS[t][1]));
            *(float2*)&Ps[(i0 + 8) * 76 + n] =
                make_float2(to_tf32(accS[t][2]), to_tf32(accS[t][3]));
            O[t][0] *= pf0; O[t][1] *= pf0; O[t][2] *= pf1; O[t][3] *= pf1;
        }
        __syncthreads();

#pragma unroll 2
        for (int ks = 0; ks < 8; ks++) {
            int kr = 8 * ks + kq;
            u32 a[4];
            a[0] = __float_as_uint(Ps[i0 * 76 + kr]);
            a[1] = __float_as_uint(Ps[(i0 + 8) * 76 + kr]);
            a[2] = __float_as_uint(Ps[i0 * 76 + kr + 4]);
            a[3] = __float_as_uint(Ps[(i0 + 8) * 76 + kr + 4]);
#pragma unroll
            for (int t = 0; t < 8; t++) {
                u32 b0 = __float_as_uint(Vs[kr * 72 + 8 * t + g]);
                u32 b1 = __float_as_uint(Vs[(kr + 4) * 72 + 8 * t + g]);
                mma8(O[t], a, b0, b1);
            }
        }
    }

    float inv0 = 1.0f / lrun0, inv1 = 1.0f / lrun1;
#pragma unroll
    for (int t = 0; t < 8; t++) {
        int col = h * HD + 8 * t + 2 * kq;
        size_t r0a = ((size_t)(b * LEN + l0 + i0)) * DIM + col;
        size_t r1a = ((size_t)(b * LEN + l0 + i0 + 8)) * DIM + col;
        *(float2*)&out[r0a] = make_float2(O[t][0] * inv0, O[t][1] * inv0);
        *(float2*)&out[r1a] = make_float2(O[t][2] * inv1, O[t][3] * inv1);
    }
}

// ---------------------------------------------------------------------------
extern "C" void kernel_launch(void* const* d_in, const int* in_sizes, int n_in,
                              void* d_out, int out_size)
{
    const float* x    = (const float*)d_in[0];
    const float* Wqkv = (const float*)d_in[1];
    const float* bqkv = (const float*)d_in[2];
    const float* emb  = (const float*)d_in[3];
    float* out = (float*)d_out;

    cudaFuncSetAttribute(attn_kernel, cudaFuncAttributeMaxDynamicSharedMemorySize,
                         ATT_SMEM_BYTES);

    etrans_kernel<<<512, 256>>>(emb);

    dim3 gq(3072 / 128, 4096 / 128);
    qkv_kernel<<<gq, 256>>>(x, Wqkv, bqkv);

    dim3 ga(LEN / 128, BATCH * HEADS);
    attn_kernel<<<ga, 256, ATT_SMEM_BYTES>>>(out);
}

// round 8
// speedup vs baseline: 2.8481x; 1.0168x over previous
#include <cuda_runtime.h>
#include <cuda_bf16.h>

#define BATCH 4
#define LEN   1024
#define DIM   1024
#define HEADS 16
#define HD    64
#define SCALE 0.125f

typedef unsigned long long u64;
typedef unsigned int u32;

__device__ __forceinline__ float to_tf32(float x) {
    asm("cvt.rna.tf32.f32 %0, %0;" : "+f"(x)); return x;
}
__device__ __forceinline__ void mma8(float* d, const u32* a, u32 b0, u32 b1) {
    asm volatile(
        "mma.sync.aligned.m16n8k8.row.col.f32.tf32.tf32.f32 "
        "{%0,%1,%2,%3}, {%4,%5,%6,%7}, {%8,%9}, {%0,%1,%2,%3};"
        : "+f"(d[0]), "+f"(d[1]), "+f"(d[2]), "+f"(d[3])
        : "r"(a[0]), "r"(a[1]), "r"(a[2]), "r"(a[3]), "r"(b0), "r"(b1));
}

// Scratch (tf32-rounded): Q^T,K^T [bh][d][l]; V [bh][l][d]; E^T [d][2048]
__device__ float g_qt[BATCH * HEADS * HD * LEN];
__device__ float g_kt[BATCH * HEADS * HD * LEN];
__device__ float g_v [BATCH * HEADS * LEN * HD];
__device__ float g_et[HD * 2048];

// ---------------------------------------------------------------------------
// Kernel 0: transpose + tf32-round dist_emb [2047,64] -> g_et [64][2048]
// ---------------------------------------------------------------------------
__global__ void etrans_kernel(const float* __restrict__ emb)
{
    int idx = blockIdx.x * 256 + threadIdx.x;
    if (idx < 2047 * 64) {
        int r = idx >> 6, c = idx & 63;
        g_et[c * 2048 + r] = to_tf32(emb[idx]);
    }
}

// ---------------------------------------------------------------------------
// Kernel 1: QKV GEMM on tf32 tensor cores (unchanged from R7 passing version).
// ---------------------------------------------------------------------------
#define ASTR 36
#define BSTR 136

__global__ __launch_bounds__(256, 2) void qkv_kernel(
    const float* __restrict__ A,
    const float* __restrict__ B,
    const float* __restrict__ bias)
{
    __shared__ float As[128 * ASTR];
    __shared__ float Bs[32 * BSTR];

    const int tid  = threadIdx.x;
    const int wid  = tid >> 5;
    const int lane = tid & 31;
    const int g    = lane >> 2;
    const int kq   = lane & 3;
    const int wm   = wid & 1;
    const int wn   = wid >> 1;
    const int m0 = blockIdx.y * 128;
    const int n0 = blockIdx.x * 128;

    float acc[4][4][4];
#pragma unroll
    for (int mt = 0; mt < 4; mt++)
#pragma unroll
        for (int nt = 0; nt < 4; nt++)
#pragma unroll
            for (int c = 0; c < 4; c++) acc[mt][nt][c] = 0.f;

    for (int k0 = 0; k0 < 1024; k0 += 32) {
#pragma unroll
        for (int it = 0; it < 4; it++) {
            int f = tid + 256 * it;
            int rm = f >> 3, kc = (f & 7) * 4;
            float4 va = *(const float4*)&A[(size_t)(m0 + rm) * 1024 + k0 + kc];
            va.x = to_tf32(va.x); va.y = to_tf32(va.y);
            va.z = to_tf32(va.z); va.w = to_tf32(va.w);
            *(float4*)&As[rm * ASTR + kc] = va;

            int kb = f >> 5, cb = (f & 31) * 4;
            float4 vb = *(const float4*)&B[(size_t)(k0 + kb) * 3072 + n0 + cb];
            vb.x = to_tf32(vb.x); vb.y = to_tf32(vb.y);
            vb.z = to_tf32(vb.z); vb.w = to_tf32(vb.w);
            *(float4*)&Bs[kb * BSTR + cb] = vb;
        }
        __syncthreads();

#pragma unroll
        for (int s = 0; s < 4; s++) {
            int kk = 8 * s + kq;
            u32 a[4][4];
#pragma unroll
            for (int mt = 0; mt < 4; mt++) {
                int r = 64 * wm + 16 * mt + g;
                a[mt][0] = __float_as_uint(As[r * ASTR + kk]);
                a[mt][1] = __float_as_uint(As[(r + 8) * ASTR + kk]);
                a[mt][2] = __float_as_uint(As[r * ASTR + kk + 4]);
                a[mt][3] = __float_as_uint(As[(r + 8) * ASTR + kk + 4]);
            }
            u32 b0[4], b1[4];
#pragma unroll
            for (int nt = 0; nt < 4; nt++) {
                int c = 32 * wn + 8 * nt + g;
                b0[nt] = __float_as_uint(Bs[kk * BSTR + c]);
                b1[nt] = __float_as_uint(Bs[(kk + 4) * BSTR + c]);
            }
#pragma unroll
            for (int mt = 0; mt < 4; mt++)
#pragma unroll
                for (int nt = 0; nt < 4; nt++)
                    mma8(acc[mt][nt], a[mt], b0[nt], b1[nt]);
        }
        __syncthreads();
    }

#pragma unroll
    for (int mt = 0; mt < 4; mt++) {
        int r0 = m0 + 64 * wm + 16 * mt + g;
#pragma unroll
        for (int nt = 0; nt < 4; nt++) {
            int c0 = n0 + 32 * wn + 8 * nt + 2 * kq;
#pragma unroll
            for (int e = 0; e < 4; e++) {
                int m = r0 + (e >> 1) * 8;
                int n = c0 + (e & 1);
                float val = to_tf32(acc[mt][nt][e] + bias[n]);
                int bb = m >> 10, l = m & 1023;
                int s = n >> 10, h = (n >> 6) & 15, hd = n & 63;
                int bh = bb * HEADS + h;
                if (s == 0)
                    g_qt[((size_t)bh * HD + hd) * LEN + l] = val;
                else if (s == 1)
                    g_kt[((size_t)bh * HD + hd) * LEN + l] = val;
                else
                    g_v [((size_t)bh * LEN + l) * HD + hd] = val;
            }
        }
    }
}

// ---------------------------------------------------------------------------
// Kernel 2: tf32 mma flash attention, rolling-ring Gq/E over delta mod 192.
// CTA 256 thr (8 warps), l-tile 128, r-tile 64.
// smem (floats): QT[128][136], ET[64][200] ring (persists), Gq bf16[128][192]
// ring (persists), KT[64][72], Gk bf16[64][192], Vs[64][72];
// Ps[128][76] overlays KT+Gk.
// ---------------------------------------------------------------------------
#define oQT 0
#define oET 17408
#define oGQ 30208
#define oKT 42496
#define oGK 47104
#define oVS 53248
#define oPS 42496
#define SMEMF 57856
#define ATT_SMEM_BYTES (SMEMF * 4)   // 231424 B

__global__ __launch_bounds__(256) void attn_kernel(float* __restrict__ out)
{
    extern __shared__ float sm[];
    float* QT = sm + oQT;
    float* ET = sm + oET;
    float* KT = sm + oKT;
    float* Vs = sm + oVS;
    float* Ps = sm + oPS;
    __nv_bfloat16* Gq = (__nv_bfloat16*)(sm + oGQ);
    __nv_bfloat16* Gk = (__nv_bfloat16*)(sm + oGK);

    const int tid  = threadIdx.x;
    const int wid  = tid >> 5;
    const int lane = tid & 31;
    const int g    = lane >> 2;
    const int kq   = lane & 3;
    const int l0 = blockIdx.x * 128;
    const int bh = blockIdx.y;
    const int b = bh >> 4, h = bh & 15;
    const size_t bqt = (size_t)bh * HD * LEN;
    const size_t bv  = (size_t)bh * LEN * HD;

#pragma unroll 4
    for (int it = 0; it < 32; it++) {
        int idx = tid + 256 * it;
        int d = idx >> 7, c = idx & 127;
        QT[d * 136 + c] = g_qt[bqt + (size_t)d * LEN + l0 + c];
    }

    const int i0  = 16 * wid + g;
    const int wmk = wid & 3, wnk = wid >> 2;
    const int rk0 = 16 * wmk + g;

    float mrun0 = -1e30f, mrun1 = -1e30f, lrun0 = 0.f, lrun1 = 0.f;
    float O[8][4];
#pragma unroll
    for (int t = 0; t < 8; t++)
#pragma unroll
        for (int c = 0; c < 4; c++) O[t][c] = 0.f;

    for (int j0 = 0; j0 < LEN; j0 += 64) {
        const int ebase = l0 - j0 + 960;        // abs delta start, mult of 64
        const int rb    = ebase % 192;          // ring offset in {0,64,128}
        const int nblk  = (j0 == 0) ? 3 : 1;

        __syncthreads();   // prior PV reads of Ps/Vs done; expired ET cols free

        // ---- tile loads: KT, Vs, new E ring block(s) ----
#pragma unroll 4
        for (int it = 0; it < 16; it++) {
            int idx = tid + 256 * it;
            int r0_ = idx >> 6, c = idx & 63;
            KT[r0_ * 72 + c] = g_kt[bqt + (size_t)r0_ * LEN + j0 + c];
            Vs[r0_ * 72 + c] = g_v [bv + (size_t)(j0 + r0_) * HD + c];
        }
        for (int bi = 0; bi < nblk; bi++) {
            int rblk = (rb + 64 * bi) % 192;
            const float* src = g_et + (size_t)(8 * wid) * 2048 + ebase + 64 * bi;
            float* dst = ET + (8 * wid) * 200 + rblk;
#pragma unroll
            for (int dd = 0; dd < 8; dd++)
#pragma unroll
                for (int s = 0; s < 2; s++)
                    dst[dd * 200 + 32 * s + lane] = src[dd * 2048 + 32 * s + lane];
        }
        __syncthreads();

        // ---- S1 = Q@K^T ----
        float accS[8][4];
#pragma unroll
        for (int t = 0; t < 8; t++)
#pragma unroll
            for (int c = 0; c < 4; c++) accS[t][c] = 0.f;
#pragma unroll 2
        for (int ks = 0; ks < 8; ks++) {
            int kr = 8 * ks + kq;
            u32 a[4];
            a[0] = __float_as_uint(QT[kr * 136 + i0]);
            a[1] = __float_as_uint(QT[kr * 136 + i0 + 8]);
            a[2] = __float_as_uint(QT[(kr + 4) * 136 + i0]);
            a[3] = __float_as_uint(QT[(kr + 4) * 136 + i0 + 8]);
#pragma unroll
            for (int t = 0; t < 8; t++) {
                u32 b0 = __float_as_uint(KT[kr * 72 + 8 * t + g]);
                u32 b1 = __float_as_uint(KT[(kr + 4) * 72 + 8 * t + g]);
                mma8(accS[t], a, b0, b1);
            }
        }

        // ---- Gq: compute ONLY new ring block(s) (64 cols each) ----
#pragma unroll 1
        for (int bi = 0; bi < nblk; bi++) {
            int rblk = (rb + 64 * bi) % 192;
            float acc[8][4];
#pragma unroll
            for (int t = 0; t < 8; t++)
#pragma unroll
                for (int c = 0; c < 4; c++) acc[t][c] = 0.f;
#pragma unroll 2
            for (int ks = 0; ks < 8; ks++) {
                int kr = 8 * ks + kq;
                u32 a[4];
                a[0] = __float_as_uint(QT[kr * 136 + i0]);
                a[1] = __float_as_uint(QT[kr * 136 + i0 + 8]);
                a[2] = __float_as_uint(QT[(kr + 4) * 136 + i0]);
                a[3] = __float_as_uint(QT[(kr + 4) * 136 + i0 + 8]);
#pragma unroll
                for (int t = 0; t < 8; t++) {
                    int n = rblk + 8 * t + g;
                    u32 b0 = __float_as_uint(ET[kr * 200 + n]);
                    u32 b1 = __float_as_uint(ET[(kr + 4) * 200 + n]);
                    mma8(acc[t], a, b0, b1);
                }
            }
#pragma unroll
            for (int t = 0; t < 8; t++) {
                int n = rblk + 8 * t + 2 * kq;
                *(__nv_bfloat162*)&Gq[i0 * 192 + n] =
                    __floats2bfloat162_rn(acc[t][0], acc[t][1]);
                *(__nv_bfloat162*)&Gq[(i0 + 8) * 192 + n] =
                    __floats2bfloat162_rn(acc[t][2], acc[t][3]);
            }
        }

        // ---- Gk = K@Ew^T over full ring (192 cols), warps 4m x 2n ----
#pragma unroll 1
        for (int ch = 0; ch < 2; ch++) {
            float acc[6][4];
#pragma unroll
            for (int t = 0; t < 6; t++)
#pragma unroll
                for (int c = 0; c < 4; c++) acc[t][c] = 0.f;
#pragma unroll 2
            for (int ks = 0; ks < 8; ks++) {
                int kr = 8 * ks + kq;
                u32 a[4];
                a[0] = __float_as_uint(KT[kr * 72 + rk0]);
                a[1] = __float_as_uint(KT[kr * 72 + rk0 + 8]);
                a[2] = __float_as_uint(KT[(kr + 4) * 72 + rk0]);
                a[3] = __float_as_uint(KT[(kr + 4) * 72 + rk0 + 8]);
#pragma unroll
                for (int t = 0; t < 6; t++) {
                    int n = 96 * wnk + 48 * ch + 8 * t + g;
                    u32 b0 = __float_as_uint(ET[kr * 200 + n]);
                    u32 b1 = __float_as_uint(ET[(kr + 4) * 200 + n]);
                    mma8(acc[t], a, b0, b1);
                }
            }
#pragma unroll
            for (int t = 0; t < 6; t++) {
                int n = 96 * wnk + 48 * ch + 8 * t + 2 * kq;
                *(__nv_bfloat162*)&Gk[rk0 * 192 + n] =
                    __floats2bfloat162_rn(acc[t][0], acc[t][1]);
                *(__nv_bfloat162*)&Gk[(rk0 + 8) * 192 + n] =
                    __floats2bfloat162_rn(acc[t][2], acc[t][3]);
            }
        }
        __syncthreads();

        // ---- gather bias (ring index) + online softmax ----
        const int base = l0 + i0 - j0 + 1023;   // >= 63 always
#pragma unroll
        for (int t = 0; t < 8; t++)
#pragma unroll
            for (int e = 0; e < 2; e++) {
                int jloc = 8 * t + 2 * kq + e;
                int dabs = base - jloc;
                int r  = dabs % 192;
                int r2 = (dabs + 8) % 192;
                float gq0 = __bfloat162float(Gq[i0 * 192 + r]);
                float gk0 = __bfloat162float(Gk[jloc * 192 + r]);
                float gq1 = __bfloat162float(Gq[(i0 + 8) * 192 + r2]);
                float gk1 = __bfloat162float(Gk[jloc * 192 + r2]);
                accS[t][e]     = (accS[t][e]     + gq0 + gk0) * SCALE;
                accS[t][2 + e] = (accS[t][2 + e] + gq1 + gk1) * SCALE;
            }

        float mx0 = -1e30f, mx1 = -1e30f;
#pragma unroll
        for (int t = 0; t < 8; t++) {
            mx0 = fmaxf(mx0, fmaxf(accS[t][0], accS[t][1]));
            mx1 = fmaxf(mx1, fmaxf(accS[t][2], accS[t][3]));
        }
        mx0 = fmaxf(mx0, __shfl_xor_sync(0xffffffffu, mx0, 1));
        mx0 = fmaxf(mx0, __shfl_xor_sync(0xffffffffu, mx0, 2));
        mx1 = fmaxf(mx1, __shfl_xor_sync(0xffffffffu, mx1, 1));
        mx1 = fmaxf(mx1, __shfl_xor_sync(0xffffffffu, mx1, 2));
        float nm0 = fmaxf(mrun0, mx0), nm1 = fmaxf(mrun1, mx1);
        float pf0 = __expf(mrun0 - nm0), pf1 = __expf(mrun1 - nm1);
        float s0 = 0.f, s1 = 0.f;
#pragma unroll
        for (int t = 0; t < 8; t++) {
            accS[t][0] = __expf(accS[t][0] - nm0);
            accS[t][1] = __expf(accS[t][1] - nm0);
            accS[t][2] = __expf(accS[t][2] - nm1);
            accS[t][3] = __expf(accS[t][3] - nm1);
            s0 += accS[t][0] + accS[t][1];
            s1 += accS[t][2] + accS[t][3];
        }
        s0 += __shfl_xor_sync(0xffffffffu, s0, 1);
        s0 += __shfl_xor_sync(0xffffffffu, s0, 2);
        s1 += __shfl_xor_sync(0xffffffffu, s1, 1);
        s1 += __shfl_xor_sync(0xffffffffu, s1, 2);
        lrun0 = lrun0 * pf0 + s0;  mrun0 = nm0;
        lrun1 = lrun1 * pf1 + s1;  mrun1 = nm1;

        __syncthreads();   // all gather reads done before Ps overlays KT/Gk

#pragma unroll
        for (int t = 0; t < 8; t++) {
            int n = 8 * t + 2 * kq;
            *(float2*)&Ps[i0 * 76 + n] =
                make_float2(to_tf32(accS[t][0]), to_tf32(accS[t][1]));
            *(float2*)&Ps[(i0 + 8) * 76 + n] =
                make_float2(to_tf32(accS[t][2]), to_tf32(accS[t][3]));
            O[t][0] *= pf0; O[t][1] *= pf0; O[t][2] *= pf1; O[t][3] *= pf1;
        }
        __syncthreads();

        // ---- O += P @ V ----
#pragma unroll 2
        for (int ks = 0; ks < 8; ks++) {
            int kr = 8 * ks + kq;
            u32 a[4];
            a[0] = __float_as_uint(Ps[i0 * 76 + kr]);
            a[1] = __float_as_uint(Ps[(i0 + 8) * 76 + kr]);
            a[2] = __float_as_uint(Ps[i0 * 76 + kr + 4]);
            a[3] = __float_as_uint(Ps[(i0 + 8) * 76 + kr + 4]);
#pragma unroll
            for (int t = 0; t < 8; t++) {
                u32 b0 = __float_as_uint(Vs[kr * 72 + 8 * t + g]);
                u32 b1 = __float_as_uint(Vs[(kr + 4) * 72 + 8 * t + g]);
                mma8(O[t], a, b0, b1);
            }
        }
    }

    float inv0 = 1.0f / lrun0, inv1 = 1.0f / lrun1;
#pragma unroll
    for (int t = 0; t < 8; t++) {
        int col = h * HD + 8 * t + 2 * kq;
        size_t r0a = ((size_t)(b * LEN + l0 + i0)) * DIM + col;
        size_t r1a = ((size_t)(b * LEN + l0 + i0 + 8)) * DIM + col;
        *(float2*)&out[r0a] = make_float2(O[t][0] * inv0, O[t][1] * inv0);
        *(float2*)&out[r1a] = make_float2(O[t][2] * inv1, O[t][3] * inv1);
    }
}

// ---------------------------------------------------------------------------
extern "C" void kernel_launch(void* const* d_in, const int* in_sizes, int n_in,
                              void* d_out, int out_size)
{
    const float* x    = (const float*)d_in[0];
    const float* Wqkv = (const float*)d_in[1];
    const float* bqkv = (const float*)d_in[2];
    const float* emb  = (const float*)d_in[3];
    float* out = (float*)d_out;

    cudaFuncSetAttribute(attn_kernel, cudaFuncAttributeMaxDynamicSharedMemorySize,
                         ATT_SMEM_BYTES);

    etrans_kernel<<<512, 256>>>(emb);

    dim3 gq(3072 / 128, 4096 / 128);
    qkv_kernel<<<gq, 256>>>(x, Wqkv, bqkv);

    dim3 ga(LEN / 128, BATCH * HEADS);
    attn_kernel<<<ga, 256, ATT_SMEM_BYTES>>>(out);
}

// round 9
// speedup vs baseline: 3.1376x; 1.1017x over previous
#include <cuda_runtime.h>
#include <cuda_bf16.h>

#define BATCH 4
#define LEN   1024
#define DIM   1024
#define HEADS 16
#define HD    64
#define SCALE 0.125f

typedef unsigned long long u64;
typedef unsigned int u32;

__device__ __forceinline__ float to_tf32(float x) {
    asm("cvt.rna.tf32.f32 %0, %0;" : "+f"(x)); return x;
}
__device__ __forceinline__ void mma8(float* d, const u32* a, u32 b0, u32 b1) {
    asm volatile(
        "mma.sync.aligned.m16n8k8.row.col.f32.tf32.tf32.f32 "
        "{%0,%1,%2,%3}, {%4,%5,%6,%7}, {%8,%9}, {%0,%1,%2,%3};"
        : "+f"(d[0]), "+f"(d[1]), "+f"(d[2]), "+f"(d[3])
        : "r"(a[0]), "r"(a[1]), "r"(a[2]), "r"(a[3]), "r"(b0), "r"(b1));
}
__device__ __forceinline__ void mma16bf(float* d, const u32* a, u32 b0, u32 b1) {
    asm volatile(
        "mma.sync.aligned.m16n8k16.row.col.f32.bf16.bf16.f32 "
        "{%0,%1,%2,%3}, {%4,%5,%6,%7}, {%8,%9}, {%0,%1,%2,%3};"
        : "+f"(d[0]), "+f"(d[1]), "+f"(d[2]), "+f"(d[3])
        : "r"(a[0]), "r"(a[1]), "r"(a[2]), "r"(a[3]), "r"(b0), "r"(b1));
}

// Scratch: Q/K/V [bh][l][d] f32 (tf32-rounded); Qbf/Kbf [bh][l][d] bf16;
// Ebf [2048][64] bf16.
__device__ float g_q[BATCH * HEADS * LEN * HD];
__device__ float g_k[BATCH * HEADS * LEN * HD];
__device__ float g_v[BATCH * HEADS * LEN * HD];
__device__ __nv_bfloat16 g_qbf[BATCH * HEADS * LEN * HD];
__device__ __nv_bfloat16 g_kbf[BATCH * HEADS * LEN * HD];
__device__ __nv_bfloat16 g_ebf[2048 * 64];

// ---------------------------------------------------------------------------
// Kernel 0: dist_emb [2047,64] f32 -> g_ebf [2048][64] bf16 (row 2047 = 0)
// ---------------------------------------------------------------------------
__global__ void etrans_kernel(const float* __restrict__ emb)
{
    int idx = blockIdx.x * 256 + threadIdx.x;
    if (idx < 2048 * 64) {
        float v = (idx < 2047 * 64) ? emb[idx] : 0.0f;
        g_ebf[idx] = __float2bfloat16(v);
    }
}

// ---------------------------------------------------------------------------
// Kernel 1: QKV GEMM on tf32 tensor cores. Epilogue -> Q/K/V [bh][l][d] f32
// (tf32-rounded) + Qbf/Kbf bf16 copies.
// ---------------------------------------------------------------------------
#define ASTR 36
#define BSTR 136

__global__ __launch_bounds__(256, 2) void qkv_kernel(
    const float* __restrict__ A,
    const float* __restrict__ B,
    const float* __restrict__ bias)
{
    __shared__ float As[128 * ASTR];
    __shared__ float Bs[32 * BSTR];

    const int tid  = threadIdx.x;
    const int wid  = tid >> 5;
    const int lane = tid & 31;
    const int g    = lane >> 2;
    const int kq   = lane & 3;
    const int wm   = wid & 1;
    const int wn   = wid >> 1;
    const int m0 = blockIdx.y * 128;
    const int n0 = blockIdx.x * 128;

    float acc[4][4][4];
#pragma unroll
    for (int mt = 0; mt < 4; mt++)
#pragma unroll
        for (int nt = 0; nt < 4; nt++)
#pragma unroll
            for (int c = 0; c < 4; c++) acc[mt][nt][c] = 0.f;

    for (int k0 = 0; k0 < 1024; k0 += 32) {
#pragma unroll
        for (int it = 0; it < 4; it++) {
            int f = tid + 256 * it;
            int rm = f >> 3, kc = (f & 7) * 4;
            float4 va = *(const float4*)&A[(size_t)(m0 + rm) * 1024 + k0 + kc];
            va.x = to_tf32(va.x); va.y = to_tf32(va.y);
            va.z = to_tf32(va.z); va.w = to_tf32(va.w);
            *(float4*)&As[rm * ASTR + kc] = va;

            int kb = f >> 5, cb = (f & 31) * 4;
            float4 vb = *(const float4*)&B[(size_t)(k0 + kb) * 3072 + n0 + cb];
            vb.x = to_tf32(vb.x); vb.y = to_tf32(vb.y);
            vb.z = to_tf32(vb.z); vb.w = to_tf32(vb.w);
            *(float4*)&Bs[kb * BSTR + cb] = vb;
        }
        __syncthreads();

#pragma unroll
        for (int s = 0; s < 4; s++) {
            int kk = 8 * s + kq;
            u32 a[4][4];
#pragma unroll
            for (int mt = 0; mt < 4; mt++) {
                int r = 64 * wm + 16 * mt + g;
                a[mt][0] = __float_as_uint(As[r * ASTR + kk]);
                a[mt][1] = __float_as_uint(As[(r + 8) * ASTR + kk]);
                a[mt][2] = __float_as_uint(As[r * ASTR + kk + 4]);
                a[mt][3] = __float_as_uint(As[(r + 8) * ASTR + kk + 4]);
            }
            u32 b0[4], b1[4];
#pragma unroll
            for (int nt = 0; nt < 4; nt++) {
                int c = 32 * wn + 8 * nt + g;
                b0[nt] = __float_as_uint(Bs[kk * BSTR + c]);
                b1[nt] = __float_as_uint(Bs[(kk + 4) * BSTR + c]);
            }
#pragma unroll
            for (int mt = 0; mt < 4; mt++)
#pragma unroll
                for (int nt = 0; nt < 4; nt++)
                    mma8(acc[mt][nt], a[mt], b0[nt], b1[nt]);
        }
        __syncthreads();
    }

#pragma unroll
    for (int mt = 0; mt < 4; mt++) {
        int r0 = m0 + 64 * wm + 16 * mt + g;
#pragma unroll
        for (int nt = 0; nt < 4; nt++) {
            int c0 = n0 + 32 * wn + 8 * nt + 2 * kq;
#pragma unroll
            for (int e = 0; e < 4; e++) {
                int m = r0 + (e >> 1) * 8;
                int n = c0 + (e & 1);
                float val = to_tf32(acc[mt][nt][e] + bias[n]);
                int bb = m >> 10, l = m & 1023;
                int s = n >> 10, h = (n >> 6) & 15, hd = n & 63;
                int bh = bb * HEADS + h;
                size_t off = ((size_t)bh * LEN + l) * HD + hd;
                if (s == 0) {
                    g_q[off] = val;
                    g_qbf[off] = __float2bfloat16(val);
                } else if (s == 1) {
                    g_k[off] = val;
                    g_kbf[off] = __float2bfloat16(val);
                } else {
                    g_v[off] = val;
                }
            }
        }
    }
}

// ---------------------------------------------------------------------------
// Kernel 2: flash attention. S1/PV on tf32 k8 mma; Gq/Gk on bf16 k16 mma.
// Rolling E/Gq ring over delta mod 192. CTA 256 thr, l-tile 128, r-tile 64.
// smem (float units):
//   Qf[128][68] f32      @0      (8704)
//   Qbf[128][72] bf16    @8704   (4608)
//   Ebf[192][72] bf16    @13312  (6912)  ring
//   Gq  [128][192] bf16  @20224  (12288) ring
//   KT[64][68] f32       @32512  (4352)
//   Kbf[64][72] bf16     @36864  (2304)
//   Gk [64][192] bf16    @39168  (6144)
//   Vs[64][68] f32       @45312  (4352)
//   Ps[128][76] f32      @32512  (overlay KT+Kbf+Gk)
// ---------------------------------------------------------------------------
#define oQF 0
#define oQB 8704
#define oEB 13312
#define oGQ 20224
#define oKT 32512
#define oKB 36864
#define oGK 39168
#define oVS 45312
#define SMEMF 49664
#define ATT_SMEM_BYTES (SMEMF * 4)   // 198656 B

__global__ __launch_bounds__(256) void attn_kernel(float* __restrict__ out)
{
    extern __shared__ float sm[];
    float* Qf = sm + oQF;
    __nv_bfloat16* Qbf = (__nv_bfloat16*)(sm + oQB);
    __nv_bfloat16* Ebf = (__nv_bfloat16*)(sm + oEB);
    __nv_bfloat16* Gq  = (__nv_bfloat16*)(sm + oGQ);
    float* KT = sm + oKT;
    __nv_bfloat16* Kbf = (__nv_bfloat16*)(sm + oKB);
    __nv_bfloat16* Gk  = (__nv_bfloat16*)(sm + oGK);
    float* Vs = sm + oVS;
    float* Ps = sm + oKT;   // overlay

    const int tid  = threadIdx.x;
    const int wid  = tid >> 5;
    const int lane = tid & 31;
    const int g    = lane >> 2;
    const int kq   = lane & 3;
    const int l0 = blockIdx.x * 128;
    const int bh = blockIdx.y;
    const int b = bh >> 4, h = bh & 15;
    const size_t base = (size_t)bh * LEN * HD;

    // ---- one-time loads: Qf (f32) and Qbf (bf16), rows l0..l0+127 ----
#pragma unroll 4
    for (int it = 0; it < 8; it++) {
        int idx = tid + 256 * it;            // 2048 float4s
        int r = idx >> 4, c4 = (idx & 15) * 4;
        *(float4*)&Qf[r * 68 + c4] =
            *(const float4*)&g_q[base + (size_t)(l0 + r) * HD + c4];
    }
#pragma unroll 2
    for (int it = 0; it < 4; it++) {
        int idx = tid + 256 * it;            // 1024 u128 (8 bf16 each)
        int r = idx >> 3, c8 = (idx & 7) * 8;
        *(float4*)&Qbf[r * 72 + c8] =
            *(const float4*)&g_qbf[base + (size_t)(l0 + r) * HD + c8];
    }

    const int i0  = 16 * wid + g;
    const int wmk = wid & 3, wnk = wid >> 2;
    const int rk0 = 16 * wmk + g;

    float mrun0 = -1e30f, mrun1 = -1e30f, lrun0 = 0.f, lrun1 = 0.f;
    float O[8][4];
#pragma unroll
    for (int t = 0; t < 8; t++)
#pragma unroll
        for (int c = 0; c < 4; c++) O[t][c] = 0.f;

    for (int j0 = 0; j0 < LEN; j0 += 64) {
        const int ebase = l0 - j0 + 960;     // multiple of 64
        const int rb    = ebase % 192;       // in {0,64,128}
        const int nblk  = (j0 == 0) ? 3 : 1;

        __syncthreads();

        // ---- tile loads: KT, Vs (f32), Kbf, new Ebf ring blocks ----
#pragma unroll 2
        for (int it = 0; it < 4; it++) {
            int idx = tid + 256 * it;        // 1024 float4s
            int r = idx >> 4, c4 = (idx & 15) * 4;
            *(float4*)&KT[r * 68 + c4] =
                *(const float4*)&g_k[base + (size_t)(j0 + r) * HD + c4];
            *(float4*)&Vs[r * 68 + c4] =
                *(const float4*)&g_v[base + (size_t)(j0 + r) * HD + c4];
        }
#pragma unroll 2
        for (int it = 0; it < 2; it++) {
            int idx = tid + 256 * it;        // 512 u128
            int r = idx >> 3, c8 = (idx & 7) * 8;
            *(float4*)&Kbf[r * 72 + c8] =
                *(const float4*)&g_kbf[base + (size_t)(j0 + r) * HD + c8];
        }
        for (int bi = 0; bi < nblk; bi++) {
            int rblk = (rb + 64 * bi) % 192;
#pragma unroll 2
            for (int it = 0; it < 2; it++) {
                int idx = tid + 256 * it;    // 512 u128
                int r = idx >> 3, c8 = (idx & 7) * 8;
                *(float4*)&Ebf[(rblk + r) * 72 + c8] =
                    *(const float4*)&g_ebf[(size_t)(ebase + 64 * bi + r) * 64 + c8];
            }
        }
        __syncthreads();

        // ---- S1 = Q@K^T (tf32 k8) ----
        float accS[8][4];
#pragma unroll
        for (int t = 0; t < 8; t++)
#pragma unroll
            for (int c = 0; c < 4; c++) accS[t][c] = 0.f;
#pragma unroll 2
        for (int ks = 0; ks < 8; ks++) {
            int kr = 8 * ks + kq;
            u32 a[4];
            a[0] = __float_as_uint(Qf[(16 * wid + g) * 68 + kr]);
            a[1] = __float_as_uint(Qf[(16 * wid + g + 8) * 68 + kr]);
            a[2] = __float_as_uint(Qf[(16 * wid + g) * 68 + kr + 4]);
            a[3] = __float_as_uint(Qf[(16 * wid + g + 8) * 68 + kr + 4]);
#pragma unroll
            for (int t = 0; t < 8; t++) {
                u32 b0 = __float_as_uint(KT[(8 * t + g) * 68 + kr]);
                u32 b1 = __float_as_uint(KT[(8 * t + g) * 68 + kr + 4]);
                mma8(accS[t], a, b0, b1);
            }
        }

        // ---- Gq: new ring block(s) only (bf16 k16) ----
#pragma unroll 1
        for (int bi = 0; bi < nblk; bi++) {
            int rblk = (rb + 64 * bi) % 192;
            float acc[8][4];
#pragma unroll
            for (int t = 0; t < 8; t++)
#pragma unroll
                for (int c = 0; c < 4; c++) acc[t][c] = 0.f;
#pragma unroll
            for (int ks = 0; ks < 4; ks++) {
                int kd = 16 * ks + 2 * kq;
                u32 a[4];
                a[0] = *(const u32*)&Qbf[(16 * wid + g) * 72 + kd];
                a[1] = *(const u32*)&Qbf[(16 * wid + g + 8) * 72 + kd];
                a[2] = *(const u32*)&Qbf[(16 * wid + g) * 72 + kd + 8];
                a[3] = *(const u32*)&Qbf[(16 * wid + g + 8) * 72 + kd + 8];
#pragma unroll
                for (int t = 0; t < 8; t++) {
                    int n = rblk + 8 * t + g;
                    u32 b0 = *(const u32*)&Ebf[n * 72 + kd];
                    u32 b1 = *(const u32*)&Ebf[n * 72 + kd + 8];
                    mma16bf(acc[t], a, b0, b1);
                }
            }
#pragma unroll
            for (int t = 0; t < 8; t++) {
                int n = rblk + 8 * t + 2 * kq;
                *(__nv_bfloat162*)&Gq[i0 * 192 + n] =
                    __floats2bfloat162_rn(acc[t][0], acc[t][1]);
                *(__nv_bfloat162*)&Gq[(i0 + 8) * 192 + n] =
                    __floats2bfloat162_rn(acc[t][2], acc[t][3]);
            }
        }

        // ---- Gk over full ring (bf16 k16), warps 4m x 2n ----
        {
            float acc[12][4];
#pragma unroll
            for (int t = 0; t < 12; t++)
#pragma unroll
                for (int c = 0; c < 4; c++) acc[t][c] = 0.f;
#pragma unroll
            for (int ks = 0; ks < 4; ks++) {
                int kd = 16 * ks + 2 * kq;
                u32 a[4];
                a[0] = *(const u32*)&Kbf[(16 * wmk + g) * 72 + kd];
                a[1] = *(const u32*)&Kbf[(16 * wmk + g + 8) * 72 + kd];
                a[2] = *(const u32*)&Kbf[(16 * wmk + g) * 72 + kd + 8];
                a[3] = *(const u32*)&Kbf[(16 * wmk + g + 8) * 72 + kd + 8];
#pragma unroll
                for (int t = 0; t < 12; t++) {
                    int n = 96 * wnk + 8 * t + g;
                    u32 b0 = *(const u32*)&Ebf[n * 72 + kd];
                    u32 b1 = *(const u32*)&Ebf[n * 72 + kd + 8];
                    mma16bf(acc[t], a, b0, b1);
                }
            }
#pragma unroll
            for (int t = 0; t < 12; t++) {
                int n = 96 * wnk + 8 * t + 2 * kq;
                *(__nv_bfloat162*)&Gk[rk0 * 192 + n] =
                    __floats2bfloat162_rn(acc[t][0], acc[t][1]);
                *(__nv_bfloat162*)&Gk[(rk0 + 8) * 192 + n] =
                    __floats2bfloat162_rn(acc[t][2], acc[t][3]);
            }
        }
        __syncthreads();

        // ---- gather bias (ring index) + online softmax ----
        const int gbase = l0 + i0 - j0 + 1023;
#pragma unroll
        for (int t = 0; t < 8; t++)
#pragma unroll
            for (int e = 0; e < 2; e++) {
                int jloc = 8 * t + 2 * kq + e;
                int dabs = gbase - jloc;
                int r  = dabs % 192;
                int r2 = (dabs + 8) % 192;
                float gq0 = __bfloat162float(Gq[i0 * 192 + r]);
                float gk0 = __bfloat162float(Gk[jloc * 192 + r]);
                float gq1 = __bfloat162float(Gq[(i0 + 8) * 192 + r2]);
                float gk1 = __bfloat162float(Gk[jloc * 192 + r2]);
                accS[t][e]     = (accS[t][e]     + gq0 + gk0) * SCALE;
                accS[t][2 + e] = (accS[t][2 + e] + gq1 + gk1) * SCALE;
            }

        float mx0 = -1e30f, mx1 = -1e30f;
#pragma unroll
        for (int t = 0; t < 8; t++) {
            mx0 = fmaxf(mx0, fmaxf(accS[t][0], accS[t][1]));
            mx1 = fmaxf(mx1, fmaxf(accS[t][2], accS[t][3]));
        }
        mx0 = fmaxf(mx0, __shfl_xor_sync(0xffffffffu, mx0, 1));
        mx0 = fmaxf(mx0, __shfl_xor_sync(0xffffffffu, mx0, 2));
        mx1 = fmaxf(mx1, __shfl_xor_sync(0xffffffffu, mx1, 1));
        mx1 = fmaxf(mx1, __shfl_xor_sync(0xffffffffu, mx1, 2));
        float nm0 = fmaxf(mrun0, mx0), nm1 = fmaxf(mrun1, mx1);
        float pf0 = __expf(mrun0 - nm0), pf1 = __expf(mrun1 - nm1);
        float s0 = 0.f, s1 = 0.f;
#pragma unroll
        for (int t = 0; t < 8; t++) {
            accS[t][0] = __expf(accS[t][0] - nm0);
            accS[t][1] = __expf(accS[t][1] - nm0);
            accS[t][2] = __expf(accS[t][2] - nm1);
            accS[t][3] = __expf(accS[t][3] - nm1);
            s0 += accS[t][0] + accS[t][1];
            s1 += accS[t][2] + accS[t][3];
        }
        s0 += __shfl_xor_sync(0xffffffffu, s0, 1);
        s0 += __shfl_xor_sync(0xffffffffu, s0, 2);
        s1 += __shfl_xor_sync(0xffffffffu, s1, 1);
        s1 += __shfl_xor_sync(0xffffffffu, s1, 2);
        lrun0 = lrun0 * pf0 + s0;  mrun0 = nm0;
        lrun1 = lrun1 * pf1 + s1;  mrun1 = nm1;

        __syncthreads();   // gather reads done before Ps overlays KT/Kbf/Gk

#pragma unroll
        for (int t = 0; t < 8; t++) {
            int n = 8 * t + 2 * kq;
            *(float2*)&Ps[i0 * 76 + n] =
                make_float2(to_tf32(accS[t][0]), to_tf32(accS[t][1]));
            *(float2*)&Ps[(i0 + 8) * 76 + n] =
                make_float2(to_tf32(accS[t][2]), to_tf32(accS[t][3]));
            O[t][0] *= pf0; O[t][1] *= pf0; O[t][2] *= pf1; O[t][3] *= pf1;
        }
        __syncthreads();

        // ---- O += P @ V (tf32 k8) ----
#pragma unroll 2
        for (int ks = 0; ks < 8; ks++) {
            int kr = 8 * ks + kq;
            u32 a[4];
            a[0] = __float_as_uint(Ps[i0 * 76 + kr]);
            a[1] = __float_as_uint(Ps[(i0 + 8) * 76 + kr]);
            a[2] = __float_as_uint(Ps[i0 * 76 + kr + 4]);
            a[3] = __float_as_uint(Ps[(i0 + 8) * 76 + kr + 4]);
#pragma unroll
            for (int t = 0; t < 8; t++) {
                u32 b0 = __float_as_uint(Vs[kr * 68 + 8 * t + g]);
                u32 b1 = __float_as_uint(Vs[(kr + 4) * 68 + 8 * t + g]);
                mma8(O[t], a, b0, b1);
            }
        }
    }

    float inv0 = 1.0f / lrun0, inv1 = 1.0f / lrun1;
#pragma unroll
    for (int t = 0; t < 8; t++) {
        int col = h * HD + 8 * t + 2 * kq;
        size_t r0a = ((size_t)(b * LEN + l0 + i0)) * DIM + col;
        size_t r1a = ((size_t)(b * LEN + l0 + i0 + 8)) * DIM + col;
        *(float2*)&out[r0a] = make_float2(O[t][0] * inv0, O[t][1] * inv0);
        *(float2*)&out[r1a] = make_float2(O[t][2] * inv1, O[t][3] * inv1);
    }
}

// ---------------------------------------------------------------------------
extern "C" void kernel_launch(void* const* d_in, const int* in_sizes, int n_in,
                              void* d_out, int out_size)
{
    const float* x    = (const float*)d_in[0];
    const float* Wqkv = (const float*)d_in[1];
    const float* bqkv = (const float*)d_in[2];
    const float* emb  = (const float*)d_in[3];
    float* out = (float*)d_out;

    cudaFuncSetAttribute(attn_kernel, cudaFuncAttributeMaxDynamicSharedMemorySize,
                         ATT_SMEM_BYTES);

    etrans_kernel<<<512, 256>>>(emb);

    dim3 gq(3072 / 128, 4096 / 128);
    qkv_kernel<<<gq, 256>>>(x, Wqkv, bqkv);

    dim3 ga(LEN / 128, BATCH * HEADS);
    attn_kernel<<<ga, 256, ATT_SMEM_BYTES>>>(out);
}

// round 10
// speedup vs baseline: 3.9728x; 1.2662x over previous
#include <cuda_runtime.h>
#include <cuda_bf16.h>

#define BATCH 4
#define LEN   1024
#define DIM   1024
#define HEADS 16
#define HD    64
#define SCALE 0.125f

typedef unsigned long long u64;
typedef unsigned int u32;

__device__ __forceinline__ float to_tf32(float x) {
    asm("cvt.rna.tf32.f32 %0, %0;" : "+f"(x)); return x;
}
__device__ __forceinline__ void mma8(float* d, const u32* a, u32 b0, u32 b1) {
    asm volatile(
        "mma.sync.aligned.m16n8k8.row.col.f32.tf32.tf32.f32 "
        "{%0,%1,%2,%3}, {%4,%5,%6,%7}, {%8,%9}, {%0,%1,%2,%3};"
        : "+f"(d[0]), "+f"(d[1]), "+f"(d[2]), "+f"(d[3])
        : "r"(a[0]), "r"(a[1]), "r"(a[2]), "r"(a[3]), "r"(b0), "r"(b1));
}
__device__ __forceinline__ void mma16bf(float* d, const u32* a, u32 b0, u32 b1) {
    asm volatile(
        "mma.sync.aligned.m16n8k16.row.col.f32.bf16.bf16.f32 "
        "{%0,%1,%2,%3}, {%4,%5,%6,%7}, {%8,%9}, {%0,%1,%2,%3};"
        : "+f"(d[0]), "+f"(d[1]), "+f"(d[2]), "+f"(d[3])
        : "r"(a[0]), "r"(a[1]), "r"(a[2]), "r"(a[3]), "r"(b0), "r"(b1));
}
__device__ __forceinline__ void cp16(void* smem_dst, const void* gptr) {
    u32 s = (u32)__cvta_generic_to_shared(smem_dst);
    asm volatile("cp.async.ca.shared.global [%0], [%1], 16;" :: "r"(s), "l"(gptr));
}

// Scratch: Q/K/V [bh][l][d] f32 (tf32-rounded); Qbf/Kbf bf16; Ebf [2048][64];
// tf32-rounded copies of x and W for the cp.async GEMM.
__device__ float g_q[BATCH * HEADS * LEN * HD];
__device__ float g_k[BATCH * HEADS * LEN * HD];
__device__ float g_v[BATCH * HEADS * LEN * HD];
__device__ __nv_bfloat16 g_qbf[BATCH * HEADS * LEN * HD];
__device__ __nv_bfloat16 g_kbf[BATCH * HEADS * LEN * HD];
__device__ __nv_bfloat16 g_ebf[2048 * 64];
__device__ float g_xr[4096 * 1024];
__device__ float g_wr[1024 * 3072];

// ---------------------------------------------------------------------------
// Kernel 0a: dist_emb [2047,64] f32 -> g_ebf [2048][64] bf16 (row 2047 = 0)
// ---------------------------------------------------------------------------
__global__ void etrans_kernel(const float* __restrict__ emb)
{
    int idx = blockIdx.x * 256 + threadIdx.x;
    if (idx < 2048 * 64) {
        float v = (idx < 2047 * 64) ? emb[idx] : 0.0f;
        g_ebf[idx] = __float2bfloat16(v);
    }
}

// ---------------------------------------------------------------------------
// Kernel 0b: tf32-round x -> g_xr and W -> g_wr (raw copies for cp.async)
// ---------------------------------------------------------------------------
#define NX4 1048576   // 4096*1024/4
#define NW4 786432    // 1024*3072/4
__global__ void prep_kernel(const float* __restrict__ x,
                            const float* __restrict__ W)
{
    int idx = blockIdx.x * 256 + threadIdx.x;
    if (idx < NX4) {
        float4 v = ((const float4*)x)[idx];
        v.x = to_tf32(v.x); v.y = to_tf32(v.y);
        v.z = to_tf32(v.z); v.w = to_tf32(v.w);
        ((float4*)g_xr)[idx] = v;
    } else if (idx < NX4 + NW4) {
        int j = idx - NX4;
        float4 v = ((const float4*)W)[j];
        v.x = to_tf32(v.x); v.y = to_tf32(v.y);
        v.z = to_tf32(v.z); v.w = to_tf32(v.w);
        ((float4*)g_wr)[j] = v;
    }
}

// ---------------------------------------------------------------------------
// Kernel 1: QKV GEMM, tf32 mma, cp.async double-buffered pipeline (depth 2).
// ---------------------------------------------------------------------------
#define ASTR 36
#define BSTR 136

__global__ __launch_bounds__(256, 2) void qkv_kernel(const float* __restrict__ bias)
{
    __shared__ float As[2][128 * ASTR];
    __shared__ float Bs[2][32 * BSTR];

    const int tid  = threadIdx.x;
    const int wid  = tid >> 5;
    const int lane = tid & 31;
    const int g    = lane >> 2;
    const int kq   = lane & 3;
    const int wm   = wid & 1;
    const int wn   = wid >> 1;
    const int m0 = blockIdx.y * 128;
    const int n0 = blockIdx.x * 128;

    float acc[4][4][4];
#pragma unroll
    for (int mt = 0; mt < 4; mt++)
#pragma unroll
        for (int nt = 0; nt < 4; nt++)
#pragma unroll
            for (int c = 0; c < 4; c++) acc[mt][nt][c] = 0.f;

    // issue one tile-pair load into buffer `buf` for k-offset k0
    auto issue = [&](int buf, int k0) {
#pragma unroll
        for (int it = 0; it < 4; it++) {
            int f = tid + 256 * it;
            int rm = f >> 3, kc = (f & 7) * 4;
            cp16(&As[buf][rm * ASTR + kc],
                 &g_xr[(size_t)(m0 + rm) * 1024 + k0 + kc]);
            int kb = f >> 5, cb = (f & 31) * 4;
            cp16(&Bs[buf][kb * BSTR + cb],
                 &g_wr[(size_t)(k0 + kb) * 3072 + n0 + cb]);
        }
        asm volatile("cp.async.commit_group;");
    };

    issue(0, 0);
    issue(1, 32);

    for (int i = 0; i < 32; i++) {
        int buf = i & 1;
        if (i < 31) asm volatile("cp.async.wait_group 1;");
        else        asm volatile("cp.async.wait_group 0;");
        __syncthreads();

#pragma unroll
        for (int s = 0; s < 4; s++) {
            int kk = 8 * s + kq;
            u32 a[4][4];
#pragma unroll
            for (int mt = 0; mt < 4; mt++) {
                int r = 64 * wm + 16 * mt + g;
                a[mt][0] = __float_as_uint(As[buf][r * ASTR + kk]);
                a[mt][1] = __float_as_uint(As[buf][(r + 8) * ASTR + kk]);
                a[mt][2] = __float_as_uint(As[buf][r * ASTR + kk + 4]);
                a[mt][3] = __float_as_uint(As[buf][(r + 8) * ASTR + kk + 4]);
            }
            u32 b0[4], b1[4];
#pragma unroll
            for (int nt = 0; nt < 4; nt++) {
                int c = 32 * wn + 8 * nt + g;
                b0[nt] = __float_as_uint(Bs[buf][kk * BSTR + c]);
                b1[nt] = __float_as_uint(Bs[buf][(kk + 4) * BSTR + c]);
            }
#pragma unroll
            for (int mt = 0; mt < 4; mt++)
#pragma unroll
                for (int nt = 0; nt < 4; nt++)
                    mma8(acc[mt][nt], a[mt], b0[nt], b1[nt]);
        }
        __syncthreads();
        if (i < 30) issue(buf, (i + 2) * 32);
    }

#pragma unroll
    for (int mt = 0; mt < 4; mt++) {
        int r0 = m0 + 64 * wm + 16 * mt + g;
#pragma unroll
        for (int nt = 0; nt < 4; nt++) {
            int c0 = n0 + 32 * wn + 8 * nt + 2 * kq;
#pragma unroll
            for (int e = 0; e < 4; e++) {
                int m = r0 + (e >> 1) * 8;
                int n = c0 + (e & 1);
                float val = to_tf32(acc[mt][nt][e] + bias[n]);
                int bb = m >> 10, l = m & 1023;
                int s = n >> 10, h = (n >> 6) & 15, hd = n & 63;
                int bh = bb * HEADS + h;
                size_t off = ((size_t)bh * LEN + l) * HD + hd;
                if (s == 0) {
                    g_q[off] = val;
                    g_qbf[off] = __float2bfloat16(val);
                } else if (s == 1) {
                    g_k[off] = val;
                    g_kbf[off] = __float2bfloat16(val);
                } else {
                    g_v[off] = val;
                }
            }
        }
    }
}

// ---------------------------------------------------------------------------
// Kernel 2: flash attention. S1/PV tf32 k8; Gq/Gk bf16 k16; E/Gq ring mod 192.
// Gq/Gk row stride = 200 bf16 (100 words; bank stride 4/row -> conflict-free
// gather; stride 192 was 8-way conflicted).
// smem (float units):
//   Qf[128][68] f32      @0      (8704)
//   Qbf[128][72] bf16    @8704   (4608)
//   Ebf[192][72] bf16    @13312  (6912)  ring
//   Gq [128 rows x200] bf16 @20224 (12800) ring
//   KT[64][68] f32       @33024  (4352)
//   Kbf[64][72] bf16     @37376  (2304)
//   Gk [64 x200] bf16    @39680  (6400)
//   Vs[64][68] f32       @46080  (4352)
//   Ps[128][76] f32      @33024  (overlay KT+Kbf+Gk)
// ---------------------------------------------------------------------------
#define oQF 0
#define oQB 8704
#define oEB 13312
#define oGQ 20224
#define oKT 33024
#define oKB 37376
#define oGK 39680
#define oVS 46080
#define SMEMF 50432
#define ATT_SMEM_BYTES (SMEMF * 4)   // 201728 B
#define GSTR 200

__global__ __launch_bounds__(256) void attn_kernel(float* __restrict__ out)
{
    extern __shared__ float sm[];
    float* Qf = sm + oQF;
    __nv_bfloat16* Qbf = (__nv_bfloat16*)(sm + oQB);
    __nv_bfloat16* Ebf = (__nv_bfloat16*)(sm + oEB);
    __nv_bfloat16* Gq  = (__nv_bfloat16*)(sm + oGQ);
    float* KT = sm + oKT;
    __nv_bfloat16* Kbf = (__nv_bfloat16*)(sm + oKB);
    __nv_bfloat16* Gk  = (__nv_bfloat16*)(sm + oGK);
    float* Vs = sm + oVS;
    float* Ps = sm + oKT;   // overlay

    const int tid  = threadIdx.x;
    const int wid  = tid >> 5;
    const int lane = tid & 31;
    const int g    = lane >> 2;
    const int kq   = lane & 3;
    const int l0 = blockIdx.x * 128;
    const int bh = blockIdx.y;
    const int b = bh >> 4, h = bh & 15;
    const size_t base = (size_t)bh * LEN * HD;

    // ---- one-time loads: Qf (f32) and Qbf (bf16) ----
#pragma unroll 4
    for (int it = 0; it < 8; it++) {
        int idx = tid + 256 * it;
        int r = idx >> 4, c4 = (idx & 15) * 4;
        *(float4*)&Qf[r * 68 + c4] =
            *(const float4*)&g_q[base + (size_t)(l0 + r) * HD + c4];
    }
#pragma unroll 2
    for (int it = 0; it < 4; it++) {
        int idx = tid + 256 * it;
        int r = idx >> 3, c8 = (idx & 7) * 8;
        *(float4*)&Qbf[r * 72 + c8] =
            *(const float4*)&g_qbf[base + (size_t)(l0 + r) * HD + c8];
    }

    const int i0  = 16 * wid + g;
    const int wmk = wid & 3, wnk = wid >> 2;
    const int rk0 = 16 * wmk + g;

    float mrun0 = -1e30f, mrun1 = -1e30f, lrun0 = 0.f, lrun1 = 0.f;
    float O[8][4];
#pragma unroll
    for (int t = 0; t < 8; t++)
#pragma unroll
        for (int c = 0; c < 4; c++) O[t][c] = 0.f;

    for (int j0 = 0; j0 < LEN; j0 += 64) {
        const int ebase = l0 - j0 + 960;
        const int rb    = ebase % 192;
        const int nblk  = (j0 == 0) ? 3 : 1;

        __syncthreads();

        // ---- tile loads ----
#pragma unroll 2
        for (int it = 0; it < 4; it++) {
            int idx = tid + 256 * it;
            int r = idx >> 4, c4 = (idx & 15) * 4;
            *(float4*)&KT[r * 68 + c4] =
                *(const float4*)&g_k[base + (size_t)(j0 + r) * HD + c4];
            *(float4*)&Vs[r * 68 + c4] =
                *(const float4*)&g_v[base + (size_t)(j0 + r) * HD + c4];
        }
#pragma unroll 2
        for (int it = 0; it < 2; it++) {
            int idx = tid + 256 * it;
            int r = idx >> 3, c8 = (idx & 7) * 8;
            *(float4*)&Kbf[r * 72 + c8] =
                *(const float4*)&g_kbf[base + (size_t)(j0 + r) * HD + c8];
        }
        for (int bi = 0; bi < nblk; bi++) {
            int rblk = (rb + 64 * bi) % 192;
#pragma unroll 2
            for (int it = 0; it < 2; it++) {
                int idx = tid + 256 * it;
                int r = idx >> 3, c8 = (idx & 7) * 8;
                *(float4*)&Ebf[(rblk + r) * 72 + c8] =
                    *(const float4*)&g_ebf[(size_t)(ebase + 64 * bi + r) * 64 + c8];
            }
        }
        __syncthreads();

        // ---- S1 = Q@K^T (tf32 k8) ----
        float accS[8][4];
#pragma unroll
        for (int t = 0; t < 8; t++)
#pragma unroll
            for (int c = 0; c < 4; c++) accS[t][c] = 0.f;
#pragma unroll 2
        for (int ks = 0; ks < 8; ks++) {
            int kr = 8 * ks + kq;
            u32 a[4];
            a[0] = __float_as_uint(Qf[i0 * 68 + kr]);
            a[1] = __float_as_uint(Qf[(i0 + 8) * 68 + kr]);
            a[2] = __float_as_uint(Qf[i0 * 68 + kr + 4]);
            a[3] = __float_as_uint(Qf[(i0 + 8) * 68 + kr + 4]);
#pragma unroll
            for (int t = 0; t < 8; t++) {
                u32 b0 = __float_as_uint(KT[(8 * t + g) * 68 + kr]);
                u32 b1 = __float_as_uint(KT[(8 * t + g) * 68 + kr + 4]);
                mma8(accS[t], a, b0, b1);
            }
        }

        // ---- Gq: new ring block(s) only (bf16 k16) ----
#pragma unroll 1
        for (int bi = 0; bi < nblk; bi++) {
            int rblk = (rb + 64 * bi) % 192;
            float acc[8][4];
#pragma unroll
            for (int t = 0; t < 8; t++)
#pragma unroll
                for (int c = 0; c < 4; c++) acc[t][c] = 0.f;
#pragma unroll
            for (int ks = 0; ks < 4; ks++) {
                int kd = 16 * ks + 2 * kq;
                u32 a[4];
                a[0] = *(const u32*)&Qbf[i0 * 72 + kd];
                a[1] = *(const u32*)&Qbf[(i0 + 8) * 72 + kd];
                a[2] = *(const u32*)&Qbf[i0 * 72 + kd + 8];
                a[3] = *(const u32*)&Qbf[(i0 + 8) * 72 + kd + 8];
#pragma unroll
                for (int t = 0; t < 8; t++) {
                    int n = rblk + 8 * t + g;
                    u32 b0 = *(const u32*)&Ebf[n * 72 + kd];
                    u32 b1 = *(const u32*)&Ebf[n * 72 + kd + 8];
                    mma16bf(acc[t], a, b0, b1);
                }
            }
#pragma unroll
            for (int t = 0; t < 8; t++) {
                int n = rblk + 8 * t + 2 * kq;
                *(__nv_bfloat162*)&Gq[i0 * GSTR + n] =
                    __floats2bfloat162_rn(acc[t][0], acc[t][1]);
                *(__nv_bfloat162*)&Gq[(i0 + 8) * GSTR + n] =
                    __floats2bfloat162_rn(acc[t][2], acc[t][3]);
            }
        }

        // ---- Gk over full ring (bf16 k16), warps 4m x 2n ----
        {
            float acc[12][4];
#pragma unroll
            for (int t = 0; t < 12; t++)
#pragma unroll
                for (int c = 0; c < 4; c++) acc[t][c] = 0.f;
#pragma unroll
            for (int ks = 0; ks < 4; ks++) {
                int kd = 16 * ks + 2 * kq;
                u32 a[4];
                a[0] = *(const u32*)&Kbf[(16 * wmk + g) * 72 + kd];
                a[1] = *(const u32*)&Kbf[(16 * wmk + g + 8) * 72 + kd];
                a[2] = *(const u32*)&Kbf[(16 * wmk + g) * 72 + kd + 8];
                a[3] = *(const u32*)&Kbf[(16 * wmk + g + 8) * 72 + kd + 8];
#pragma unroll
                for (int t = 0; t < 12; t++) {
                    int n = 96 * wnk + 8 * t + g;
                    u32 b0 = *(const u32*)&Ebf[n * 72 + kd];
                    u32 b1 = *(const u32*)&Ebf[n * 72 + kd + 8];
                    mma16bf(acc[t], a, b0, b1);
                }
            }
#pragma unroll
            for (int t = 0; t < 12; t++) {
                int n = 96 * wnk + 8 * t + 2 * kq;
                *(__nv_bfloat162*)&Gk[rk0 * GSTR + n] =
                    __floats2bfloat162_rn(acc[t][0], acc[t][1]);
                *(__nv_bfloat162*)&Gk[(rk0 + 8) * GSTR + n] =
                    __floats2bfloat162_rn(acc[t][2], acc[t][3]);
            }
        }
        __syncthreads();

        // ---- gather bias (ring index) + online softmax ----
        const int gbase = l0 + i0 - j0 + 1023;
#pragma unroll
        for (int t = 0; t < 8; t++)
#pragma unroll
            for (int e = 0; e < 2; e++) {
                int jloc = 8 * t + 2 * kq + e;
                int dabs = gbase - jloc;
                int r  = dabs % 192;
                int r2 = (dabs + 8) % 192;
                float gq0 = __bfloat162float(Gq[i0 * GSTR + r]);
                float gk0 = __bfloat162float(Gk[jloc * GSTR + r]);
                float gq1 = __bfloat162float(Gq[(i0 + 8) * GSTR + r2]);
                float gk1 = __bfloat162float(Gk[jloc * GSTR + r2]);
                accS[t][e]     = (accS[t][e]     + gq0 + gk0) * SCALE;
                accS[t][2 + e] = (accS[t][2 + e] + gq1 + gk1) * SCALE;
            }

        float mx0 = -1e30f, mx1 = -1e30f;
#pragma unroll
        for (int t = 0; t < 8; t++) {
            mx0 = fmaxf(mx0, fmaxf(accS[t][0], accS[t][1]));
            mx1 = fmaxf(mx1, fmaxf(accS[t][2], accS[t][3]));
        }
        mx0 = fmaxf(mx0, __shfl_xor_sync(0xffffffffu, mx0, 1));
        mx0 = fmaxf(mx0, __shfl_xor_sync(0xffffffffu, mx0, 2));
        mx1 = fmaxf(mx1, __shfl_xor_sync(0xffffffffu, mx1, 1));
        mx1 = fmaxf(mx1, __shfl_xor_sync(0xffffffffu, mx1, 2));
        float nm0 = fmaxf(mrun0, mx0), nm1 = fmaxf(mrun1, mx1);
        float pf0 = __expf(mrun0 - nm0), pf1 = __expf(mrun1 - nm1);
        float s0 = 0.f, s1 = 0.f;
#pragma unroll
        for (int t = 0; t < 8; t++) {
            accS[t][0] = __expf(accS[t][0] - nm0);
            accS[t][1] = __expf(accS[t][1] - nm0);
            accS[t][2] = __expf(accS[t][2] - nm1);
            accS[t][3] = __expf(accS[t][3] - nm1);
            s0 += accS[t][0] + accS[t][1];
            s1 += accS[t][2] + accS[t][3];
        }
        s0 += __shfl_xor_sync(0xffffffffu, s0, 1);
        s0 += __shfl_xor_sync(0xffffffffu, s0, 2);
        s1 += __shfl_xor_sync(0xffffffffu, s1, 1);
        s1 += __shfl_xor_sync(0xffffffffu, s1, 2);
        lrun0 = lrun0 * pf0 + s0;  mrun0 = nm0;
        lrun1 = lrun1 * pf1 + s1;  mrun1 = nm1;

        __syncthreads();   // gather reads done before Ps overlays KT/Kbf/Gk

#pragma unroll
        for (int t = 0; t < 8; t++) {
            int n = 8 * t + 2 * kq;
            *(float2*)&Ps[i0 * 76 + n] =
                make_float2(to_tf32(accS[t][0]), to_tf32(accS[t][1]));
            *(float2*)&Ps[(i0 + 8) * 76 + n] =
                make_float2(to_tf32(accS[t][2]), to_tf32(accS[t][3]));
            O[t][0] *= pf0; O[t][1] *= pf0; O[t][2] *= pf1; O[t][3] *= pf1;
        }
        __syncthreads();

        // ---- O += P @ V (tf32 k8) ----
#pragma unroll 2
        for (int ks = 0; ks < 8; ks++) {
            int kr = 8 * ks + kq;
            u32 a[4];
            a[0] = __float_as_uint(Ps[i0 * 76 + kr]);
            a[1] = __float_as_uint(Ps[(i0 + 8) * 76 + kr]);
            a[2] = __float_as_uint(Ps[i0 * 76 + kr + 4]);
            a[3] = __float_as_uint(Ps[(i0 + 8) * 76 + kr + 4]);
#pragma unroll
            for (int t = 0; t < 8; t++) {
                u32 b0 = __float_as_uint(Vs[kr * 68 + 8 * t + g]);
                u32 b1 = __float_as_uint(Vs[(kr + 4) * 68 + 8 * t + g]);
                mma8(O[t], a, b0, b1);
            }
        }
    }

    float inv0 = 1.0f / lrun0, inv1 = 1.0f / lrun1;
#pragma unroll
    for (int t = 0; t < 8; t++) {
        int col = h * HD + 8 * t + 2 * kq;
        size_t r0a = ((size_t)(b * LEN + l0 + i0)) * DIM + col;
        size_t r1a = ((size_t)(b * LEN + l0 + i0 + 8)) * DIM + col;
        *(float2*)&out[r0a] = make_float2(O[t][0] * inv0, O[t][1] * inv0);
        *(float2*)&out[r1a] = make_float2(O[t][2] * inv1, O[t][3] * inv1);
    }
}

// ---------------------------------------------------------------------------
extern "C" void kernel_launch(void* const* d_in, const int* in_sizes, int n_in,
                              void* d_out, int out_size)
{
    const float* x    = (const float*)d_in[0];
    const float* Wqkv = (const float*)d_in[1];
    const float* bqkv = (const float*)d_in[2];
    const float* emb  = (const float*)d_in[3];
    float* out = (float*)d_out;

    cudaFuncSetAttribute(attn_kernel, cudaFuncAttributeMaxDynamicSharedMemorySize,
                         ATT_SMEM_BYTES);

    etrans_kernel<<<512, 256>>>(emb);
    prep_kernel<<<(NX4 + NW4) / 256, 256>>>(x, Wqkv);

    dim3 gq(3072 / 128, 4096 / 128);
    qkv_kernel<<<gq, 256>>>(bqkv);

    dim3 ga(LEN / 128, BATCH * HEADS);
    attn_kernel<<<ga, 256, ATT_SMEM_BYTES>>>(out);
}

// round 11
// speedup vs baseline: 4.0379x; 1.0164x over previous
#include <cuda_runtime.h>
#include <cuda_bf16.h>

#define BATCH 4
#define LEN   1024
#define DIM   1024
#define HEADS 16
#define HD    64
#define SCALE 0.125f

typedef unsigned long long u64;
typedef unsigned int u32;

__device__ __forceinline__ float to_tf32(float x) {
    asm("cvt.rna.tf32.f32 %0, %0;" : "+f"(x)); return x;
}
__device__ __forceinline__ void mma8(float* d, const u32* a, u32 b0, u32 b1) {
    asm volatile(
        "mma.sync.aligned.m16n8k8.row.col.f32.tf32.tf32.f32 "
        "{%0,%1,%2,%3}, {%4,%5,%6,%7}, {%8,%9}, {%0,%1,%2,%3};"
        : "+f"(d[0]), "+f"(d[1]), "+f"(d[2]), "+f"(d[3])
        : "r"(a[0]), "r"(a[1]), "r"(a[2]), "r"(a[3]), "r"(b0), "r"(b1));
}
__device__ __forceinline__ void mma16bf(float* d, const u32* a, u32 b0, u32 b1) {
    asm volatile(
        "mma.sync.aligned.m16n8k16.row.col.f32.bf16.bf16.f32 "
        "{%0,%1,%2,%3}, {%4,%5,%6,%7}, {%8,%9}, {%0,%1,%2,%3};"
        : "+f"(d[0]), "+f"(d[1]), "+f"(d[2]), "+f"(d[3])
        : "r"(a[0]), "r"(a[1]), "r"(a[2]), "r"(a[3]), "r"(b0), "r"(b1));
}
__device__ __forceinline__ void cp16(void* smem_dst, const void* gptr) {
    u32 s = (u32)__cvta_generic_to_shared(smem_dst);
    asm volatile("cp.async.ca.shared.global [%0], [%1], 16;" :: "r"(s), "l"(gptr));
}

// Scratch: Q/K/V [bh][l][d] f32 (tf32-rounded); Qbf/Kbf bf16; Ebf [2048][64];
// tf32-rounded copies of x and W for the cp.async GEMM.
__device__ float g_q[BATCH * HEADS * LEN * HD];
__device__ float g_k[BATCH * HEADS * LEN * HD];
__device__ float g_v[BATCH * HEADS * LEN * HD];
__device__ __nv_bfloat16 g_qbf[BATCH * HEADS * LEN * HD];
__device__ __nv_bfloat16 g_kbf[BATCH * HEADS * LEN * HD];
__device__ __nv_bfloat16 g_ebf[2048 * 64];
__device__ float g_xr[4096 * 1024];
__device__ float g_wr[1024 * 3072];

// ---------------------------------------------------------------------------
// Kernel 0a: dist_emb [2047,64] f32 -> g_ebf [2048][64] bf16 (row 2047 = 0)
// ---------------------------------------------------------------------------
__global__ void etrans_kernel(const float* __restrict__ emb)
{
    int idx = blockIdx.x * 256 + threadIdx.x;
    if (idx < 2048 * 64) {
        float v = (idx < 2047 * 64) ? emb[idx] : 0.0f;
        g_ebf[idx] = __float2bfloat16(v);
    }
}

// ---------------------------------------------------------------------------
// Kernel 0b: tf32-round x -> g_xr and W -> g_wr (raw copies for cp.async)
// ---------------------------------------------------------------------------
#define NX4 1048576
#define NW4 786432
__global__ void prep_kernel(const float* __restrict__ x,
                            const float* __restrict__ W)
{
    int idx = blockIdx.x * 256 + threadIdx.x;
    if (idx < NX4) {
        float4 v = ((const float4*)x)[idx];
        v.x = to_tf32(v.x); v.y = to_tf32(v.y);
        v.z = to_tf32(v.z); v.w = to_tf32(v.w);
        ((float4*)g_xr)[idx] = v;
    } else if (idx < NX4 + NW4) {
        int j = idx - NX4;
        float4 v = ((const float4*)W)[j];
        v.x = to_tf32(v.x); v.y = to_tf32(v.y);
        v.z = to_tf32(v.z); v.w = to_tf32(v.w);
        ((float4*)g_wr)[j] = v;
    }
}

// ---------------------------------------------------------------------------
// Kernel 1: QKV GEMM, tf32 mma, cp.async double-buffered (unchanged from R10).
// ---------------------------------------------------------------------------
#define ASTR 36
#define BSTR 136

__global__ __launch_bounds__(256, 2) void qkv_kernel(const float* __restrict__ bias)
{
    __shared__ float As[2][128 * ASTR];
    __shared__ float Bs[2][32 * BSTR];

    const int tid  = threadIdx.x;
    const int wid  = tid >> 5;
    const int lane = tid & 31;
    const int g    = lane >> 2;
    const int kq   = lane & 3;
    const int wm   = wid & 1;
    const int wn   = wid >> 1;
    const int m0 = blockIdx.y * 128;
    const int n0 = blockIdx.x * 128;

    float acc[4][4][4];
#pragma unroll
    for (int mt = 0; mt < 4; mt++)
#pragma unroll
        for (int nt = 0; nt < 4; nt++)
#pragma unroll
            for (int c = 0; c < 4; c++) acc[mt][nt][c] = 0.f;

    auto issue = [&](int buf, int k0) {
#pragma unroll
        for (int it = 0; it < 4; it++) {
            int f = tid + 256 * it;
            int rm = f >> 3, kc = (f & 7) * 4;
            cp16(&As[buf][rm * ASTR + kc],
                 &g_xr[(size_t)(m0 + rm) * 1024 + k0 + kc]);
            int kb = f >> 5, cb = (f & 31) * 4;
            cp16(&Bs[buf][kb * BSTR + cb],
                 &g_wr[(size_t)(k0 + kb) * 3072 + n0 + cb]);
        }
        asm volatile("cp.async.commit_group;");
    };

    issue(0, 0);
    issue(1, 32);

    for (int i = 0; i < 32; i++) {
        int buf = i & 1;
        if (i < 31) asm volatile("cp.async.wait_group 1;");
        else        asm volatile("cp.async.wait_group 0;");
        __syncthreads();

#pragma unroll
        for (int s = 0; s < 4; s++) {
            int kk = 8 * s + kq;
            u32 a[4][4];
#pragma unroll
            for (int mt = 0; mt < 4; mt++) {
                int r = 64 * wm + 16 * mt + g;
                a[mt][0] = __float_as_uint(As[buf][r * ASTR + kk]);
                a[mt][1] = __float_as_uint(As[buf][(r + 8) * ASTR + kk]);
                a[mt][2] = __float_as_uint(As[buf][r * ASTR + kk + 4]);
                a[mt][3] = __float_as_uint(As[buf][(r + 8) * ASTR + kk + 4]);
            }
            u32 b0[4], b1[4];
#pragma unroll
            for (int nt = 0; nt < 4; nt++) {
                int c = 32 * wn + 8 * nt + g;
                b0[nt] = __float_as_uint(Bs[buf][kk * BSTR + c]);
                b1[nt] = __float_as_uint(Bs[buf][(kk + 4) * BSTR + c]);
            }
#pragma unroll
            for (int mt = 0; mt < 4; mt++)
#pragma unroll
                for (int nt = 0; nt < 4; nt++)
                    mma8(acc[mt][nt], a[mt], b0[nt], b1[nt]);
        }
        __syncthreads();
        if (i < 30) issue(buf, (i + 2) * 32);
    }

#pragma unroll
    for (int mt = 0; mt < 4; mt++) {
        int r0 = m0 + 64 * wm + 16 * mt + g;
#pragma unroll
        for (int nt = 0; nt < 4; nt++) {
            int c0 = n0 + 32 * wn + 8 * nt + 2 * kq;
#pragma unroll
            for (int e = 0; e < 4; e++) {
                int m = r0 + (e >> 1) * 8;
                int n = c0 + (e & 1);
                float val = to_tf32(acc[mt][nt][e] + bias[n]);
                int bb = m >> 10, l = m & 1023;
                int s = n >> 10, h = (n >> 6) & 15, hd = n & 63;
                int bh = bb * HEADS + h;
                size_t off = ((size_t)bh * LEN + l) * HD + hd;
                if (s == 0) {
                    g_q[off] = val;
                    g_qbf[off] = __float2bfloat16(val);
                } else if (s == 1) {
                    g_k[off] = val;
                    g_kbf[off] = __float2bfloat16(val);
                } else {
                    g_v[off] = val;
                }
            }
        }
    }
}

// ---------------------------------------------------------------------------
// Kernel 2: flash attention, 512 threads (16 warps) for 2x issue parallelism.
// Warp pair (wr, wc): wr = wid&7 owns rows [16wr,16wr+16); wc = wid>>3 owns
// r-columns [32wc, 32wc+32). Gk: 4m x 4n. Softmax combined across the pair
// via one smem exchange (pmax + rescaled partial sums).
// smem (float units):
//   Qf[128][68] @0 (8704); Qbf[128][72]bf16 @8704 (4608);
//   Ebf[192][72]bf16 @13312 (6912, ring); Gq[128][200]bf16 @20224 (12800, ring);
//   KT[64][68] @33024 (4352); Kbf[64][72]bf16 @37376 (2304);
//   Gk[64][200]bf16 @39680 (6400); Vs[64][68] @46080 (4352);
//   sMax[2][128] @50432 (256); sSum[2][128] @50688 (256);
//   Ps[128][76] overlays @33024 (9728 <= 13056).
// ---------------------------------------------------------------------------
#define oQF 0
#define oQB 8704
#define oEB 13312
#define oGQ 20224
#define oKT 33024
#define oKB 37376
#define oGK 39680
#define oVS 46080
#define oSM 50432
#define oSS 50688
#define SMEMF 50944
#define ATT_SMEM_BYTES (SMEMF * 4)   // 203776 B
#define GSTR 200

__global__ __launch_bounds__(512) void attn_kernel(float* __restrict__ out)
{
    extern __shared__ float sm[];
    float* Qf = sm + oQF;
    __nv_bfloat16* Qbf = (__nv_bfloat16*)(sm + oQB);
    __nv_bfloat16* Ebf = (__nv_bfloat16*)(sm + oEB);
    __nv_bfloat16* Gq  = (__nv_bfloat16*)(sm + oGQ);
    float* KT = sm + oKT;
    __nv_bfloat16* Kbf = (__nv_bfloat16*)(sm + oKB);
    __nv_bfloat16* Gk  = (__nv_bfloat16*)(sm + oGK);
    float* Vs = sm + oVS;
    float* sMax = sm + oSM;
    float* sSum = sm + oSS;
    float* Ps = sm + oKT;   // overlay

    const int tid  = threadIdx.x;
    const int wid  = tid >> 5;
    const int lane = tid & 31;
    const int g    = lane >> 2;
    const int kq   = lane & 3;
    const int wr   = wid & 7;    // row band
    const int wc   = wid >> 3;   // column half
    const int l0 = blockIdx.x * 128;
    const int bh = blockIdx.y;
    const int b = bh >> 4, h = bh & 15;
    const size_t base = (size_t)bh * LEN * HD;

    // ---- one-time loads: Qf (f32) and Qbf (bf16) ----
#pragma unroll 4
    for (int it = 0; it < 4; it++) {
        int idx = tid + 512 * it;
        int r = idx >> 4, c4 = (idx & 15) * 4;
        *(float4*)&Qf[r * 68 + c4] =
            *(const float4*)&g_q[base + (size_t)(l0 + r) * HD + c4];
    }
#pragma unroll 2
    for (int it = 0; it < 2; it++) {
        int idx = tid + 512 * it;
        int r = idx >> 3, c8 = (idx & 7) * 8;
        *(float4*)&Qbf[r * 72 + c8] =
            *(const float4*)&g_qbf[base + (size_t)(l0 + r) * HD + c8];
    }

    const int i0  = 16 * wr + g;
    const int wmk = wid & 3, wnk = wid >> 2;   // Gk: 4m x 4n
    const int rk0 = 16 * wmk + g;

    float mrun0 = -1e30f, mrun1 = -1e30f, lrun0 = 0.f, lrun1 = 0.f;
    float O[4][4];
#pragma unroll
    for (int t = 0; t < 4; t++)
#pragma unroll
        for (int c = 0; c < 4; c++) O[t][c] = 0.f;

    for (int j0 = 0; j0 < LEN; j0 += 64) {
        const int ebase = l0 - j0 + 960;
        const int rb    = ebase % 192;
        const int nblk  = (j0 == 0) ? 3 : 1;

        __syncthreads();   // (a) prior PV reads of Ps/Vs done

        // ---- tile loads ----
#pragma unroll 2
        for (int it = 0; it < 2; it++) {
            int idx = tid + 512 * it;
            int r = idx >> 4, c4 = (idx & 15) * 4;
            *(float4*)&KT[r * 68 + c4] =
                *(const float4*)&g_k[base + (size_t)(j0 + r) * HD + c4];
            *(float4*)&Vs[r * 68 + c4] =
                *(const float4*)&g_v[base + (size_t)(j0 + r) * HD + c4];
        }
        {
            int r = tid >> 3, c8 = (tid & 7) * 8;
            *(float4*)&Kbf[r * 72 + c8] =
                *(const float4*)&g_kbf[base + (size_t)(j0 + r) * HD + c8];
        }
        for (int bi = 0; bi < nblk; bi++) {
            int rblk = (rb + 64 * bi) % 192;
            int r = tid >> 3, c8 = (tid & 7) * 8;
            *(float4*)&Ebf[(rblk + r) * 72 + c8] =
                *(const float4*)&g_ebf[(size_t)(ebase + 64 * bi + r) * 64 + c8];
        }
        __syncthreads();   // (b)

        // ---- S1 = Q@K^T (tf32 k8): rows i0 band x cols [32wc, 32wc+32) ----
        float accS[4][4];
#pragma unroll
        for (int t = 0; t < 4; t++)
#pragma unroll
            for (int c = 0; c < 4; c++) accS[t][c] = 0.f;
#pragma unroll 2
        for (int ks = 0; ks < 8; ks++) {
            int kr = 8 * ks + kq;
            u32 a[4];
            a[0] = __float_as_uint(Qf[i0 * 68 + kr]);
            a[1] = __float_as_uint(Qf[(i0 + 8) * 68 + kr]);
            a[2] = __float_as_uint(Qf[i0 * 68 + kr + 4]);
            a[3] = __float_as_uint(Qf[(i0 + 8) * 68 + kr + 4]);
#pragma unroll
            for (int t = 0; t < 4; t++) {
                int n = 32 * wc + 8 * t + g;
                u32 b0 = __float_as_uint(KT[n * 68 + kr]);
                u32 b1 = __float_as_uint(KT[n * 68 + kr + 4]);
                mma8(accS[t], a, b0, b1);
            }
        }

        // ---- Gq: new ring block(s), warp covers 32 cols of each ----
#pragma unroll 1
        for (int bi = 0; bi < nblk; bi++) {
            int rblk = (rb + 64 * bi) % 192;
            float acc[4][4];
#pragma unroll
            for (int t = 0; t < 4; t++)
#pragma unroll
                for (int c = 0; c < 4; c++) acc[t][c] = 0.f;
#pragma unroll
            for (int ks = 0; ks < 4; ks++) {
                int kd = 16 * ks + 2 * kq;
                u32 a[4];
                a[0] = *(const u32*)&Qbf[i0 * 72 + kd];
                a[1] = *(const u32*)&Qbf[(i0 + 8) * 72 + kd];
                a[2] = *(const u32*)&Qbf[i0 * 72 + kd + 8];
                a[3] = *(const u32*)&Qbf[(i0 + 8) * 72 + kd + 8];
#pragma unroll
                for (int t = 0; t < 4; t++) {
                    int n = rblk + 32 * wc + 8 * t + g;
                    u32 b0 = *(const u32*)&Ebf[n * 72 + kd];
                    u32 b1 = *(const u32*)&Ebf[n * 72 + kd + 8];
                    mma16bf(acc[t], a, b0, b1);
                }
            }
#pragma unroll
            for (int t = 0; t < 4; t++) {
                int n = rblk + 32 * wc + 8 * t + 2 * kq;
                *(__nv_bfloat162*)&Gq[i0 * GSTR + n] =
                    __floats2bfloat162_rn(acc[t][0], acc[t][1]);
                *(__nv_bfloat162*)&Gq[(i0 + 8) * GSTR + n] =
                    __floats2bfloat162_rn(acc[t][2], acc[t][3]);
            }
        }

        // ---- Gk over full ring: warps 4m x 4n (48 cols each) ----
        {
            float acc[6][4];
#pragma unroll
            for (int t = 0; t < 6; t++)
#pragma unroll
                for (int c = 0; c < 4; c++) acc[t][c] = 0.f;
#pragma unroll
            for (int ks = 0; ks < 4; ks++) {
                int kd = 16 * ks + 2 * kq;
                u32 a[4];
                a[0] = *(const u32*)&Kbf[rk0 * 72 + kd];
                a[1] = *(const u32*)&Kbf[(rk0 + 8) * 72 + kd];
                a[2] = *(const u32*)&Kbf[rk0 * 72 + kd + 8];
                a[3] = *(const u32*)&Kbf[(rk0 + 8) * 72 + kd + 8];
#pragma unroll
                for (int t = 0; t < 6; t++) {
                    int n = 48 * wnk + 8 * t + g;
                    u32 b0 = *(const u32*)&Ebf[n * 72 + kd];
                    u32 b1 = *(const u32*)&Ebf[n * 72 + kd + 8];
                    mma16bf(acc[t], a, b0, b1);
                }
            }
#pragma unroll
            for (int t = 0; t < 6; t++) {
                int n = 48 * wnk + 8 * t + 2 * kq;
                *(__nv_bfloat162*)&Gk[rk0 * GSTR + n] =
                    __floats2bfloat162_rn(acc[t][0], acc[t][1]);
                *(__nv_bfloat162*)&Gk[(rk0 + 8) * GSTR + n] =
                    __floats2bfloat162_rn(acc[t][2], acc[t][3]);
            }
        }
        __syncthreads();   // (c) Gq/Gk visible

        // ---- gather bias (ring index) ----
        const int gbase = l0 + i0 - j0 + 1023;
#pragma unroll
        for (int t = 0; t < 4; t++)
#pragma unroll
            for (int e = 0; e < 2; e++) {
                int jloc = 32 * wc + 8 * t + 2 * kq + e;
                int dabs = gbase - jloc;
                int r  = dabs % 192;
                int r2 = (dabs + 8) % 192;
                float gq0 = __bfloat162float(Gq[i0 * GSTR + r]);
                float gk0 = __bfloat162float(Gk[jloc * GSTR + r]);
                float gq1 = __bfloat162float(Gq[(i0 + 8) * GSTR + r2]);
                float gk1 = __bfloat162float(Gk[jloc * GSTR + r2]);
                accS[t][e]     = (accS[t][e]     + gq0 + gk0) * SCALE;
                accS[t][2 + e] = (accS[t][2 + e] + gq1 + gk1) * SCALE;
            }

        // ---- partial softmax over this warp's 32 cols ----
        float mx0 = -1e30f, mx1 = -1e30f;
#pragma unroll
        for (int t = 0; t < 4; t++) {
            mx0 = fmaxf(mx0, fmaxf(accS[t][0], accS[t][1]));
            mx1 = fmaxf(mx1, fmaxf(accS[t][2], accS[t][3]));
        }
        mx0 = fmaxf(mx0, __shfl_xor_sync(0xffffffffu, mx0, 1));
        mx0 = fmaxf(mx0, __shfl_xor_sync(0xffffffffu, mx0, 2));
        mx1 = fmaxf(mx1, __shfl_xor_sync(0xffffffffu, mx1, 1));
        mx1 = fmaxf(mx1, __shfl_xor_sync(0xffffffffu, mx1, 2));
        float ps0 = 0.f, ps1 = 0.f;
#pragma unroll
        for (int t = 0; t < 4; t++) {
            ps0 += __expf(accS[t][0] - mx0) + __expf(accS[t][1] - mx0);
            ps1 += __expf(accS[t][2] - mx1) + __expf(accS[t][3] - mx1);
        }
        ps0 += __shfl_xor_sync(0xffffffffu, ps0, 1);
        ps0 += __shfl_xor_sync(0xffffffffu, ps0, 2);
        ps1 += __shfl_xor_sync(0xffffffffu, ps1, 1);
        ps1 += __shfl_xor_sync(0xffffffffu, ps1, 2);
        if (kq == 0) {
            sMax[wc * 128 + i0] = mx0;  sMax[wc * 128 + i0 + 8] = mx1;
            sSum[wc * 128 + i0] = ps0;  sSum[wc * 128 + i0 + 8] = ps1;
        }
        __syncthreads();   // (d) partials visible

        // ---- combine across warp pair ----
        float omx0 = sMax[(1 - wc) * 128 + i0];
        float omx1 = sMax[(1 - wc) * 128 + i0 + 8];
        float osm0 = sSum[(1 - wc) * 128 + i0];
        float osm1 = sSum[(1 - wc) * 128 + i0 + 8];
        float nm0 = fmaxf(mrun0, fmaxf(mx0, omx0));
        float nm1 = fmaxf(mrun1, fmaxf(mx1, omx1));
        float pf0 = __expf(mrun0 - nm0), pf1 = __expf(mrun1 - nm1);
        float ts0 = ps0 * __expf(mx0 - nm0) + osm0 * __expf(omx0 - nm0);
        float ts1 = ps1 * __expf(mx1 - nm1) + osm1 * __expf(omx1 - nm1);
        lrun0 = lrun0 * pf0 + ts0;  mrun0 = nm0;
        lrun1 = lrun1 * pf1 + ts1;  mrun1 = nm1;

        // ---- write P (tf32) into Ps (overlay) and scale O ----
#pragma unroll
        for (int t = 0; t < 4; t++) {
            int n = 32 * wc + 8 * t + 2 * kq;
            float p00 = __expf(accS[t][0] - nm0);
            float p01 = __expf(accS[t][1] - nm0);
            float p10 = __expf(accS[t][2] - nm1);
            float p11 = __expf(accS[t][3] - nm1);
            *(float2*)&Ps[i0 * 76 + n] = make_float2(to_tf32(p00), to_tf32(p01));
            *(float2*)&Ps[(i0 + 8) * 76 + n] = make_float2(to_tf32(p10), to_tf32(p11));
            O[t][0] *= pf0; O[t][1] *= pf0; O[t][2] *= pf1; O[t][3] *= pf1;
        }
        __syncthreads();   // (e) Ps complete

        // ---- O += P @ V (tf32 k8): rows i0 band x V-cols [32wc, +32) ----
#pragma unroll 2
        for (int ks = 0; ks < 8; ks++) {
            int kr = 8 * ks + kq;
            u32 a[4];
            a[0] = __float_as_uint(Ps[i0 * 76 + kr]);
            a[1] = __float_as_uint(Ps[(i0 + 8) * 76 + kr]);
            a[2] = __float_as_uint(Ps[i0 * 76 + kr + 4]);
            a[3] = __float_as_uint(Ps[(i0 + 8) * 76 + kr + 4]);
#pragma unroll
            for (int t = 0; t < 4; t++) {
                int n = 32 * wc + 8 * t + g;
                u32 b0 = __float_as_uint(Vs[kr * 68 + n]);
                u32 b1 = __float_as_uint(Vs[(kr + 4) * 68 + n]);
                mma8(O[t], a, b0, b1);
            }
        }
    }

    // ---- epilogue ----
    float inv0 = 1.0f / lrun0, inv1 = 1.0f / lrun1;
#pragma unroll
    for (int t = 0; t < 4; t++) {
        int col = h * HD + 32 * wc + 8 * t + 2 * kq;
        size_t r0a = ((size_t)(b * LEN + l0 + i0)) * DIM + col;
        size_t r1a = ((size_t)(b * LEN + l0 + i0 + 8)) * DIM + col;
        *(float2*)&out[r0a] = make_float2(O[t][0] * inv0, O[t][1] * inv0);
        *(float2*)&out[r1a] = make_float2(O[t][2] * inv1, O[t][3] * inv1);
    }
}

// ---------------------------------------------------------------------------
extern "C" void kernel_launch(void* const* d_in, const int* in_sizes, int n_in,
                              void* d_out, int out_size)
{
    const float* x    = (const float*)d_in[0];
    const float* Wqkv = (const float*)d_in[1];
    const float* bqkv = (const float*)d_in[2];
    const float* emb  = (const float*)d_in[3];
    float* out = (float*)d_out;

    cudaFuncSetAttribute(attn_kernel, cudaFuncAttributeMaxDynamicSharedMemorySize,
                         ATT_SMEM_BYTES);

    etrans_kernel<<<512, 256>>>(emb);
    prep_kernel<<<(NX4 + NW4) / 256, 256>>>(x, Wqkv);

    dim3 gq(3072 / 128, 4096 / 128);
    qkv_kernel<<<gq, 256>>>(bqkv);

    dim3 ga(LEN / 128, BATCH * HEADS);
    attn_kernel<<<ga, 512, ATT_SMEM_BYTES>>>(out);
}

// round 12
// speedup vs baseline: 4.1537x; 1.0287x over previous
#include <cuda_runtime.h>
#include <cuda_bf16.h>

#define BATCH 4
#define LEN   1024
#define DIM   1024
#define HEADS 16
#define HD    64
#define SCALE 0.125f

typedef unsigned long long u64;
typedef unsigned int u32;

__device__ __forceinline__ float to_tf32(float x) {
    asm("cvt.rna.tf32.f32 %0, %0;" : "+f"(x)); return x;
}
__device__ __forceinline__ void mma8(float* d, const u32* a, u32 b0, u32 b1) {
    asm volatile(
        "mma.sync.aligned.m16n8k8.row.col.f32.tf32.tf32.f32 "
        "{%0,%1,%2,%3}, {%4,%5,%6,%7}, {%8,%9}, {%0,%1,%2,%3};"
        : "+f"(d[0]), "+f"(d[1]), "+f"(d[2]), "+f"(d[3])
        : "r"(a[0]), "r"(a[1]), "r"(a[2]), "r"(a[3]), "r"(b0), "r"(b1));
}
__device__ __forceinline__ void mma16bf(float* d, const u32* a, u32 b0, u32 b1) {
    asm volatile(
        "mma.sync.aligned.m16n8k16.row.col.f32.bf16.bf16.f32 "
        "{%0,%1,%2,%3}, {%4,%5,%6,%7}, {%8,%9}, {%0,%1,%2,%3};"
        : "+f"(d[0]), "+f"(d[1]), "+f"(d[2]), "+f"(d[3])
        : "r"(a[0]), "r"(a[1]), "r"(a[2]), "r"(a[3]), "r"(b0), "r"(b1));
}
__device__ __forceinline__ void ldsm4(u32& r0, u32& r1, u32& r2, u32& r3, u32 addr) {
    asm volatile(
        "ldmatrix.sync.aligned.m8n8.x4.shared.b16 {%0,%1,%2,%3}, [%4];"
        : "=r"(r0), "=r"(r1), "=r"(r2), "=r"(r3) : "r"(addr));
}
__device__ __forceinline__ void cp16(void* smem_dst, const void* gptr) {
    u32 s = (u32)__cvta_generic_to_shared(smem_dst);
    asm volatile("cp.async.ca.shared.global [%0], [%1], 16;" :: "r"(s), "l"(gptr));
}

// Scratch
__device__ float g_q[BATCH * HEADS * LEN * HD];
__device__ float g_k[BATCH * HEADS * LEN * HD];
__device__ float g_v[BATCH * HEADS * LEN * HD];
__device__ __nv_bfloat16 g_qbf[BATCH * HEADS * LEN * HD];
__device__ __nv_bfloat16 g_kbf[BATCH * HEADS * LEN * HD];
__device__ __nv_bfloat16 g_ebf[2048 * 64];
__device__ float g_xr[4096 * 1024];
__device__ float g_wr[1024 * 3072];

// ---------------------------------------------------------------------------
// Kernel 0: tf32-round x -> g_xr, W -> g_wr; dist_emb -> g_ebf (bf16, row 2047=0)
// ---------------------------------------------------------------------------
#define NX4 1048576
#define NW4 786432
#define NE4 32768
__global__ void prep_kernel(const float* __restrict__ x,
                            const float* __restrict__ W,
                            const float* __restrict__ emb)
{
    int idx = blockIdx.x * 256 + threadIdx.x;
    if (idx < NX4) {
        float4 v = ((const float4*)x)[idx];
        v.x = to_tf32(v.x); v.y = to_tf32(v.y);
        v.z = to_tf32(v.z); v.w = to_tf32(v.w);
        ((float4*)g_xr)[idx] = v;
    } else if (idx < NX4 + NW4) {
        int j = idx - NX4;
        float4 v = ((const float4*)W)[j];
        v.x = to_tf32(v.x); v.y = to_tf32(v.y);
        v.z = to_tf32(v.z); v.w = to_tf32(v.w);
        ((float4*)g_wr)[j] = v;
    } else if (idx < NX4 + NW4 + NE4) {
        int j = (idx - NX4 - NW4) * 4;
#pragma unroll
        for (int i = 0; i < 4; i++) {
            float v = (j + i < 2047 * 64) ? emb[j + i] : 0.0f;
            g_ebf[j + i] = __float2bfloat16(v);
        }
    }
}

// ---------------------------------------------------------------------------
// Kernel 1: QKV GEMM, tf32 mma, cp.async double-buffered (unchanged).
// ---------------------------------------------------------------------------
#define ASTR 36
#define BSTR 136

__global__ __launch_bounds__(256, 2) void qkv_kernel(const float* __restrict__ bias)
{
    __shared__ float As[2][128 * ASTR];
    __shared__ float Bs[2][32 * BSTR];

    const int tid  = threadIdx.x;
    const int wid  = tid >> 5;
    const int lane = tid & 31;
    const int g    = lane >> 2;
    const int kq   = lane & 3;
    const int wm   = wid & 1;
    const int wn   = wid >> 1;
    const int m0 = blockIdx.y * 128;
    const int n0 = blockIdx.x * 128;

    float acc[4][4][4];
#pragma unroll
    for (int mt = 0; mt < 4; mt++)
#pragma unroll
        for (int nt = 0; nt < 4; nt++)
#pragma unroll
            for (int c = 0; c < 4; c++) acc[mt][nt][c] = 0.f;

    auto issue = [&](int buf, int k0) {
#pragma unroll
        for (int it = 0; it < 4; it++) {
            int f = tid + 256 * it;
            int rm = f >> 3, kc = (f & 7) * 4;
            cp16(&As[buf][rm * ASTR + kc],
                 &g_xr[(size_t)(m0 + rm) * 1024 + k0 + kc]);
            int kb = f >> 5, cb = (f & 31) * 4;
            cp16(&Bs[buf][kb * BSTR + cb],
                 &g_wr[(size_t)(k0 + kb) * 3072 + n0 + cb]);
        }
        asm volatile("cp.async.commit_group;");
    };

    issue(0, 0);
    issue(1, 32);

    for (int i = 0; i < 32; i++) {
        int buf = i & 1;
        if (i < 31) asm volatile("cp.async.wait_group 1;");
        else        asm volatile("cp.async.wait_group 0;");
        __syncthreads();

#pragma unroll
        for (int s = 0; s < 4; s++) {
            int kk = 8 * s + kq;
            u32 a[4][4];
#pragma unroll
            for (int mt = 0; mt < 4; mt++) {
                int r = 64 * wm + 16 * mt + g;
                a[mt][0] = __float_as_uint(As[buf][r * ASTR + kk]);
                a[mt][1] = __float_as_uint(As[buf][(r + 8) * ASTR + kk]);
                a[mt][2] = __float_as_uint(As[buf][r * ASTR + kk + 4]);
                a[mt][3] = __float_as_uint(As[buf][(r + 8) * ASTR + kk + 4]);
            }
            u32 b0[4], b1[4];
#pragma unroll
            for (int nt = 0; nt < 4; nt++) {
                int c = 32 * wn + 8 * nt + g;
                b0[nt] = __float_as_uint(Bs[buf][kk * BSTR + c]);
                b1[nt] = __float_as_uint(Bs[buf][(kk + 4) * BSTR + c]);
            }
#pragma unroll
            for (int mt = 0; mt < 4; mt++)
#pragma unroll
                for (int nt = 0; nt < 4; nt++)
                    mma8(acc[mt][nt], a[mt], b0[nt], b1[nt]);
        }
        __syncthreads();
        if (i < 30) issue(buf, (i + 2) * 32);
    }

#pragma unroll
    for (int mt = 0; mt < 4; mt++) {
        int r0 = m0 + 64 * wm + 16 * mt + g;
#pragma unroll
        for (int nt = 0; nt < 4; nt++) {
            int c0 = n0 + 32 * wn + 8 * nt + 2 * kq;
#pragma unroll
            for (int e = 0; e < 4; e++) {
                int m = r0 + (e >> 1) * 8;
                int n = c0 + (e & 1);
                float val = to_tf32(acc[mt][nt][e] + bias[n]);
                int bb = m >> 10, l = m & 1023;
                int s = n >> 10, h = (n >> 6) & 15, hd = n & 63;
                int bh = bb * HEADS + h;
                size_t off = ((size_t)bh * LEN + l) * HD + hd;
                if (s == 0) {
                    g_q[off] = val;
                    g_qbf[off] = __float2bfloat16(val);
                } else if (s == 1) {
                    g_k[off] = val;
                    g_kbf[off] = __float2bfloat16(val);
                } else {
                    g_v[off] = val;
                }
            }
        }
    }
}

// ---------------------------------------------------------------------------
// Kernel 2: flash attention, 512 threads. R11 structure + this round:
// ldmatrix for bf16 frags, exp dedup, cheap ring index.
// ---------------------------------------------------------------------------
#define oQF 0
#define oQB 8704
#define oEB 13312
#define oGQ 20224
#define oKT 33024
#define oKB 37376
#define oGK 39680
#define oVS 46080
#define oSM 50432
#define oSS 50688
#define SMEMF 50944
#define ATT_SMEM_BYTES (SMEMF * 4)   // 203776 B
#define GSTR 200

__global__ __launch_bounds__(512) void attn_kernel(float* __restrict__ out)
{
    extern __shared__ float sm[];
    float* Qf = sm + oQF;
    __nv_bfloat16* Qbf = (__nv_bfloat16*)(sm + oQB);
    __nv_bfloat16* Ebf = (__nv_bfloat16*)(sm + oEB);
    __nv_bfloat16* Gq  = (__nv_bfloat16*)(sm + oGQ);
    float* KT = sm + oKT;
    __nv_bfloat16* Kbf = (__nv_bfloat16*)(sm + oKB);
    __nv_bfloat16* Gk  = (__nv_bfloat16*)(sm + oGK);
    float* Vs = sm + oVS;
    float* sMax = sm + oSM;
    float* sSum = sm + oSS;
    float* Ps = sm + oKT;   // overlay

    const int tid  = threadIdx.x;
    const int wid  = tid >> 5;
    const int lane = tid & 31;
    const int g    = lane >> 2;
    const int kq   = lane & 3;
    const int wr   = wid & 7;
    const int wc   = wid >> 3;
    const int l0 = blockIdx.x * 128;
    const int bh = blockIdx.y;
    const int b = bh >> 4, h = bh & 15;
    const size_t base = (size_t)bh * LEN * HD;

    // ldmatrix lane decodes
    const int rdA = (lane & 7) + ((lane >> 3) & 1) * 8;   // A tiles: m0/m1 rows, m2/m3 cols+8
    const int cdA = ((lane >> 4) & 1) * 8;
    const int rdB = (lane & 7) + ((lane >> 4) & 1) * 8;   // B tiles: m0/m1 k-halves, m2/m3 rows+8
    const int cdB = ((lane >> 3) & 1) * 8;

    // ---- one-time loads: Qf (f32) and Qbf (bf16) ----
#pragma unroll 4
    for (int it = 0; it < 4; it++) {
        int idx = tid + 512 * it;
        int r = idx >> 4, c4 = (idx & 15) * 4;
        *(float4*)&Qf[r * 68 + c4] =
            *(const float4*)&g_q[base + (size_t)(l0 + r) * HD + c4];
    }
#pragma unroll 2
    for (int it = 0; it < 2; it++) {
        int idx = tid + 512 * it;
        int r = idx >> 3, c8 = (idx & 7) * 8;
        *(float4*)&Qbf[r * 72 + c8] =
            *(const float4*)&g_qbf[base + (size_t)(l0 + r) * HD + c8];
    }

    const int i0  = 16 * wr + g;
    const int wmk = wid & 3, wnk = wid >> 2;   // Gk: 4m x 4n
    const int rk0 = 16 * wmk + g;

    // ldmatrix base addresses (byte offsets into smem, bf16 stride 72 = 144 B)
    const u32 aQbase = (u32)__cvta_generic_to_shared(
        &Qbf[(16 * wr + rdA) * 72 + cdA]);
    const u32 aKbase = (u32)__cvta_generic_to_shared(
        &Kbf[(16 * wmk + rdA) * 72 + cdA]);
    const u32 eBase  = (u32)__cvta_generic_to_shared(Ebf);

    float mrun0 = -1e30f, mrun1 = -1e30f, lrun0 = 0.f, lrun1 = 0.f;
    float O[4][4];
#pragma unroll
    for (int t = 0; t < 4; t++)
#pragma unroll
        for (int c = 0; c < 4; c++) O[t][c] = 0.f;

    for (int j0 = 0; j0 < LEN; j0 += 64) {
        const int ebase = l0 - j0 + 960;
        const int rb    = ebase % 192;
        const int nblk  = (j0 == 0) ? 3 : 1;

        __syncthreads();   // (a)

        // ---- tile loads ----
#pragma unroll 2
        for (int it = 0; it < 2; it++) {
            int idx = tid + 512 * it;
            int r = idx >> 4, c4 = (idx & 15) * 4;
            *(float4*)&KT[r * 68 + c4] =
                *(const float4*)&g_k[base + (size_t)(j0 + r) * HD + c4];
            *(float4*)&Vs[r * 68 + c4] =
                *(const float4*)&g_v[base + (size_t)(j0 + r) * HD + c4];
        }
        {
            int r = tid >> 3, c8 = (tid & 7) * 8;
            *(float4*)&Kbf[r * 72 + c8] =
                *(const float4*)&g_kbf[base + (size_t)(j0 + r) * HD + c8];
        }
        for (int bi = 0; bi < nblk; bi++) {
            int rblk = (rb + 64 * bi) % 192;
            int r = tid >> 3, c8 = (tid & 7) * 8;
            *(float4*)&Ebf[(rblk + r) * 72 + c8] =
                *(const float4*)&g_ebf[(size_t)(ebase + 64 * bi + r) * 64 + c8];
        }
        __syncthreads();   // (b)

        // ---- S1 = Q@K^T (tf32 k8) ----
        float accS[4][4];
#pragma unroll
        for (int t = 0; t < 4; t++)
#pragma unroll
            for (int c = 0; c < 4; c++) accS[t][c] = 0.f;
#pragma unroll 2
        for (int ks = 0; ks < 8; ks++) {
            int kr = 8 * ks + kq;
            u32 a[4];
            a[0] = __float_as_uint(Qf[i0 * 68 + kr]);
            a[1] = __float_as_uint(Qf[(i0 + 8) * 68 + kr]);
            a[2] = __float_as_uint(Qf[i0 * 68 + kr + 4]);
            a[3] = __float_as_uint(Qf[(i0 + 8) * 68 + kr + 4]);
#pragma unroll
            for (int t = 0; t < 4; t++) {
                int n = 32 * wc + 8 * t + g;
                u32 b0 = __float_as_uint(KT[n * 68 + kr]);
                u32 b1 = __float_as_uint(KT[n * 68 + kr + 4]);
                mma8(accS[t], a, b0, b1);
            }
        }

        // ---- Gq: new ring block(s), ldmatrix frags (bf16 k16) ----
#pragma unroll 1
        for (int bi = 0; bi < nblk; bi++) {
            int rblk = (rb + 64 * bi) % 192;
            u32 eA = eBase + (u32)(((rblk + 32 * wc + rdB) * 72 + cdB) * 2);
            float acc[4][4];
#pragma unroll
            for (int t = 0; t < 4; t++)
#pragma unroll
                for (int c = 0; c < 4; c++) acc[t][c] = 0.f;
#pragma unroll
            for (int ks = 0; ks < 4; ks++) {
                u32 a[4];
                ldsm4(a[0], a[1], a[2], a[3], aQbase + 32 * ks);
#pragma unroll
                for (int tp = 0; tp < 2; tp++) {
                    u32 e0, e1, e2, e3;
                    ldsm4(e0, e1, e2, e3, eA + tp * 2304 + 32 * ks);
                    mma16bf(acc[2 * tp],     a, e0, e1);
                    mma16bf(acc[2 * tp + 1], a, e2, e3);
                }
            }
#pragma unroll
            for (int t = 0; t < 4; t++) {
                int n = rblk + 32 * wc + 8 * t + 2 * kq;
                *(__nv_bfloat162*)&Gq[i0 * GSTR + n] =
                    __floats2bfloat162_rn(acc[t][0], acc[t][1]);
                *(__nv_bfloat162*)&Gq[(i0 + 8) * GSTR + n] =
                    __floats2bfloat162_rn(acc[t][2], acc[t][3]);
            }
        }

        // ---- Gk over full ring, ldmatrix frags: warps 4m x 4n (48 cols) ----
        {
            u32 eG = eBase + (u32)(((48 * wnk + rdB) * 72 + cdB) * 2);
            float acc[6][4];
#pragma unroll
            for (int t = 0; t < 6; t++)
#pragma unroll
                for (int c = 0; c < 4; c++) acc[t][c] = 0.f;
#pragma unroll
            for (int ks = 0; ks < 4; ks++) {
                u32 a[4];
                ldsm4(a[0], a[1], a[2], a[3], aKbase + 32 * ks);
#pragma unroll
                for (int tp = 0; tp < 3; tp++) {
                    u32 e0, e1, e2, e3;
                    ldsm4(e0, e1, e2, e3, eG + tp * 2304 + 32 * ks);
                    mma16bf(acc[2 * tp],     a, e0, e1);
                    mma16bf(acc[2 * tp + 1], a, e2, e3);
                }
            }
#pragma unroll
            for (int t = 0; t < 6; t++) {
                int n = 48 * wnk + 8 * t + 2 * kq;
                *(__nv_bfloat162*)&Gk[rk0 * GSTR + n] =
                    __floats2bfloat162_rn(acc[t][0], acc[t][1]);
                *(__nv_bfloat162*)&Gk[(rk0 + 8) * GSTR + n] =
                    __floats2bfloat162_rn(acc[t][2], acc[t][3]);
            }
        }
        __syncthreads();   // (c)

        // ---- gather bias (cheap ring index) ----
        int rbase = (l0 + i0 - j0 + 1023) % 192;
        int rbase8 = rbase + 8; if (rbase8 >= 192) rbase8 -= 192;
        const __nv_bfloat16* gq0r = &Gq[i0 * GSTR];
        const __nv_bfloat16* gq1r = &Gq[(i0 + 8) * GSTR];
#pragma unroll
        for (int t = 0; t < 4; t++)
#pragma unroll
            for (int e = 0; e < 2; e++) {
                int jloc = 32 * wc + 8 * t + 2 * kq + e;
                int r  = rbase  - jloc;  r  += (r  >> 31) & 192;
                int r2 = rbase8 - jloc;  r2 += (r2 >> 31) & 192;
                float gq0 = __bfloat162float(gq0r[r]);
                float gk0 = __bfloat162float(Gk[jloc * GSTR + r]);
                float gq1 = __bfloat162float(gq1r[r2]);
                float gk1 = __bfloat162float(Gk[jloc * GSTR + r2]);
                accS[t][e]     = (accS[t][e]     + gq0 + gk0) * SCALE;
                accS[t][2 + e] = (accS[t][2 + e] + gq1 + gk1) * SCALE;
            }

        // ---- partial softmax (exp once, rescale later) ----
        float mx0 = -1e30f, mx1 = -1e30f;
#pragma unroll
        for (int t = 0; t < 4; t++) {
            mx0 = fmaxf(mx0, fmaxf(accS[t][0], accS[t][1]));
            mx1 = fmaxf(mx1, fmaxf(accS[t][2], accS[t][3]));
        }
        mx0 = fmaxf(mx0, __shfl_xor_sync(0xffffffffu, mx0, 1));
        mx0 = fmaxf(mx0, __shfl_xor_sync(0xffffffffu, mx0, 2));
        mx1 = fmaxf(mx1, __shfl_xor_sync(0xffffffffu, mx1, 1));
        mx1 = fmaxf(mx1, __shfl_xor_sync(0xffffffffu, mx1, 2));
        float pe[4][4];
        float ps0 = 0.f, ps1 = 0.f;
#pragma unroll
        for (int t = 0; t < 4; t++) {
            pe[t][0] = __expf(accS[t][0] - mx0);
            pe[t][1] = __expf(accS[t][1] - mx0);
            pe[t][2] = __expf(accS[t][2] - mx1);
            pe[t][3] = __expf(accS[t][3] - mx1);
            ps0 += pe[t][0] + pe[t][1];
            ps1 += pe[t][2] + pe[t][3];
        }
        ps0 += __shfl_xor_sync(0xffffffffu, ps0, 1);
        ps0 += __shfl_xor_sync(0xffffffffu, ps0, 2);
        ps1 += __shfl_xor_sync(0xffffffffu, ps1, 1);
        ps1 += __shfl_xor_sync(0xffffffffu, ps1, 2);
        if (kq == 0) {
            sMax[wc * 128 + i0] = mx0;  sMax[wc * 128 + i0 + 8] = mx1;
            sSum[wc * 128 + i0] = ps0;  sSum[wc * 128 + i0 + 8] = ps1;
        }
        __syncthreads();   // (d)

        // ---- combine across warp pair ----
        float omx0 = sMax[(1 - wc) * 128 + i0];
        float omx1 = sMax[(1 - wc) * 128 + i0 + 8];
        float osm0 = sSum[(1 - wc) * 128 + i0];
        float osm1 = sSum[(1 - wc) * 128 + i0 + 8];
        float nm0 = fmaxf(mrun0, fmaxf(mx0, omx0));
        float nm1 = fmaxf(mrun1, fmaxf(mx1, omx1));
        float pf0 = __expf(mrun0 - nm0), pf1 = __expf(mrun1 - nm1);
        float sc0 = __expf(mx0 - nm0),   sc1 = __expf(mx1 - nm1);
        float ts0 = ps0 * sc0 + osm0 * __expf(omx0 - nm0);
        float ts1 = ps1 * sc1 + osm1 * __expf(omx1 - nm1);
        lrun0 = lrun0 * pf0 + ts0;  mrun0 = nm0;
        lrun1 = lrun1 * pf1 + ts1;  mrun1 = nm1;

        // ---- write P (tf32) and scale O ----
#pragma unroll
        for (int t = 0; t < 4; t++) {
            int n = 32 * wc + 8 * t + 2 * kq;
            *(float2*)&Ps[i0 * 76 + n] =
                make_float2(to_tf32(pe[t][0] * sc0), to_tf32(pe[t][1] * sc0));
            *(float2*)&Ps[(i0 + 8) * 76 + n] =
                make_float2(to_tf32(pe[t][2] * sc1), to_tf32(pe[t][3] * sc1));
            O[t][0] *= pf0; O[t][1] *= pf0; O[t][2] *= pf1; O[t][3] *= pf1;
        }
        __syncthreads();   // (e)

        // ---- O += P @ V (tf32 k8) ----
#pragma unroll 2
        for (int ks = 0; ks < 8; ks++) {
            int kr = 8 * ks + kq;
            u32 a[4];
            a[0] = __float_as_uint(Ps[i0 * 76 + kr]);
            a[1] = __float_as_uint(Ps[(i0 + 8) * 76 + kr]);
            a[2] = __float_as_uint(Ps[i0 * 76 + kr + 4]);
            a[3] = __float_as_uint(Ps[(i0 + 8) * 76 + kr + 4]);
#pragma unroll
            for (int t = 0; t < 4; t++) {
                int n = 32 * wc + 8 * t + g;
                u32 b0 = __float_as_uint(Vs[kr * 68 + n]);
                u32 b1 = __float_as_uint(Vs[(kr + 4) * 68 + n]);
                mma8(O[t], a, b0, b1);
            }
        }
    }

    // ---- epilogue ----
    float inv0 = 1.0f / lrun0, inv1 = 1.0f / lrun1;
#pragma unroll
    for (int t = 0; t < 4; t++) {
        int col = h * HD + 32 * wc + 8 * t + 2 * kq;
        size_t r0a = ((size_t)(b * LEN + l0 + i0)) * DIM + col;
        size_t r1a = ((size_t)(b * LEN + l0 + i0 + 8)) * DIM + col;
        *(float2*)&out[r0a] = make_float2(O[t][0] * inv0, O[t][1] * inv0);
        *(float2*)&out[r1a] = make_float2(O[t][2] * inv1, O[t][3] * inv1);
    }
}

// ---------------------------------------------------------------------------
extern "C" void kernel_launch(void* const* d_in, const int* in_sizes, int n_in,
                              void* d_out, int out_size)
{
    const float* x    = (const float*)d_in[0];
    const float* Wqkv = (const float*)d_in[1];
    const float* bqkv = (const float*)d_in[2];
    const float* emb  = (const float*)d_in[3];
    float* out = (float*)d_out;

    cudaFuncSetAttribute(attn_kernel, cudaFuncAttributeMaxDynamicSharedMemorySize,
                         ATT_SMEM_BYTES);

    prep_kernel<<<(NX4 + NW4 + NE4 + 255) / 256, 256>>>(x, Wqkv, emb);

    dim3 gq(3072 / 128, 4096 / 128);
    qkv_kernel<<<gq, 256>>>(bqkv);

    dim3 ga(LEN / 128, BATCH * HEADS);
    attn_kernel<<<ga, 512, ATT_SMEM_BYTES>>>(out);
}

// round 14
// speedup vs baseline: 4.3390x; 1.0446x over previous
#include <cuda_runtime.h>
#include <cuda_bf16.h>

#define BATCH 4
#define LEN   1024
#define DIM   1024
#define HEADS 16
#define HD    64
#define SCALE 0.125f

typedef unsigned long long u64;
typedef unsigned int u32;

__device__ __forceinline__ float to_tf32(float x) {
    asm("cvt.rna.tf32.f32 %0, %0;" : "+f"(x)); return x;
}
__device__ __forceinline__ void mma8(float* d, const u32* a, u32 b0, u32 b1) {
    asm volatile(
        "mma.sync.aligned.m16n8k8.row.col.f32.tf32.tf32.f32 "
        "{%0,%1,%2,%3}, {%4,%5,%6,%7}, {%8,%9}, {%0,%1,%2,%3};"
        : "+f"(d[0]), "+f"(d[1]), "+f"(d[2]), "+f"(d[3])
        : "r"(a[0]), "r"(a[1]), "r"(a[2]), "r"(a[3]), "r"(b0), "r"(b1));
}
__device__ __forceinline__ void mma16bf(float* d, const u32* a, u32 b0, u32 b1) {
    asm volatile(
        "mma.sync.aligned.m16n8k16.row.col.f32.bf16.bf16.f32 "
        "{%0,%1,%2,%3}, {%4,%5,%6,%7}, {%8,%9}, {%0,%1,%2,%3};"
        : "+f"(d[0]), "+f"(d[1]), "+f"(d[2]), "+f"(d[3])
        : "r"(a[0]), "r"(a[1]), "r"(a[2]), "r"(a[3]), "r"(b0), "r"(b1));
}
__device__ __forceinline__ void ldsm4(u32& r0, u32& r1, u32& r2, u32& r3, u32 addr) {
    asm volatile(
        "ldmatrix.sync.aligned.m8n8.x4.shared.b16 {%0,%1,%2,%3}, [%4];"
        : "=r"(r0), "=r"(r1), "=r"(r2), "=r"(r3) : "r"(addr));
}
__device__ __forceinline__ void cp16(void* smem_dst, const void* gptr) {
    u32 s = (u32)__cvta_generic_to_shared(smem_dst);
    asm volatile("cp.async.ca.shared.global [%0], [%1], 16;" :: "r"(s), "l"(gptr));
}

// Scratch. Packed f32 layouts (k-interleaved, c = 20*(d%4) + d/4, row stride 80):
//   g_qp/g_kp: [bh*LEN + l][80]
//   g_vp:      [(bh*HD + d)*16 + l/64][80] with c = 20*(l%4) + (l%64)/4
__device__ float g_qp[BATCH * HEADS * LEN * 80];
__device__ float g_kp[BATCH * HEADS * LEN * 80];
__device__ float g_vp[BATCH * HEADS * HD * 16 * 80];
__device__ __nv_bfloat16 g_qbf[BATCH * HEADS * LEN * HD];
__device__ __nv_bfloat16 g_kbf[BATCH * HEADS * LEN * HD];
__device__ __nv_bfloat16 g_ebf[2048 * 64];
__device__ float g_xr[4096 * 1024];
__device__ float g_wr[1024 * 3072];

// ---------------------------------------------------------------------------
// Kernel 0: tf32-round x -> g_xr, W -> g_wr; dist_emb -> g_ebf (bf16)
// ---------------------------------------------------------------------------
#define NX4 1048576
#define NW4 786432
#define NE4 32768
__global__ void prep_kernel(const float* __restrict__ x,
                            const float* __restrict__ W,
                            const float* __restrict__ emb)
{
    int idx = blockIdx.x * 256 + threadIdx.x;
    if (idx < NX4) {
        float4 v = ((const float4*)x)[idx];
        v.x = to_tf32(v.x); v.y = to_tf32(v.y);
        v.z = to_tf32(v.z); v.w = to_tf32(v.w);
        ((float4*)g_xr)[idx] = v;
    } else if (idx < NX4 + NW4) {
        int j = idx - NX4;
        float4 v = ((const float4*)W)[j];
        v.x = to_tf32(v.x); v.y = to_tf32(v.y);
        v.z = to_tf32(v.z); v.w = to_tf32(v.w);
        ((float4*)g_wr)[j] = v;
    } else if (idx < NX4 + NW4 + NE4) {
        int j = (idx - NX4 - NW4) * 4;
#pragma unroll
        for (int i = 0; i < 4; i++) {
            float v = (j + i < 2047 * 64) ? emb[j + i] : 0.0f;
            g_ebf[j + i] = __float2bfloat16(v);
        }
    }
}

// ---------------------------------------------------------------------------
// Kernel 1: QKV GEMM, tf32 mma, cp.async double-buffered. Epilogue writes
// packed Q/K/V layouts + bf16 copies of Q,K.
// ---------------------------------------------------------------------------
#define ASTR 36
#define BSTR 136

__global__ __launch_bounds__(256, 2) void qkv_kernel(const float* __restrict__ bias)
{
    __shared__ float As[2][128 * ASTR];
    __shared__ float Bs[2][32 * BSTR];

    const int tid  = threadIdx.x;
    const int wid  = tid >> 5;
    const int lane = tid & 31;
    const int g    = lane >> 2;
    const int kq   = lane & 3;
    const int wm   = wid & 1;
    const int wn   = wid >> 1;
    const int m0 = blockIdx.y * 128;
    const int n0 = blockIdx.x * 128;

    float acc[4][4][4];
#pragma unroll
    for (int mt = 0; mt < 4; mt++)
#pragma unroll
        for (int nt = 0; nt < 4; nt++)
#pragma unroll
            for (int c = 0; c < 4; c++) acc[mt][nt][c] = 0.f;

    auto issue = [&](int buf, int k0) {
#pragma unroll
        for (int it = 0; it < 4; it++) {
            int f = tid + 256 * it;
            int rm = f >> 3, kc = (f & 7) * 4;
            cp16(&As[buf][rm * ASTR + kc],
                 &g_xr[(size_t)(m0 + rm) * 1024 + k0 + kc]);
            int kb = f >> 5, cb = (f & 31) * 4;
            cp16(&Bs[buf][kb * BSTR + cb],
                 &g_wr[(size_t)(k0 + kb) * 3072 + n0 + cb]);
        }
        asm volatile("cp.async.commit_group;");
    };

    issue(0, 0);
    issue(1, 32);

    for (int i = 0; i < 32; i++) {
        int buf = i & 1;
        if (i < 31) asm volatile("cp.async.wait_group 1;");
        else        asm volatile("cp.async.wait_group 0;");
        __syncthreads();

#pragma unroll
        for (int s = 0; s < 4; s++) {
            int kk = 8 * s + kq;
            u32 a[4][4];
#pragma unroll
            for (int mt = 0; mt < 4; mt++) {
                int r = 64 * wm + 16 * mt + g;
                a[mt][0] = __float_as_uint(As[buf][r * ASTR + kk]);
                a[mt][1] = __float_as_uint(As[buf][(r + 8) * ASTR + kk]);
                a[mt][2] = __float_as_uint(As[buf][r * ASTR + kk + 4]);
                a[mt][3] = __float_as_uint(As[buf][(r + 8) * ASTR + kk + 4]);
            }
            u32 b0[4], b1[4];
#pragma unroll
            for (int nt = 0; nt < 4; nt++) {
                int c = 32 * wn + 8 * nt + g;
                b0[nt] = __float_as_uint(Bs[buf][kk * BSTR + c]);
                b1[nt] = __float_as_uint(Bs[buf][(kk + 4) * BSTR + c]);
            }
#pragma unroll
            for (int mt = 0; mt < 4; mt++)
#pragma unroll
                for (int nt = 0; nt < 4; nt++)
                    mma8(acc[mt][nt], a[mt], b0[nt], b1[nt]);
        }
        __syncthreads();
        if (i < 30) issue(buf, (i + 2) * 32);
    }

#pragma unroll
    for (int mt = 0; mt < 4; mt++) {
        int r0 = m0 + 64 * wm + 16 * mt + g;
#pragma unroll
        for (int nt = 0; nt < 4; nt++) {
            int c0 = n0 + 32 * wn + 8 * nt + 2 * kq;
#pragma unroll
            for (int e = 0; e < 4; e++) {
                int m = r0 + (e >> 1) * 8;
                int n = c0 + (e & 1);
                float val = to_tf32(acc[mt][nt][e] + bias[n]);
                int bb = m >> 10, l = m & 1023;
                int s = n >> 10, h = (n >> 6) & 15, hd = n & 63;
                int bh = bb * HEADS + h;
                size_t row = (size_t)bh * LEN + l;
                if (s == 0) {
                    g_qp[row * 80 + 20 * (hd & 3) + (hd >> 2)] = val;
                    g_qbf[row * HD + hd] = __float2bfloat16(val);
                } else if (s == 1) {
                    g_kp[row * 80 + 20 * (hd & 3) + (hd >> 2)] = val;
                    g_kbf[row * HD + hd] = __float2bfloat16(val);
                } else {
                    g_vp[(((size_t)bh * HD + hd) * 16 + (l >> 6)) * 80 +
                         20 * (l & 3) + ((l & 63) >> 2)] = val;
                }
            }
        }
    }
}

// ---------------------------------------------------------------------------
// Kernel 2: flash attention, 512 threads. Packed tf32 frag loads (LDS.128),
// Q a-frags hoisted (no Qf smem tile). Gq/Gk via ldmatrix bf16 k16.
// smem (float units):
//   Qbf[128][72]bf16 @0 (4608); Ebf[192][72]bf16 @4608 (6912, ring);
//   Gq[128][200]bf16 @11520 (12800, ring); KT[64][80] @24320 (5120);
//   Kbf[64][72]bf16 @29440 (2304); Gk[64][200]bf16 @31744 (6400);
//   Vs[64][80] @38144 (5120); sMax @43264 (256); sSum @43520 (256).
//   Ps[128][76] overlays KT+Kbf+Gk @24320 (9728 <= 13824).
// ---------------------------------------------------------------------------
#define oQB 0
#define oEB 4608
#define oGQ 11520
#define oKT 24320
#define oKB 29440
#define oGK 31744
#define oVS 38144
#define oSM 43264
#define oSS 43520
#define SMEMF 43776
#define ATT_SMEM_BYTES (SMEMF * 4)   // 175104 B
#define GSTR 200

__global__ __launch_bounds__(512) void attn_kernel(float* __restrict__ out)
{
    extern __shared__ float sm[];
    __nv_bfloat16* Qbf = (__nv_bfloat16*)(sm + oQB);
    __nv_bfloat16* Ebf = (__nv_bfloat16*)(sm + oEB);
    __nv_bfloat16* Gq  = (__nv_bfloat16*)(sm + oGQ);
    float* KT = sm + oKT;
    __nv_bfloat16* Kbf = (__nv_bfloat16*)(sm + oKB);
    __nv_bfloat16* Gk  = (__nv_bfloat16*)(sm + oGK);
    float* Vs = sm + oVS;
    float* sMax = sm + oSM;
    float* sSum = sm + oSS;
    float* Ps = sm + oKT;   // overlay

    const int tid  = threadIdx.x;
    const int wid  = tid >> 5;
    const int lane = tid & 31;
    const int g    = lane >> 2;
    const int kq   = lane & 3;
    const int wr   = wid & 7;
    const int wc   = wid >> 3;
    const int l0 = blockIdx.x * 128;
    const int bh = blockIdx.y;
    const int b = bh >> 4, h = bh & 15;
    const size_t baseb = (size_t)bh * LEN * HD;   // bf16 arrays

    // ldmatrix lane decodes
    const int rdA = (lane & 7) + ((lane >> 3) & 1) * 8;
    const int cdA = ((lane >> 4) & 1) * 8;
    const int rdB = (lane & 7) + ((lane >> 4) & 1) * 8;
    const int cdB = ((lane >> 3) & 1) * 8;

    // ---- one-time: Qbf smem tile ----
#pragma unroll 2
    for (int it = 0; it < 2; it++) {
        int idx = tid + 512 * it;
        int r = idx >> 3, c8 = (idx & 7) * 8;
        *(float4*)&Qbf[r * 72 + c8] =
            *(const float4*)&g_qbf[baseb + (size_t)(l0 + r) * HD + c8];
    }

    const int i0  = 16 * wr + g;
    const int wmk = wid & 3, wnk = wid >> 2;
    const int rk0 = 16 * wmk + g;

    // ---- hoisted Q a-frags (packed, straight from global/L2) ----
    float4 qa[8];
    {
        const float* q0 = &g_qp[((size_t)bh * LEN + l0 + i0) * 80 + 20 * kq];
        const float* q1 = &g_qp[((size_t)bh * LEN + l0 + i0 + 8) * 80 + 20 * kq];
#pragma unroll
        for (int jj = 0; jj < 4; jj++) {
            qa[jj]     = *(const float4*)(q0 + 4 * jj);
            qa[4 + jj] = *(const float4*)(q1 + 4 * jj);
        }
    }

    const u32 aQbase = (u32)__cvta_generic_to_shared(
        &Qbf[(16 * wr + rdA) * 72 + cdA]);
    const u32 aKbase = (u32)__cvta_generic_to_shared(
        &Kbf[(16 * wmk + rdA) * 72 + cdA]);
    const u32 eBase  = (u32)__cvta_generic_to_shared(Ebf);

    float mrun0 = -1e30f, mrun1 = -1e30f, lrun0 = 0.f, lrun1 = 0.f;
    float O[4][4];
#pragma unroll
    for (int t = 0; t < 4; t++)
#pragma unroll
        for (int c = 0; c < 4; c++) O[t][c] = 0.f;

    for (int j0 = 0; j0 < LEN; j0 += 64) {
        const int ebase = l0 - j0 + 960;
        const int rb    = ebase % 192;
        const int nblk  = (j0 == 0) ? 3 : 1;

        __syncthreads();   // (a)

        // ---- tile loads: KT (packed), Vs (packed), Kbf, Ebf ----
#pragma unroll
        for (int it = 0; it < 5; it++) {
            int idx = tid + 512 * it;
            if (idx < 1280) {
                int r = idx / 20, c4 = (idx % 20) * 4;
                *(float4*)&KT[r * 80 + c4] =
                    *(const float4*)&g_kp[((size_t)bh * LEN + j0 + r) * 80 + c4];
            } else {
                int i2 = idx - 1280;
                int r = i2 / 20, c4 = (i2 % 20) * 4;
                *(float4*)&Vs[r * 80 + c4] =
                    *(const float4*)&g_vp[(((size_t)bh * HD + r) * 16 + (j0 >> 6)) * 80 + c4];
            }
        }
        {
            int r = tid >> 3, c8 = (tid & 7) * 8;
            *(float4*)&Kbf[r * 72 + c8] =
                *(const float4*)&g_kbf[baseb + (size_t)(j0 + r) * HD + c8];
        }
        for (int bi = 0; bi < nblk; bi++) {
            int rblk = (rb + 64 * bi) % 192;
            int r = tid >> 3, c8 = (tid & 7) * 8;
            *(float4*)&Ebf[(rblk + r) * 72 + c8] =
                *(const float4*)&g_ebf[(size_t)(ebase + 64 * bi + r) * 64 + c8];
        }
        __syncthreads();   // (b)

        // ---- S1 = Q@K^T (tf32 k8, packed LDS.128 b-frags) ----
        float accS[4][4];
#pragma unroll
        for (int t = 0; t < 4; t++)
#pragma unroll
            for (int c = 0; c < 4; c++) accS[t][c] = 0.f;
#pragma unroll
        for (int t = 0; t < 4; t++) {
            int n = 32 * wc + 8 * t + g;
            float4 kb[4];
#pragma unroll
            for (int jj = 0; jj < 4; jj++)
                kb[jj] = *(const float4*)&KT[n * 80 + 20 * kq + 4 * jj];
#pragma unroll
            for (int ks = 0; ks < 8; ks++) {
                int jj = ks >> 1;
                u32 a[4];
                u32 b0, b1;
                if ((ks & 1) == 0) {
                    a[0] = __float_as_uint(qa[jj].x);
                    a[1] = __float_as_uint(qa[4 + jj].x);
                    a[2] = __float_as_uint(qa[jj].y);
                    a[3] = __float_as_uint(qa[4 + jj].y);
                    b0 = __float_as_uint(kb[jj].x);
                    b1 = __float_as_uint(kb[jj].y);
                } else {
                    a[0] = __float_as_uint(qa[jj].z);
                    a[1] = __float_as_uint(qa[4 + jj].z);
                    a[2] = __float_as_uint(qa[jj].w);
                    a[3] = __float_as_uint(qa[4 + jj].w);
                    b0 = __float_as_uint(kb[jj].z);
                    b1 = __float_as_uint(kb[jj].w);
                }
                mma8(accS[t], a, b0, b1);
            }
        }

        // ---- Gq: new ring block(s), ldmatrix frags (bf16 k16) ----
#pragma unroll 1
        for (int bi = 0; bi < nblk; bi++) {
            int rblk = (rb + 64 * bi) % 192;
            u32 eA = eBase + (u32)(((rblk + 32 * wc + rdB) * 72 + cdB) * 2);
            float acc[4][4];
#pragma unroll
            for (int t = 0; t < 4; t++)
#pragma unroll
                for (int c = 0; c < 4; c++) acc[t][c] = 0.f;
#pragma unroll
            for (int ks = 0; ks < 4; ks++) {
                u32 a[4];
                ldsm4(a[0], a[1], a[2], a[3], aQbase + 32 * ks);
#pragma unroll
                for (int tp = 0; tp < 2; tp++) {
                    u32 e0, e1, e2, e3;
                    ldsm4(e0, e1, e2, e3, eA + tp * 2304 + 32 * ks);
                    mma16bf(acc[2 * tp],     a, e0, e1);
                    mma16bf(acc[2 * tp + 1], a, e2, e3);
                }
            }
#pragma unroll
            for (int t = 0; t < 4; t++) {
                int n = rblk + 32 * wc + 8 * t + 2 * kq;
                *(__nv_bfloat162*)&Gq[i0 * GSTR + n] =
                    __floats2bfloat162_rn(acc[t][0], acc[t][1]);
                *(__nv_bfloat162*)&Gq[(i0 + 8) * GSTR + n] =
                    __floats2bfloat162_rn(acc[t][2], acc[t][3]);
            }
        }

        // ---- Gk over full ring, ldmatrix frags: warps 4m x 4n (48 cols) ----
        {
            u32 eG = eBase + (u32)(((48 * wnk + rdB) * 72 + cdB) * 2);
            float acc[6][4];
#pragma unroll
            for (int t = 0; t < 6; t++)
#pragma unroll
                for (int c = 0; c < 4; c++) acc[t][c] = 0.f;
#pragma unroll
            for (int ks = 0; ks < 4; ks++) {
                u32 a[4];
                ldsm4(a[0], a[1], a[2], a[3], aKbase + 32 * ks);
#pragma unroll
                for (int tp = 0; tp < 3; tp++) {
                    u32 e0, e1, e2, e3;
                    ldsm4(e0, e1, e2, e3, eG + tp * 2304 + 32 * ks);
                    mma16bf(acc[2 * tp],     a, e0, e1);
                    mma16bf(acc[2 * tp + 1], a, e2, e3);
                }
            }
#pragma unroll
            for (int t = 0; t < 6; t++) {
                int n = 48 * wnk + 8 * t + 2 * kq;
                *(__nv_bfloat162*)&Gk[rk0 * GSTR + n] =
                    __floats2bfloat162_rn(acc[t][0], acc[t][1]);
                *(__nv_bfloat162*)&Gk[(rk0 + 8) * GSTR + n] =
                    __floats2bfloat162_rn(acc[t][2], acc[t][3]);
            }
        }
        __syncthreads();   // (c)

        // ---- gather bias (cheap ring index) ----
        int rbase = (l0 + i0 - j0 + 1023) % 192;
        int rbase8 = rbase + 8; if (rbase8 >= 192) rbase8 -= 192;
        const __nv_bfloat16* gq0r = &Gq[i0 * GSTR];
        const __nv_bfloat16* gq1r = &Gq[(i0 + 8) * GSTR];
#pragma unroll
        for (int t = 0; t < 4; t++)
#pragma unroll
            for (int e = 0; e < 2; e++) {
                int jloc = 32 * wc + 8 * t + 2 * kq + e;
                int r  = rbase  - jloc;  r  += (r  >> 31) & 192;
                int r2 = rbase8 - jloc;  r2 += (r2 >> 31) & 192;
                float gq0 = __bfloat162float(gq0r[r]);
                float gk0 = __bfloat162float(Gk[jloc * GSTR + r]);
                float gq1 = __bfloat162float(gq1r[r2]);
                float gk1 = __bfloat162float(Gk[jloc * GSTR + r2]);
                accS[t][e]     = (accS[t][e]     + gq0 + gk0) * SCALE;
                accS[t][2 + e] = (accS[t][2 + e] + gq1 + gk1) * SCALE;
            }

        // ---- partial softmax (exp once, rescale later) ----
        float mx0 = -1e30f, mx1 = -1e30f;
#pragma unroll
        for (int t = 0; t < 4; t++) {
            mx0 = fmaxf(mx0, fmaxf(accS[t][0], accS[t][1]));
            mx1 = fmaxf(mx1, fmaxf(accS[t][2], accS[t][3]));
        }
        mx0 = fmaxf(mx0, __shfl_xor_sync(0xffffffffu, mx0, 1));
        mx0 = fmaxf(mx0, __shfl_xor_sync(0xffffffffu, mx0, 2));
        mx1 = fmaxf(mx1, __shfl_xor_sync(0xffffffffu, mx1, 1));
        mx1 = fmaxf(mx1, __shfl_xor_sync(0xffffffffu, mx1, 2));
        float pe[4][4];
        float ps0 = 0.f, ps1 = 0.f;
#pragma unroll
        for (int t = 0; t < 4; t++) {
            pe[t][0] = __expf(accS[t][0] - mx0);
            pe[t][1] = __expf(accS[t][1] - mx0);
            pe[t][2] = __expf(accS[t][2] - mx1);
            pe[t][3] = __expf(accS[t][3] - mx1);
            ps0 += pe[t][0] + pe[t][1];
            ps1 += pe[t][2] + pe[t][3];
        }
        ps0 += __shfl_xor_sync(0xffffffffu, ps0, 1);
        ps0 += __shfl_xor_sync(0xffffffffu, ps0, 2);
        ps1 += __shfl_xor_sync(0xffffffffu, ps1, 1);
        ps1 += __shfl_xor_sync(0xffffffffu, ps1, 2);
        if (kq == 0) {
            sMax[wc * 128 + i0] = mx0;  sMax[wc * 128 + i0 + 8] = mx1;
            sSum[wc * 128 + i0] = ps0;  sSum[wc * 128 + i0 + 8] = ps1;
        }
        __syncthreads();   // (d)

        // ---- combine across warp pair ----
        float omx0 = sMax[(1 - wc) * 128 + i0];
        float omx1 = sMax[(1 - wc) * 128 + i0 + 8];
        float osm0 = sSum[(1 - wc) * 128 + i0];
        float osm1 = sSum[(1 - wc) * 128 + i0 + 8];
        float nm0 = fmaxf(mrun0, fmaxf(mx0, omx0));
        float nm1 = fmaxf(mrun1, fmaxf(mx1, omx1));
        float pf0 = __expf(mrun0 - nm0), pf1 = __expf(mrun1 - nm1);
        float sc0 = __expf(mx0 - nm0),   sc1 = __expf(mx1 - nm1);
        float ts0 = ps0 * sc0 + osm0 * __expf(omx0 - nm0);
        float ts1 = ps1 * sc1 + osm1 * __expf(omx1 - nm1);
        lrun0 = lrun0 * pf0 + ts0;  mrun0 = nm0;
        lrun1 = lrun1 * pf1 + ts1;  mrun1 = nm1;

        // ---- write P (tf32) and scale O ----
#pragma unroll
        for (int t = 0; t < 4; t++) {
            int n = 32 * wc + 8 * t + 2 * kq;
            *(float2*)&Ps[i0 * 76 + n] =
                make_float2(to_tf32(pe[t][0] * sc0), to_tf32(pe[t][1] * sc0));
            *(float2*)&Ps[(i0 + 8) * 76 + n] =
                make_float2(to_tf32(pe[t][2] * sc1), to_tf32(pe[t][3] * sc1));
            O[t][0] *= pf0; O[t][1] *= pf0; O[t][2] *= pf1; O[t][3] *= pf1;
        }
        __syncthreads();   // (e)

        // ---- O += P @ V (tf32 k8, packed LDS.128 b-frags) ----
        u32 aP[8][4];
#pragma unroll
        for (int ks = 0; ks < 8; ks++) {
            int kr = 8 * ks + kq;
            aP[ks][0] = __float_as_uint(Ps[i0 * 76 + kr]);
            aP[ks][1] = __float_as_uint(Ps[(i0 + 8) * 76 + kr]);
            aP[ks][2] = __float_as_uint(Ps[i0 * 76 + kr + 4]);
            aP[ks][3] = __float_as_uint(Ps[(i0 + 8) * 76 + kr + 4]);
        }
#pragma unroll
        for (int t = 0; t < 4; t++) {
            int n = 32 * wc + 8 * t + g;   // head-dim row of packed Vs
            float4 vb[4];
#pragma unroll
            for (int jj = 0; jj < 4; jj++)
                vb[jj] = *(const float4*)&Vs[n * 80 + 20 * kq + 4 * jj];
#pragma unroll
            for (int ks = 0; ks < 8; ks++) {
                int jj = ks >> 1;
                u32 b0, b1;
                if ((ks & 1) == 0) {
                    b0 = __float_as_uint(vb[jj].x);
                    b1 = __float_as_uint(vb[jj].y);
                } else {
                    b0 = __float_as_uint(vb[jj].z);
                    b1 = __float_as_uint(vb[jj].w);
                }
                mma8(O[t], aP[ks], b0, b1);
            }
        }
    }

    // ---- epilogue ----
    float inv0 = 1.0f / lrun0, inv1 = 1.0f / lrun1;
#pragma unroll
    for (int t = 0; t < 4; t++) {
        int col = h * HD + 32 * wc + 8 * t + 2 * kq;
        size_t r0a = ((size_t)(b * LEN + l0 + i0)) * DIM + col;
        size_t r1a = ((size_t)(b * LEN + l0 + i0 + 8)) * DIM + col;
        *(float2*)&out[r0a] = make_float2(O[t][0] * inv0, O[t][1] * inv0);
        *(float2*)&out[r1a] = make_float2(O[t][2] * inv1, O[t][3] * inv1);
    }
}

// ---------------------------------------------------------------------------
extern "C" void kernel_launch(void* const* d_in, const int* in_sizes, int n_in,
                              void* d_out, int out_size)
{
    const float* x    = (const float*)d_in[0];
    const float* Wqkv = (const float*)d_in[1];
    const float* bqkv = (const float*)d_in[2];
    const float* emb  = (const float*)d_in[3];
    float* out = (float*)d_out;

    cudaFuncSetAttribute(attn_kernel, cudaFuncAttributeMaxDynamicSharedMemorySize,
                         ATT_SMEM_BYTES);

    prep_kernel<<<(NX4 + NW4 + NE4 + 255) / 256, 256>>>(x, Wqkv, emb);

    dim3 gq(3072 / 128, 4096 / 128);
    qkv_kernel<<<gq, 256>>>(bqkv);

    dim3 ga(LEN / 128, BATCH * HEADS);
    attn_kernel<<<ga, 512, ATT_SMEM_BYTES>>>(out);
}